// round 5
// baseline (speedup 1.0000x reference)
#include <cuda_runtime.h>
#include <cuda_bf16.h>
#include <math.h>

#define SCALE_Q 0.17677669529663687f
#define KSTR 40   // smem row stride in bf16 elems (80B, conflict-free for LDSM)

// ---------------- scratch (device globals) ----------------------------------
__device__ float g_qkv[83886080];            // 131072 x 640 fp32 (padded qkv)
__device__ float g_x2v[25165824];            // x after attn residual (B,C,H,W)
__device__ __nv_bfloat16 g_ah[25165824];     // activations hi (131072 x 192)
__device__ __nv_bfloat16 g_al[25165824];     // activations lo
__device__ __nv_bfloat16 g_bh[100663296];    // fc1 out hi (131072 x 768)
__device__ __nv_bfloat16 g_bl[100663296];    // fc1 out lo
__device__ __nv_bfloat16 g_wh[516096];       // weights hi (padded: qkv|proj|fc1|fc2)
__device__ __nv_bfloat16 g_wl[516096];       // weights lo
__device__ float g_M[2][32][4096];           // per-batch 64x64 patch conv matrices
__device__ float2 g_gn[2][32][32];           // (mean, rstd)

// padded weight offsets (rows padded to mult of 128, pad rows stay zero)
#define WOFF_QKV 0
#define WOFF_PROJ 122880     // 640*192
#define WOFF_FC1 172032      // + 256*192
#define WOFF_FC2 319488      // + 768*192

__constant__ float c_cos8[8] = {
    1.f, 0.70710678118654752f, 0.f, -0.70710678118654752f,
   -1.f, -0.70710678118654752f, 0.f, 0.70710678118654752f};

// ---------------- small helpers ---------------------------------------------
__device__ __forceinline__ unsigned su32(const void* p) {
    return (unsigned)__cvta_generic_to_shared(p);
}
__device__ __forceinline__ void cpasync16(unsigned dst, const void* src) {
    asm volatile("cp.async.ca.shared.global [%0], [%1], 16;" :: "r"(dst), "l"(src) : "memory");
}
__device__ __forceinline__ void cpcommit() {
    asm volatile("cp.async.commit_group;" ::: "memory");
}
template <int W> __device__ __forceinline__ void cpwait() {
    asm volatile("cp.async.wait_group %0;" :: "n"(W) : "memory");
}
__device__ __forceinline__ void ldsm4(unsigned a, unsigned& r0, unsigned& r1,
                                      unsigned& r2, unsigned& r3) {
    asm volatile("ldmatrix.sync.aligned.m8n8.x4.shared.b16 {%0,%1,%2,%3}, [%4];"
                 : "=r"(r0), "=r"(r1), "=r"(r2), "=r"(r3) : "r"(a));
}
__device__ __forceinline__ void mma16816(float* c, const unsigned* a, const unsigned* b) {
    asm volatile(
        "mma.sync.aligned.m16n8k16.row.col.f32.bf16.bf16.f32 "
        "{%0,%1,%2,%3}, {%4,%5,%6,%7}, {%8,%9}, {%0,%1,%2,%3};"
        : "+f"(c[0]), "+f"(c[1]), "+f"(c[2]), "+f"(c[3])
        : "r"(a[0]), "r"(a[1]), "r"(a[2]), "r"(a[3]), "r"(b[0]), "r"(b[1]));
}
__device__ __forceinline__ void splitbf(float v, __nv_bfloat16& h, __nv_bfloat16& l) {
    h = __float2bfloat16(v);
    l = __float2bfloat16(v - __bfloat162float(h));
}

// ---------------- K1: adaFM spectra -> per-batch 64x64 conv matrices --------
__global__ void __launch_bounds__(256) k_prep(
    const float* __restrict__ t,
    const float* __restrict__ wmsa, const float* __restrict__ bmsa,
    const float* __restrict__ wmlp, const float* __restrict__ bmlp)
{
    int b = blockIdx.x, tid = threadIdx.x;
    __shared__ float st[640];
    __shared__ float s[2][40];
    __shared__ float seff[2][64];
    __shared__ float ker[2][64];

    for (int i = tid; i < 640; i += 256) {
        float v = t[b * 640 + i];
        st[i] = v / (1.f + __expf(-v));
    }
    __syncthreads();
    if (tid < 80) {
        int br = tid / 40, f = tid % 40;
        const float* w  = br ? wmlp : wmsa;
        const float* bb = br ? bmlp : bmsa;
        float acc = bb[f];
        for (int e = 0; e < 640; e++) acc = fmaf(st[e], w[f * 640 + e], acc);
        s[br][f] = acc;
    }
    __syncthreads();
    if (tid < 128) {
        int br = tid >> 6, i = tid & 63, k1 = i >> 3, k2 = i & 7;
        float v;
        if (k2 == 0 || k2 == 4)
            v = 0.5f * (s[br][k1 * 5 + k2] + s[br][((8 - k1) & 7) * 5 + k2]);
        else if (k2 < 4) v = s[br][k1 * 5 + k2];
        else             v = s[br][((8 - k1) & 7) * 5 + (8 - k2)];
        seff[br][i] = v;
    }
    __syncthreads();
    if (tid < 128) {
        int br = tid >> 6, i = tid & 63, d1 = i >> 3, d2 = i & 7;
        float acc = 0.f;
        #pragma unroll
        for (int k = 0; k < 64; k++)
            acc = fmaf(seff[br][k], c_cos8[((k >> 3) * d1 + (k & 7) * d2) & 7], acc);
        ker[br][i] = acc * (1.f / 64.f);
    }
    __syncthreads();
    for (int idx = tid; idx < 8192; idx += 256) {
        int br = idx >> 12, j = idx & 4095;
        int in = j >> 6, out = j & 63;
        g_M[br][b][j] = ker[br][(((out >> 3) - (in >> 3)) & 7) * 8 +
                               (((out & 7) - (in & 7)) & 7)];
    }
}

// ---------------- K1b: weight fp32 -> bf16 hi/lo -----------------------------
__global__ void k_wconv(const float* __restrict__ w,
                        __nv_bfloat16* __restrict__ h,
                        __nv_bfloat16* __restrict__ l, int n)
{
    int i = blockIdx.x * 256 + threadIdx.x;
    if (i >= n) return;
    __nv_bfloat16 hh, ll;
    splitbf(w[i], hh, ll);
    h[i] = hh; l[i] = ll;
}

// ---------------- K2: GroupNorm stats ---------------------------------------
__global__ void __launch_bounds__(256) k_gnstats(const float* __restrict__ x, int gi)
{
    int g = blockIdx.x, b = blockIdx.y;
    const float* p = x + ((size_t)b * 192 + g * 6) * 4096;
    float s = 0.f, s2 = 0.f;
    for (int i = threadIdx.x; i < 24576; i += 256) {
        float v = p[i]; s += v; s2 = fmaf(v, v, s2);
    }
    #pragma unroll
    for (int o = 16; o; o >>= 1) {
        s += __shfl_xor_sync(~0u, s, o); s2 += __shfl_xor_sync(~0u, s2, o);
    }
    __shared__ float sh[2][8];
    int wid = threadIdx.x >> 5;
    if (!(threadIdx.x & 31)) { sh[0][wid] = s; sh[1][wid] = s2; }
    __syncthreads();
    if (threadIdx.x < 32) {
        s  = (threadIdx.x < 8) ? sh[0][threadIdx.x] : 0.f;
        s2 = (threadIdx.x < 8) ? sh[1][threadIdx.x] : 0.f;
        #pragma unroll
        for (int o = 4; o; o >>= 1) {
            s += __shfl_xor_sync(~0u, s, o); s2 += __shfl_xor_sync(~0u, s2, o);
        }
        if (!threadIdx.x) {
            float m = s * (1.f / 24576.f);
            float var = s2 * (1.f / 24576.f) - m * m;
            g_gn[gi][b][g] = make_float2(m, rsqrtf(var + 1e-5f));
        }
    }
}

// ---------------- K3: GN apply + adafm patch GEMM + scatter (bf16 pair out) -
template <int MODE>
__global__ void __launch_bounds__(256) k_adafm(
    const float* __restrict__ src,
    const float* __restrict__ gw, const float* __restrict__ gbv)
{
    extern __shared__ float sm[];
    float* Xs = sm;               // 64 x 196
    float* Ms = sm + 64 * 196;    // 4096
    float* ga = Ms + 4096;        // 192
    float* gb = ga + 192;         // 192
    int patch = blockIdx.x, b = blockIdx.y;
    int py = patch >> 3, px = patch & 7, tid = threadIdx.x;

    if (tid < 192) {
        float2 st = g_gn[MODE][b][tid / 6];
        float a = st.y * gw[tid];
        ga[tid] = a; gb[tid] = gbv[tid] - st.x * a;
    }
    for (int i = tid; i < 4096; i += 256) Ms[i] = g_M[MODE][b][i];
    __syncthreads();

    int u = tid >> 5, cl = tid & 31;
    const float* sb = src + ((size_t)b * 192) * 4096 + (py * 8 + u) * 64 + px * 8;
    #pragma unroll
    for (int cb = 0; cb < 6; cb++) {
        int c = cb * 32 + cl;
        const float* pr = sb + (size_t)c * 4096;
        float4 v0 = *(const float4*)pr;
        float4 v1 = *(const float4*)(pr + 4);
        float a = ga[c], o = gb[c];
        float vv[8] = {v0.x, v0.y, v0.z, v0.w, v1.x, v1.y, v1.z, v1.w};
        #pragma unroll
        for (int j = 0; j < 8; j++)
            Xs[(u * 8 + j) * 196 + c] = fmaf(vv[j], a, o);
    }
    __syncthreads();

    int p = tid & 63, cg = tid >> 6;
    float4 acc[12];
    #pragma unroll
    for (int j = 0; j < 12; j++) acc[j] = make_float4(0.f, 0.f, 0.f, 0.f);
    for (int uu = 0; uu < 64; uu++) {
        float m = Ms[uu * 64 + p];
        const float4* xr = (const float4*)(Xs + uu * 196) + cg * 12;
        #pragma unroll
        for (int j = 0; j < 12; j++) {
            float4 xv = xr[j];
            acc[j].x = fmaf(m, xv.x, acc[j].x);
            acc[j].y = fmaf(m, xv.y, acc[j].y);
            acc[j].z = fmaf(m, xv.z, acc[j].z);
            acc[j].w = fmaf(m, xv.w, acc[j].w);
        }
    }
    int hh = py * 8 + (p >> 3), ww = px * 8 + (p & 7);
    size_t off;
    if (MODE == 0) {
        int hh2 = (hh + 60) & 63, ww2 = (ww + 60) & 63;
        int win = ((hh2 >> 3) << 3) | (ww2 >> 3);
        int nn  = ((hh2 & 7) << 3) | (ww2 & 7);
        off = (((size_t)(b * 64 + win) * 64 + nn) * 192) + cg * 48;
    } else {
        off = (((size_t)b * 4096 + hh * 64 + ww) * 192) + cg * 48;
    }
    #pragma unroll
    for (int j = 0; j < 12; j++) {
        float4 v = acc[j];
        __nv_bfloat16 h0, h1, h2, h3, l0, l1, l2, l3;
        splitbf(v.x, h0, l0); splitbf(v.y, h1, l1);
        splitbf(v.z, h2, l2); splitbf(v.w, h3, l3);
        *(ushort4*)(g_ah + off + j * 4) = make_ushort4(
            __bfloat16_as_ushort(h0), __bfloat16_as_ushort(h1),
            __bfloat16_as_ushort(h2), __bfloat16_as_ushort(h3));
        *(ushort4*)(g_al + off + j * 4) = make_ushort4(
            __bfloat16_as_ushort(l0), __bfloat16_as_ushort(l1),
            __bfloat16_as_ushort(l2), __bfloat16_as_ushort(l3));
    }
}

// ---------------- K4: pipelined bf16-pair tensor GEMM, block 128x128 --------
// C[m][n] = sum_k A[m][k]*W[n][k]; Np = padded col stride, Nr = real cols.
// EPI 0: +bias -> fp32 (row stride Np) | 1: +bias GELU -> bf16 pair
// EPI 2: +bias win-rev+roll+res | 3: +bias chan-major + res
template <int EPI>
__global__ void __launch_bounds__(256, 2) k_bgemm(
    const __nv_bfloat16* __restrict__ Ah, const __nv_bfloat16* __restrict__ Al,
    const __nv_bfloat16* __restrict__ Wh, const __nv_bfloat16* __restrict__ Wl,
    const float* __restrict__ bias, float* __restrict__ Cf,
    __nv_bfloat16* __restrict__ Ch, __nv_bfloat16* __restrict__ Cl,
    int K, int Np, int Nr, const float* __restrict__ res)
{
    extern __shared__ __nv_bfloat16 smem[];
    const int ASZ = 128 * KSTR;              // elems per matrix (A and B same)
    const int STG = 4 * ASZ;                 // Ah|Al|Bh|Bl per stage

    int m0 = blockIdx.y * 128, n0 = blockIdx.x * 128;
    int tid = threadIdx.x, lane = tid & 31, wid = tid >> 5;
    int wm = (wid & 3) * 32, wn = (wid >> 2) * 64;

    const __nv_bfloat16* Abh = Ah + (size_t)m0 * K;
    const __nv_bfloat16* Abl = Al + (size_t)m0 * K;
    const __nv_bfloat16* Bbh = Wh + (size_t)n0 * K;
    const __nv_bfloat16* Bbl = Wl + (size_t)n0 * K;
    int KT = K >> 5;

    float c[2][8][4];
    #pragma unroll
    for (int mt = 0; mt < 2; mt++)
        #pragma unroll
        for (int nt = 0; nt < 8; nt++)
            #pragma unroll
            for (int i = 0; i < 4; i++) c[mt][nt][i] = 0.f;

    auto fill = [&](int kt, int st) {
        __nv_bfloat16* base = smem + st * STG;
        int k0 = kt * 32;
        #pragma unroll
        for (int r = 0; r < 2; r++) {
            int e = tid * 2 + r, row = e >> 2, ch = e & 3;
            size_t srcoff = (size_t)row * K + k0 + ch * 8;
            unsigned d = su32(base + row * KSTR + ch * 8);
            cpasync16(d,            Abh + srcoff);
            cpasync16(d + ASZ * 2,  Abl + srcoff);
            cpasync16(d + ASZ * 4,  Bbh + srcoff);
            cpasync16(d + ASZ * 6,  Bbl + srcoff);
        }
        cpcommit();
    };

    fill(0, 0);
    for (int kt = 0; kt < KT; kt++) {
        if (kt + 1 < KT) { fill(kt + 1, (kt + 1) & 1); cpwait<1>(); }
        else             { cpwait<0>(); }
        __syncthreads();

        const __nv_bfloat16* base = smem + (kt & 1) * STG;
        unsigned sAh = su32(base);
        unsigned sAl = sAh + ASZ * 2;
        unsigned sBh = sAh + ASZ * 4;
        unsigned sBl = sAh + ASZ * 6;

        #pragma unroll
        for (int kk = 0; kk < 2; kk++) {
            unsigned ah[2][4], al[2][4];
            #pragma unroll
            for (int mt = 0; mt < 2; mt++) {
                int row = wm + mt * 16 + (lane & 15);
                int col = kk * 16 + ((lane & 16) ? 8 : 0);
                unsigned off = (unsigned)((row * KSTR + col) * 2);
                ldsm4(sAh + off, ah[mt][0], ah[mt][1], ah[mt][2], ah[mt][3]);
                ldsm4(sAl + off, al[mt][0], al[mt][1], al[mt][2], al[mt][3]);
            }
            #pragma unroll
            for (int ntp = 0; ntp < 4; ntp++) {
                int row = wn + ntp * 16 + ((lane & 16) ? 8 : 0) + (lane & 7);
                int col = kk * 16 + ((lane & 8) ? 8 : 0);
                unsigned off = (unsigned)((row * KSTR + col) * 2);
                unsigned bh[2][2], bl[2][2];
                unsigned r0, r1, r2, r3;
                ldsm4(sBh + off, r0, r1, r2, r3);
                bh[0][0] = r0; bh[0][1] = r1; bh[1][0] = r2; bh[1][1] = r3;
                ldsm4(sBl + off, r0, r1, r2, r3);
                bl[0][0] = r0; bl[0][1] = r1; bl[1][0] = r2; bl[1][1] = r3;
                #pragma unroll
                for (int mt = 0; mt < 2; mt++)
                    #pragma unroll
                    for (int j = 0; j < 2; j++) {
                        int nt = ntp * 2 + j;
                        mma16816(c[mt][nt], ah[mt], bh[j]);
                        mma16816(c[mt][nt], ah[mt], bl[j]);
                        mma16816(c[mt][nt], al[mt], bh[j]);
                    }
            }
        }
        __syncthreads();
    }

    // epilogue: row = m0+wm+mt*16+(lane>>2)+h*8, col = n0+wn+nt*8+(lane&3)*2
    int g = lane >> 2, tg = lane & 3;
    #pragma unroll
    for (int nt = 0; nt < 8; nt++) {
        int cb = n0 + wn + nt * 8 + tg * 2;
        if (cb >= Nr) continue;
        float2 bv = *(const float2*)(bias + cb);
        #pragma unroll
        for (int mt = 0; mt < 2; mt++)
            #pragma unroll
            for (int h = 0; h < 2; h++) {
                int m = m0 + wm + mt * 16 + g + h * 8;
                float v0 = c[mt][nt][h * 2 + 0] + bv.x;
                float v1 = c[mt][nt][h * 2 + 1] + bv.y;
                if (EPI == 0) {
                    *(float2*)(Cf + (size_t)m * Np + cb) = make_float2(v0, v1);
                } else if (EPI == 1) {
                    float g0 = 0.5f * v0 * (1.f + erff(v0 * 0.70710678118654752f));
                    float g1 = 0.5f * v1 * (1.f + erff(v1 * 0.70710678118654752f));
                    __nv_bfloat16 h0, h1, l0, l1;
                    splitbf(g0, h0, l0); splitbf(g1, h1, l1);
                    unsigned hp = (unsigned)__bfloat16_as_ushort(h0) |
                                  ((unsigned)__bfloat16_as_ushort(h1) << 16);
                    unsigned lp = (unsigned)__bfloat16_as_ushort(l0) |
                                  ((unsigned)__bfloat16_as_ushort(l1) << 16);
                    *(unsigned*)(Ch + (size_t)m * Np + cb) = hp;
                    *(unsigned*)(Cl + (size_t)m * Np + cb) = lp;
                } else if (EPI == 2) {
                    int b = m >> 12, win = (m >> 6) & 63, nn = m & 63;
                    int hh = ((((win >> 3) << 3) + (nn >> 3)) + 4) & 63;
                    int ww = ((((win & 7) << 3) + (nn & 7)) + 4) & 63;
                    size_t base2 = ((size_t)b * 192) * 4096 + hh * 64 + ww;
                    size_t i0 = base2 + (size_t)cb * 4096;
                    size_t i1 = base2 + (size_t)(cb + 1) * 4096;
                    Cf[i0] = res[i0] + v0;
                    Cf[i1] = res[i1] + v1;
                } else {
                    int b = m >> 12, pix = m & 4095;
                    size_t i0 = ((size_t)(b * 192 + cb)) * 4096 + pix;
                    size_t i1 = i0 + 4096;
                    Cf[i0] = res[i0] + v0;
                    Cf[i1] = res[i1] + v1;
                }
            }
    }
}

// ---------------- K5: fused window attention (qkv row stride 640) -----------
__global__ void __launch_bounds__(64) k_attn(
    const float* __restrict__ qkv, const float* __restrict__ rpb)
{
    int w = blockIdx.x, head = blockIdx.y, n = threadIdx.x;
    __shared__ float Ks[64 * 32], Vs[64 * 32], Pr[64 * 64], Br[225];
    __shared__ int Cat[64];

    const float* base = qkv + (size_t)w * 64 * 640 + head * 32;
    {
        const float4* kp = (const float4*)(base + (size_t)n * 640 + 192);
        const float4* vp = (const float4*)(base + (size_t)n * 640 + 384);
        float4* kd = (float4*)(Ks + n * 32);
        float4* vd = (float4*)(Vs + n * 32);
        #pragma unroll
        for (int i = 0; i < 8; i++) { kd[i] = kp[i]; vd[i] = vp[i]; }
    }
    for (int i = n; i < 225; i += 64) Br[i] = rpb[i * 6 + head];
    {
        int win = w & 63;
        int hh2 = ((win >> 3) << 3) + (n >> 3);
        int ww2 = ((win & 7) << 3) + (n & 7);
        int ch = hh2 < 56 ? 0 : (hh2 < 60 ? 1 : 2);
        int cw = ww2 < 56 ? 0 : (ww2 < 60 ? 1 : 2);
        Cat[n] = ch * 3 + cw;
    }
    float q[32];
    {
        const float4* qp = (const float4*)(base + (size_t)n * 640);
        #pragma unroll
        for (int i = 0; i < 8; i++) {
            float4 v = qp[i];
            q[i * 4 + 0] = v.x * SCALE_Q; q[i * 4 + 1] = v.y * SCALE_Q;
            q[i * 4 + 2] = v.z * SCALE_Q; q[i * 4 + 3] = v.w * SCALE_Q;
        }
    }
    __syncthreads();

    int rn = n >> 3, cn = n & 7, mycat = Cat[n];
    float mx = -1e30f;
    for (int m = 0; m < 64; m++) {
        float d = 0.f;
        const float* kr = Ks + m * 32;
        #pragma unroll
        for (int i = 0; i < 32; i++) d = fmaf(q[i], kr[i], d);
        d += Br[(rn - (m >> 3) + 7) * 15 + (cn - (m & 7) + 7)];
        if (Cat[m] != mycat) d -= 100.f;
        Pr[m * 64 + n] = d;
        mx = fmaxf(mx, d);
    }
    float sum = 0.f;
    for (int m = 0; m < 64; m++) {
        float e = __expf(Pr[m * 64 + n] - mx);
        Pr[m * 64 + n] = e;
        sum += e;
    }
    float inv = 1.f / sum;
    float acc[32];
    #pragma unroll
    for (int i = 0; i < 32; i++) acc[i] = 0.f;
    for (int m = 0; m < 64; m++) {
        float p = Pr[m * 64 + n];
        const float* vr = Vs + m * 32;
        #pragma unroll
        for (int i = 0; i < 32; i++) acc[i] = fmaf(p, vr[i], acc[i]);
    }
    size_t off = ((size_t)w * 64 + n) * 192 + head * 32;
    #pragma unroll
    for (int i = 0; i < 8; i++) {
        __nv_bfloat16 h0, h1, h2, h3, l0, l1, l2, l3;
        splitbf(acc[i * 4 + 0] * inv, h0, l0);
        splitbf(acc[i * 4 + 1] * inv, h1, l1);
        splitbf(acc[i * 4 + 2] * inv, h2, l2);
        splitbf(acc[i * 4 + 3] * inv, h3, l3);
        *(ushort4*)(g_ah + off + i * 4) = make_ushort4(
            __bfloat16_as_ushort(h0), __bfloat16_as_ushort(h1),
            __bfloat16_as_ushort(h2), __bfloat16_as_ushort(h3));
        *(ushort4*)(g_al + off + i * 4) = make_ushort4(
            __bfloat16_as_ushort(l0), __bfloat16_as_ushort(l1),
            __bfloat16_as_ushort(l2), __bfloat16_as_ushort(l3));
    }
}

// ---------------- launch ------------------------------------------------------
extern "C" void kernel_launch(void* const* d_in, const int* in_sizes, int n_in,
                              void* d_out, int out_size)
{
    const float* x    = (const float*)d_in[0];
    const float* t    = (const float*)d_in[1];
    const float* n1w  = (const float*)d_in[2];
    const float* n1b  = (const float*)d_in[3];
    const float* qkvw = (const float*)d_in[4];
    const float* qkvb = (const float*)d_in[5];
    const float* rpb  = (const float*)d_in[6];
    const float* pw   = (const float*)d_in[7];
    const float* pb   = (const float*)d_in[8];
    const float* n2w  = (const float*)d_in[9];
    const float* n2b  = (const float*)d_in[10];
    const float* f1w  = (const float*)d_in[11];
    const float* f1b  = (const float*)d_in[12];
    const float* f2w  = (const float*)d_in[13];
    const float* f2b  = (const float*)d_in[14];
    const float* amw  = (const float*)d_in[15];
    const float* amb  = (const float*)d_in[16];
    const float* alw  = (const float*)d_in[17];
    const float* alb  = (const float*)d_in[18];
    float* out = (float*)d_out;

    float *qkvf, *x2;
    __nv_bfloat16 *ah, *al, *bh, *bl, *wh, *wl;
    cudaGetSymbolAddress((void**)&qkvf, g_qkv);
    cudaGetSymbolAddress((void**)&x2,   g_x2v);
    cudaGetSymbolAddress((void**)&ah,   g_ah);
    cudaGetSymbolAddress((void**)&al,   g_al);
    cudaGetSymbolAddress((void**)&bh,   g_bh);
    cudaGetSymbolAddress((void**)&bl,   g_bl);
    cudaGetSymbolAddress((void**)&wh,   g_wh);
    cudaGetSymbolAddress((void**)&wl,   g_wl);

    const int ADAFM_SMEM = (64 * 196 + 4096 + 384) * 4;
    const int GEMM_SMEM  = 2 * 4 * 128 * KSTR * 2;  // 81920 B
    static int attr_done = 0;
    if (!attr_done) {
        cudaFuncSetAttribute(k_adafm<0>, cudaFuncAttributeMaxDynamicSharedMemorySize, ADAFM_SMEM);
        cudaFuncSetAttribute(k_adafm<1>, cudaFuncAttributeMaxDynamicSharedMemorySize, ADAFM_SMEM);
        cudaFuncSetAttribute(k_bgemm<0>, cudaFuncAttributeMaxDynamicSharedMemorySize, GEMM_SMEM);
        cudaFuncSetAttribute(k_bgemm<1>, cudaFuncAttributeMaxDynamicSharedMemorySize, GEMM_SMEM);
        cudaFuncSetAttribute(k_bgemm<2>, cudaFuncAttributeMaxDynamicSharedMemorySize, GEMM_SMEM);
        cudaFuncSetAttribute(k_bgemm<3>, cudaFuncAttributeMaxDynamicSharedMemorySize, GEMM_SMEM);
        attr_done = 1;
    }

    k_prep<<<32, 256>>>(t, amw, amb, alw, alb);
    k_wconv<<<432, 256>>>(qkvw, wh + WOFF_QKV,  wl + WOFF_QKV,  110592);
    k_wconv<<<144, 256>>>(pw,   wh + WOFF_PROJ, wl + WOFF_PROJ, 36864);
    k_wconv<<<576, 256>>>(f1w,  wh + WOFF_FC1,  wl + WOFF_FC1,  147456);
    k_wconv<<<576, 256>>>(f2w,  wh + WOFF_FC2,  wl + WOFF_FC2,  147456);

    k_gnstats<<<dim3(32, 32), 256>>>(x, 0);
    k_adafm<0><<<dim3(64, 32), 256, ADAFM_SMEM>>>(x, n1w, n1b);
    // qkv: (131072 x 192) @ (576 x 192)^T -> fp32, padded to 640 cols
    k_bgemm<0><<<dim3(5, 1024), 256, GEMM_SMEM>>>(ah, al, wh + WOFF_QKV, wl + WOFF_QKV,
        qkvb, qkvf, nullptr, nullptr, 192, 640, 576, nullptr);
    k_attn<<<dim3(2048, 6), 64>>>(qkvf, rpb);
    // proj + window reverse + roll + residual -> x2 (N padded 256, real 192)
    k_bgemm<2><<<dim3(2, 1024), 256, GEMM_SMEM>>>(ah, al, wh + WOFF_PROJ, wl + WOFF_PROJ,
        pb, x2, nullptr, nullptr, 192, 256, 192, x);
    k_gnstats<<<dim3(32, 32), 256>>>(x2, 1);
    k_adafm<1><<<dim3(64, 32), 256, ADAFM_SMEM>>>(x2, n2w, n2b);
    // fc1 + GELU -> bf16 pair (768 cols, no padding)
    k_bgemm<1><<<dim3(6, 1024), 256, GEMM_SMEM>>>(ah, al, wh + WOFF_FC1, wl + WOFF_FC1,
        f1b, nullptr, bh, bl, 192, 768, 768, nullptr);
    // fc2 + residual scatter -> out (N padded 256, real 192)
    k_bgemm<3><<<dim3(2, 1024), 256, GEMM_SMEM>>>(bh, bl, wh + WOFF_FC2, wl + WOFF_FC2,
        f2b, out, nullptr, nullptr, 768, 256, 192, x2);
}

// round 6
// speedup vs baseline: 1.0738x; 1.0738x over previous
#include <cuda_runtime.h>
#include <cuda_bf16.h>
#include <math.h>

#define SCALE_Q 0.17677669529663687f
#define KSTR 40   // smem row stride in bf16 elems (80B, conflict-free for LDSM)

// ---------------- scratch (device globals) ----------------------------------
__device__ float g_qkv[75497472];            // 131072 x 576 fp32
__device__ float g_x2v[25165824];            // x after attn residual (B,C,H,W)
__device__ __nv_bfloat16 g_ah[25165824];     // activations hi (131072 x 192)
__device__ __nv_bfloat16 g_al[25165824];     // activations lo
__device__ __nv_bfloat16 g_bh[100663296];    // fc1 out hi (131072 x 768)
__device__ __nv_bfloat16 g_bl[100663296];    // fc1 out lo
__device__ __nv_bfloat16 g_wh[442368];       // weights hi (qkv|proj|fc1|fc2)
__device__ __nv_bfloat16 g_wl[442368];       // weights lo
__device__ float g_M[2][32][4096];           // per-batch 64x64 patch conv matrices
__device__ float2 g_gn[2][32][32];           // (mean, rstd)

__constant__ float c_cos8[8] = {
    1.f, 0.70710678118654752f, 0.f, -0.70710678118654752f,
   -1.f, -0.70710678118654752f, 0.f, 0.70710678118654752f};

// ---------------- small helpers ---------------------------------------------
__device__ __forceinline__ unsigned su32(const void* p) {
    return (unsigned)__cvta_generic_to_shared(p);
}
__device__ __forceinline__ void cpasync16(unsigned dst, const void* src) {
    asm volatile("cp.async.cg.shared.global [%0], [%1], 16;" :: "r"(dst), "l"(src) : "memory");
}
__device__ __forceinline__ void cpcommit() {
    asm volatile("cp.async.commit_group;" ::: "memory");
}
template <int W> __device__ __forceinline__ void cpwait() {
    asm volatile("cp.async.wait_group %0;" :: "n"(W) : "memory");
}
__device__ __forceinline__ void ldsm4(unsigned a, unsigned& r0, unsigned& r1,
                                      unsigned& r2, unsigned& r3) {
    asm volatile("ldmatrix.sync.aligned.m8n8.x4.shared.b16 {%0,%1,%2,%3}, [%4];"
                 : "=r"(r0), "=r"(r1), "=r"(r2), "=r"(r3) : "r"(a));
}
__device__ __forceinline__ void mma16816(float* c, const unsigned* a, const unsigned* b) {
    asm volatile(
        "mma.sync.aligned.m16n8k16.row.col.f32.bf16.bf16.f32 "
        "{%0,%1,%2,%3}, {%4,%5,%6,%7}, {%8,%9}, {%0,%1,%2,%3};"
        : "+f"(c[0]), "+f"(c[1]), "+f"(c[2]), "+f"(c[3])
        : "r"(a[0]), "r"(a[1]), "r"(a[2]), "r"(a[3]), "r"(b[0]), "r"(b[1]));
}
__device__ __forceinline__ void splitbf(float v, __nv_bfloat16& h, __nv_bfloat16& l) {
    h = __float2bfloat16(v);
    l = __float2bfloat16(v - __bfloat162float(h));
}

// ---------------- K1: adaFM spectra -> per-batch 64x64 conv matrices --------
__global__ void __launch_bounds__(256) k_prep(
    const float* __restrict__ t,
    const float* __restrict__ wmsa, const float* __restrict__ bmsa,
    const float* __restrict__ wmlp, const float* __restrict__ bmlp)
{
    int b = blockIdx.x, tid = threadIdx.x;
    __shared__ float st[640];
    __shared__ float s[2][40];
    __shared__ float seff[2][64];
    __shared__ float ker[2][64];

    for (int i = tid; i < 640; i += 256) {
        float v = t[b * 640 + i];
        st[i] = v / (1.f + __expf(-v));
    }
    __syncthreads();
    if (tid < 80) {
        int br = tid / 40, f = tid % 40;
        const float* w  = br ? wmlp : wmsa;
        const float* bb = br ? bmlp : bmsa;
        float acc = bb[f];
        for (int e = 0; e < 640; e++) acc = fmaf(st[e], w[f * 640 + e], acc);
        s[br][f] = acc;
    }
    __syncthreads();
    if (tid < 128) {
        int br = tid >> 6, i = tid & 63, k1 = i >> 3, k2 = i & 7;
        float v;
        if (k2 == 0 || k2 == 4)
            v = 0.5f * (s[br][k1 * 5 + k2] + s[br][((8 - k1) & 7) * 5 + k2]);
        else if (k2 < 4) v = s[br][k1 * 5 + k2];
        else             v = s[br][((8 - k1) & 7) * 5 + (8 - k2)];
        seff[br][i] = v;
    }
    __syncthreads();
    if (tid < 128) {
        int br = tid >> 6, i = tid & 63, d1 = i >> 3, d2 = i & 7;
        float acc = 0.f;
        #pragma unroll
        for (int k = 0; k < 64; k++)
            acc = fmaf(seff[br][k], c_cos8[((k >> 3) * d1 + (k & 7) * d2) & 7], acc);
        ker[br][i] = acc * (1.f / 64.f);
    }
    __syncthreads();
    for (int idx = tid; idx < 8192; idx += 256) {
        int br = idx >> 12, j = idx & 4095;
        int in = j >> 6, out = j & 63;
        g_M[br][b][j] = ker[br][(((out >> 3) - (in >> 3)) & 7) * 8 +
                               (((out & 7) - (in & 7)) & 7)];
    }
}

// ---------------- K1b: weight fp32 -> bf16 hi/lo -----------------------------
__global__ void k_wconv(const float* __restrict__ w,
                        __nv_bfloat16* __restrict__ h,
                        __nv_bfloat16* __restrict__ l, int n)
{
    int i = blockIdx.x * 256 + threadIdx.x;
    if (i >= n) return;
    __nv_bfloat16 hh, ll;
    splitbf(w[i], hh, ll);
    h[i] = hh; l[i] = ll;
}

// ---------------- K2: GroupNorm stats ---------------------------------------
__global__ void __launch_bounds__(256) k_gnstats(const float* __restrict__ x, int gi)
{
    int g = blockIdx.x, b = blockIdx.y;
    const float* p = x + ((size_t)b * 192 + g * 6) * 4096;
    float s = 0.f, s2 = 0.f;
    for (int i = threadIdx.x; i < 24576; i += 256) {
        float v = p[i]; s += v; s2 = fmaf(v, v, s2);
    }
    #pragma unroll
    for (int o = 16; o; o >>= 1) {
        s += __shfl_xor_sync(~0u, s, o); s2 += __shfl_xor_sync(~0u, s2, o);
    }
    __shared__ float sh[2][8];
    int wid = threadIdx.x >> 5;
    if (!(threadIdx.x & 31)) { sh[0][wid] = s; sh[1][wid] = s2; }
    __syncthreads();
    if (threadIdx.x < 32) {
        s  = (threadIdx.x < 8) ? sh[0][threadIdx.x] : 0.f;
        s2 = (threadIdx.x < 8) ? sh[1][threadIdx.x] : 0.f;
        #pragma unroll
        for (int o = 4; o; o >>= 1) {
            s += __shfl_xor_sync(~0u, s, o); s2 += __shfl_xor_sync(~0u, s2, o);
        }
        if (!threadIdx.x) {
            float m = s * (1.f / 24576.f);
            float var = s2 * (1.f / 24576.f) - m * m;
            g_gn[gi][b][g] = make_float2(m, rsqrtf(var + 1e-5f));
        }
    }
}

// ---------------- K3: GN apply + adafm patch GEMM + scatter (bf16 pair out) -
template <int MODE>
__global__ void __launch_bounds__(256) k_adafm(
    const float* __restrict__ src,
    const float* __restrict__ gw, const float* __restrict__ gbv)
{
    extern __shared__ float sm[];
    float* Xs = sm;               // 64 x 196
    float* Ms = sm + 64 * 196;    // 4096
    float* ga = Ms + 4096;        // 192
    float* gb = ga + 192;         // 192
    int patch = blockIdx.x, b = blockIdx.y;
    int py = patch >> 3, px = patch & 7, tid = threadIdx.x;

    if (tid < 192) {
        float2 st = g_gn[MODE][b][tid / 6];
        float a = st.y * gw[tid];
        ga[tid] = a; gb[tid] = gbv[tid] - st.x * a;
    }
    for (int i = tid; i < 4096; i += 256) Ms[i] = g_M[MODE][b][i];
    __syncthreads();

    int u = tid >> 5, cl = tid & 31;
    const float* sb = src + ((size_t)b * 192) * 4096 + (py * 8 + u) * 64 + px * 8;
    #pragma unroll
    for (int cb = 0; cb < 6; cb++) {
        int c = cb * 32 + cl;
        const float* pr = sb + (size_t)c * 4096;
        float4 v0 = *(const float4*)pr;
        float4 v1 = *(const float4*)(pr + 4);
        float a = ga[c], o = gb[c];
        float vv[8] = {v0.x, v0.y, v0.z, v0.w, v1.x, v1.y, v1.z, v1.w};
        #pragma unroll
        for (int j = 0; j < 8; j++)
            Xs[(u * 8 + j) * 196 + c] = fmaf(vv[j], a, o);
    }
    __syncthreads();

    int p = tid & 63, cg = tid >> 6;
    float4 acc[12];
    #pragma unroll
    for (int j = 0; j < 12; j++) acc[j] = make_float4(0.f, 0.f, 0.f, 0.f);
    for (int uu = 0; uu < 64; uu++) {
        float m = Ms[uu * 64 + p];
        const float4* xr = (const float4*)(Xs + uu * 196) + cg * 12;
        #pragma unroll
        for (int j = 0; j < 12; j++) {
            float4 xv = xr[j];
            acc[j].x = fmaf(m, xv.x, acc[j].x);
            acc[j].y = fmaf(m, xv.y, acc[j].y);
            acc[j].z = fmaf(m, xv.z, acc[j].z);
            acc[j].w = fmaf(m, xv.w, acc[j].w);
        }
    }
    int hh = py * 8 + (p >> 3), ww = px * 8 + (p & 7);
    size_t off;
    if (MODE == 0) {
        int hh2 = (hh + 60) & 63, ww2 = (ww + 60) & 63;
        int win = ((hh2 >> 3) << 3) | (ww2 >> 3);
        int nn  = ((hh2 & 7) << 3) | (ww2 & 7);
        off = (((size_t)(b * 64 + win) * 64 + nn) * 192) + cg * 48;
    } else {
        off = (((size_t)b * 4096 + hh * 64 + ww) * 192) + cg * 48;
    }
    #pragma unroll
    for (int j = 0; j < 12; j++) {
        float4 v = acc[j];
        __nv_bfloat16 h0, h1, h2, h3, l0, l1, l2, l3;
        splitbf(v.x, h0, l0); splitbf(v.y, h1, l1);
        splitbf(v.z, h2, l2); splitbf(v.w, h3, l3);
        *(ushort4*)(g_ah + off + j * 4) = make_ushort4(
            __bfloat16_as_ushort(h0), __bfloat16_as_ushort(h1),
            __bfloat16_as_ushort(h2), __bfloat16_as_ushort(h3));
        *(ushort4*)(g_al + off + j * 4) = make_ushort4(
            __bfloat16_as_ushort(l0), __bfloat16_as_ushort(l1),
            __bfloat16_as_ushort(l2), __bfloat16_as_ushort(l3));
    }
}

// ---------------- K4: 3-stage pipelined bf16-pair tensor GEMM ----------------
// C[m][n] = sum_k A[m][k]*W[n][k]; A,W pre-split bf16 hi/lo. Block 128x64, k-tile 32.
// EPI 0: +bias -> fp32 | 1: +bias GELU -> bf16 pair | 2: +bias win-rev+roll+res
// EPI 3: +bias chan-major + res
template <int EPI>
__global__ void __launch_bounds__(256, 2) k_bgemm(
    const __nv_bfloat16* __restrict__ Ah, const __nv_bfloat16* __restrict__ Al,
    const __nv_bfloat16* __restrict__ Wh, const __nv_bfloat16* __restrict__ Wl,
    const float* __restrict__ bias, float* __restrict__ Cf,
    __nv_bfloat16* __restrict__ Ch, __nv_bfloat16* __restrict__ Cl,
    int K, int N, const float* __restrict__ res)
{
    extern __shared__ __nv_bfloat16 smem[];
    const int ASZ = 128 * KSTR, BSZ = 64 * KSTR;
    const int STG = 2 * ASZ + 2 * BSZ;   // elems per stage (15360)

    int m0 = blockIdx.y * 128, n0 = blockIdx.x * 64;
    int tid = threadIdx.x, lane = tid & 31, wid = tid >> 5;
    int wm = (wid & 3) * 32, wn = (wid >> 2) * 32;

    const __nv_bfloat16* Abh = Ah + (size_t)m0 * K;
    const __nv_bfloat16* Abl = Al + (size_t)m0 * K;
    const __nv_bfloat16* Bbh = Wh + (size_t)n0 * K;
    const __nv_bfloat16* Bbl = Wl + (size_t)n0 * K;
    int KT = K >> 5;

    float c[2][4][4];
    #pragma unroll
    for (int mt = 0; mt < 2; mt++)
        #pragma unroll
        for (int nt = 0; nt < 4; nt++)
            #pragma unroll
            for (int i = 0; i < 4; i++) c[mt][nt][i] = 0.f;

    auto fill = [&](int kt) {
        __nv_bfloat16* base = smem + (kt % 3) * STG;
        int k0 = kt * 32;
        #pragma unroll
        for (int r = 0; r < 2; r++) {
            int e = tid * 2 + r, row = e >> 2, ch = e & 3;
            unsigned d = su32(base + row * KSTR + ch * 8);
            size_t srcoff = (size_t)row * K + k0 + ch * 8;
            cpasync16(d, Abh + srcoff);
            cpasync16(d + ASZ * 2, Abl + srcoff);
        }
        {
            int row = tid >> 2, ch = tid & 3;
            unsigned d = su32(base + 2 * ASZ + row * KSTR + ch * 8);
            size_t srcoff = (size_t)row * K + k0 + ch * 8;
            cpasync16(d, Bbh + srcoff);
            cpasync16(d + BSZ * 2, Bbl + srcoff);
        }
        cpcommit();
    };

    fill(0);
    if (KT > 1) fill(1);

    for (int kt = 0; kt < KT; kt++) {
        // wait for stage kt to land; deeper stages may still be in flight
        if (kt + 1 < KT) cpwait<1>(); else cpwait<0>();
        __syncthreads();
        if (kt + 2 < KT) fill(kt + 2);   // refill buffer freed by iter kt-1

        const __nv_bfloat16* base = smem + (kt % 3) * STG;
        unsigned sAh = su32(base);
        unsigned sAl = sAh + ASZ * 2;
        unsigned sBh = su32(base + 2 * ASZ);
        unsigned sBl = sBh + BSZ * 2;

        unsigned ah[2][2][4], al[2][2][4];
        #pragma unroll
        for (int mt = 0; mt < 2; mt++)
            #pragma unroll
            for (int kk = 0; kk < 2; kk++) {
                int row = wm + mt * 16 + (lane & 15);
                int col = kk * 16 + ((lane & 16) ? 8 : 0);
                unsigned off = (unsigned)((row * KSTR + col) * 2);
                ldsm4(sAh + off, ah[mt][kk][0], ah[mt][kk][1], ah[mt][kk][2], ah[mt][kk][3]);
                ldsm4(sAl + off, al[mt][kk][0], al[mt][kk][1], al[mt][kk][2], al[mt][kk][3]);
            }
        #pragma unroll
        for (int kk = 0; kk < 2; kk++) {
            unsigned bh[4][2], bl[4][2];
            #pragma unroll
            for (int ntp = 0; ntp < 2; ntp++) {
                int row = wn + ntp * 16 + ((lane & 16) ? 8 : 0) + (lane & 7);
                int col = kk * 16 + ((lane & 8) ? 8 : 0);
                unsigned off = (unsigned)((row * KSTR + col) * 2);
                unsigned r0, r1, r2, r3;
                ldsm4(sBh + off, r0, r1, r2, r3);
                bh[ntp * 2][0] = r0; bh[ntp * 2][1] = r1;
                bh[ntp * 2 + 1][0] = r2; bh[ntp * 2 + 1][1] = r3;
                ldsm4(sBl + off, r0, r1, r2, r3);
                bl[ntp * 2][0] = r0; bl[ntp * 2][1] = r1;
                bl[ntp * 2 + 1][0] = r2; bl[ntp * 2 + 1][1] = r3;
            }
            #pragma unroll
            for (int mt = 0; mt < 2; mt++)
                #pragma unroll
                for (int nt = 0; nt < 4; nt++) {
                    mma16816(c[mt][nt], ah[mt][kk], bh[nt]);
                    mma16816(c[mt][nt], ah[mt][kk], bl[nt]);
                    mma16816(c[mt][nt], al[mt][kk], bh[nt]);
                }
        }
        __syncthreads();
    }

    // epilogue: row = m0+wm+mt*16+(lane>>2)+h*8, col = n0+wn+nt*8+(lane&3)*2
    int g = lane >> 2, tg = lane & 3;
    #pragma unroll
    for (int nt = 0; nt < 4; nt++) {
        int cb = n0 + wn + nt * 8 + tg * 2;
        float2 bv = *(const float2*)(bias + cb);
        #pragma unroll
        for (int mt = 0; mt < 2; mt++)
            #pragma unroll
            for (int h = 0; h < 2; h++) {
                int m = m0 + wm + mt * 16 + g + h * 8;
                float v0 = c[mt][nt][h * 2 + 0] + bv.x;
                float v1 = c[mt][nt][h * 2 + 1] + bv.y;
                if (EPI == 0) {
                    *(float2*)(Cf + (size_t)m * N + cb) = make_float2(v0, v1);
                } else if (EPI == 1) {
                    float g0 = 0.5f * v0 * (1.f + erff(v0 * 0.70710678118654752f));
                    float g1 = 0.5f * v1 * (1.f + erff(v1 * 0.70710678118654752f));
                    __nv_bfloat16 h0, h1, l0, l1;
                    splitbf(g0, h0, l0); splitbf(g1, h1, l1);
                    unsigned hp = (unsigned)__bfloat16_as_ushort(h0) |
                                  ((unsigned)__bfloat16_as_ushort(h1) << 16);
                    unsigned lp = (unsigned)__bfloat16_as_ushort(l0) |
                                  ((unsigned)__bfloat16_as_ushort(l1) << 16);
                    *(unsigned*)(Ch + (size_t)m * N + cb) = hp;
                    *(unsigned*)(Cl + (size_t)m * N + cb) = lp;
                } else if (EPI == 2) {
                    int b = m >> 12, win = (m >> 6) & 63, nn = m & 63;
                    int hh = ((((win >> 3) << 3) + (nn >> 3)) + 4) & 63;
                    int ww = ((((win & 7) << 3) + (nn & 7)) + 4) & 63;
                    size_t base2 = ((size_t)b * 192) * 4096 + hh * 64 + ww;
                    size_t i0 = base2 + (size_t)cb * 4096;
                    size_t i1 = base2 + (size_t)(cb + 1) * 4096;
                    Cf[i0] = res[i0] + v0;
                    Cf[i1] = res[i1] + v1;
                } else {
                    int b = m >> 12, pix = m & 4095;
                    size_t i0 = ((size_t)(b * 192 + cb)) * 4096 + pix;
                    size_t i1 = i0 + 4096;
                    Cf[i0] = res[i0] + v0;
                    Cf[i1] = res[i1] + v1;
                }
            }
    }
}

// ---------------- K5: fused window attention (bf16 pair out) -----------------
__global__ void __launch_bounds__(64) k_attn(
    const float* __restrict__ qkv, const float* __restrict__ rpb)
{
    int w = blockIdx.x, head = blockIdx.y, n = threadIdx.x;
    __shared__ float Ks[64 * 32], Vs[64 * 32], Pr[64 * 64], Br[225];
    __shared__ int Cat[64];

    const float* base = qkv + (size_t)w * 64 * 576 + head * 32;
    {
        const float4* kp = (const float4*)(base + (size_t)n * 576 + 192);
        const float4* vp = (const float4*)(base + (size_t)n * 576 + 384);
        float4* kd = (float4*)(Ks + n * 32);
        float4* vd = (float4*)(Vs + n * 32);
        #pragma unroll
        for (int i = 0; i < 8; i++) { kd[i] = kp[i]; vd[i] = vp[i]; }
    }
    for (int i = n; i < 225; i += 64) Br[i] = rpb[i * 6 + head];
    {
        int win = w & 63;
        int hh2 = ((win >> 3) << 3) + (n >> 3);
        int ww2 = ((win & 7) << 3) + (n & 7);
        int ch = hh2 < 56 ? 0 : (hh2 < 60 ? 1 : 2);
        int cw = ww2 < 56 ? 0 : (ww2 < 60 ? 1 : 2);
        Cat[n] = ch * 3 + cw;
    }
    float q[32];
    {
        const float4* qp = (const float4*)(base + (size_t)n * 576);
        #pragma unroll
        for (int i = 0; i < 8; i++) {
            float4 v = qp[i];
            q[i * 4 + 0] = v.x * SCALE_Q; q[i * 4 + 1] = v.y * SCALE_Q;
            q[i * 4 + 2] = v.z * SCALE_Q; q[i * 4 + 3] = v.w * SCALE_Q;
        }
    }
    __syncthreads();

    int rn = n >> 3, cn = n & 7, mycat = Cat[n];
    float mx = -1e30f;
    for (int m = 0; m < 64; m++) {
        float d = 0.f;
        const float* kr = Ks + m * 32;
        #pragma unroll
        for (int i = 0; i < 32; i++) d = fmaf(q[i], kr[i], d);
        d += Br[(rn - (m >> 3) + 7) * 15 + (cn - (m & 7) + 7)];
        if (Cat[m] != mycat) d -= 100.f;
        Pr[m * 64 + n] = d;
        mx = fmaxf(mx, d);
    }
    float sum = 0.f;
    for (int m = 0; m < 64; m++) {
        float e = __expf(Pr[m * 64 + n] - mx);
        Pr[m * 64 + n] = e;
        sum += e;
    }
    float inv = 1.f / sum;
    float acc[32];
    #pragma unroll
    for (int i = 0; i < 32; i++) acc[i] = 0.f;
    for (int m = 0; m < 64; m++) {
        float p = Pr[m * 64 + n];
        const float* vr = Vs + m * 32;
        #pragma unroll
        for (int i = 0; i < 32; i++) acc[i] = fmaf(p, vr[i], acc[i]);
    }
    size_t off = ((size_t)w * 64 + n) * 192 + head * 32;
    #pragma unroll
    for (int i = 0; i < 8; i++) {
        __nv_bfloat16 h0, h1, h2, h3, l0, l1, l2, l3;
        splitbf(acc[i * 4 + 0] * inv, h0, l0);
        splitbf(acc[i * 4 + 1] * inv, h1, l1);
        splitbf(acc[i * 4 + 2] * inv, h2, l2);
        splitbf(acc[i * 4 + 3] * inv, h3, l3);
        *(ushort4*)(g_ah + off + i * 4) = make_ushort4(
            __bfloat16_as_ushort(h0), __bfloat16_as_ushort(h1),
            __bfloat16_as_ushort(h2), __bfloat16_as_ushort(h3));
        *(ushort4*)(g_al + off + i * 4) = make_ushort4(
            __bfloat16_as_ushort(l0), __bfloat16_as_ushort(l1),
            __bfloat16_as_ushort(l2), __bfloat16_as_ushort(l3));
    }
}

// ---------------- launch ------------------------------------------------------
extern "C" void kernel_launch(void* const* d_in, const int* in_sizes, int n_in,
                              void* d_out, int out_size)
{
    const float* x    = (const float*)d_in[0];
    const float* t    = (const float*)d_in[1];
    const float* n1w  = (const float*)d_in[2];
    const float* n1b  = (const float*)d_in[3];
    const float* qkvw = (const float*)d_in[4];
    const float* qkvb = (const float*)d_in[5];
    const float* rpb  = (const float*)d_in[6];
    const float* pw   = (const float*)d_in[7];
    const float* pb   = (const float*)d_in[8];
    const float* n2w  = (const float*)d_in[9];
    const float* n2b  = (const float*)d_in[10];
    const float* f1w  = (const float*)d_in[11];
    const float* f1b  = (const float*)d_in[12];
    const float* f2w  = (const float*)d_in[13];
    const float* f2b  = (const float*)d_in[14];
    const float* amw  = (const float*)d_in[15];
    const float* amb  = (const float*)d_in[16];
    const float* alw  = (const float*)d_in[17];
    const float* alb  = (const float*)d_in[18];
    float* out = (float*)d_out;

    float *qkvf, *x2;
    __nv_bfloat16 *ah, *al, *bh, *bl, *wh, *wl;
    cudaGetSymbolAddress((void**)&qkvf, g_qkv);
    cudaGetSymbolAddress((void**)&x2,   g_x2v);
    cudaGetSymbolAddress((void**)&ah,   g_ah);
    cudaGetSymbolAddress((void**)&al,   g_al);
    cudaGetSymbolAddress((void**)&bh,   g_bh);
    cudaGetSymbolAddress((void**)&bl,   g_bl);
    cudaGetSymbolAddress((void**)&wh,   g_wh);
    cudaGetSymbolAddress((void**)&wl,   g_wl);

    const int ADAFM_SMEM = (64 * 196 + 4096 + 384) * 4;
    const int GEMM_SMEM  = 3 * (2 * 128 * KSTR + 2 * 64 * KSTR) * 2;  // 92160 B
    static int attr_done = 0;
    if (!attr_done) {
        cudaFuncSetAttribute(k_adafm<0>, cudaFuncAttributeMaxDynamicSharedMemorySize, ADAFM_SMEM);
        cudaFuncSetAttribute(k_adafm<1>, cudaFuncAttributeMaxDynamicSharedMemorySize, ADAFM_SMEM);
        cudaFuncSetAttribute(k_bgemm<0>, cudaFuncAttributeMaxDynamicSharedMemorySize, GEMM_SMEM);
        cudaFuncSetAttribute(k_bgemm<1>, cudaFuncAttributeMaxDynamicSharedMemorySize, GEMM_SMEM);
        cudaFuncSetAttribute(k_bgemm<2>, cudaFuncAttributeMaxDynamicSharedMemorySize, GEMM_SMEM);
        cudaFuncSetAttribute(k_bgemm<3>, cudaFuncAttributeMaxDynamicSharedMemorySize, GEMM_SMEM);
        attr_done = 1;
    }

    k_prep<<<32, 256>>>(t, amw, amb, alw, alb);
    k_wconv<<<432, 256>>>(qkvw, wh, wl, 110592);
    k_wconv<<<144, 256>>>(pw,   wh + 110592, wl + 110592, 36864);
    k_wconv<<<576, 256>>>(f1w,  wh + 147456, wl + 147456, 147456);
    k_wconv<<<576, 256>>>(f2w,  wh + 294912, wl + 294912, 147456);

    k_gnstats<<<dim3(32, 32), 256>>>(x, 0);
    k_adafm<0><<<dim3(64, 32), 256, ADAFM_SMEM>>>(x, n1w, n1b);
    // qkv: (131072 x 192) @ (576 x 192)^T -> fp32
    k_bgemm<0><<<dim3(9, 1024), 256, GEMM_SMEM>>>(ah, al, wh, wl, qkvb,
                                                  qkvf, nullptr, nullptr, 192, 576, nullptr);
    k_attn<<<dim3(2048, 6), 64>>>(qkvf, rpb);
    // proj + window reverse + roll + residual -> x2
    k_bgemm<2><<<dim3(3, 1024), 256, GEMM_SMEM>>>(ah, al, wh + 110592, wl + 110592, pb,
                                                  x2, nullptr, nullptr, 192, 192, x);
    k_gnstats<<<dim3(32, 32), 256>>>(x2, 1);
    k_adafm<1><<<dim3(64, 32), 256, ADAFM_SMEM>>>(x2, n2w, n2b);
    // fc1 + GELU -> bf16 pair
    k_bgemm<1><<<dim3(12, 1024), 256, GEMM_SMEM>>>(ah, al, wh + 147456, wl + 147456, f1b,
                                                   nullptr, bh, bl, 192, 768, nullptr);
    // fc2 + residual scatter -> out
    k_bgemm<3><<<dim3(3, 1024), 256, GEMM_SMEM>>>(bh, bl, wh + 294912, wl + 294912, f2b,
                                                  out, nullptr, nullptr, 768, 192, x2);
}

// round 8
// speedup vs baseline: 1.4805x; 1.3787x over previous
#include <cuda_runtime.h>
#include <cuda_fp16.h>
#include <math.h>

#define SCALE_Q 0.17677669529663687f
#define KSTR 40   // smem row stride in halves (80B, conflict-free for LDSM)

// ---------------- scratch (device globals) ----------------------------------
__device__ float g_qkv[75497472];            // 131072 x 576 fp32
__device__ float g_x2v[25165824];            // x after attn residual (B,C,H,W)
__device__ __half g_a[25165824];             // activations fp16 (131072 x 192)
__device__ __half g_b[100663296];            // fc1 out fp16 (131072 x 768)
__device__ __half g_w[442368];               // weights fp16 (qkv|proj|fc1|fc2)
__device__ float g_M[2][32][4096];           // per-batch 64x64 patch conv matrices
__device__ float2 g_gn[2][32][32];           // (mean, rstd)

__constant__ float c_cos8[8] = {
    1.f, 0.70710678118654752f, 0.f, -0.70710678118654752f,
   -1.f, -0.70710678118654752f, 0.f, 0.70710678118654752f};

// ---------------- helpers ----------------------------------------------------
__device__ __forceinline__ unsigned su32(const void* p) {
    return (unsigned)__cvta_generic_to_shared(p);
}
__device__ __forceinline__ void cpasync16(unsigned dst, const void* src) {
    asm volatile("cp.async.ca.shared.global [%0], [%1], 16;" :: "r"(dst), "l"(src) : "memory");
}
__device__ __forceinline__ void cpcommit() {
    asm volatile("cp.async.commit_group;" ::: "memory");
}
template <int W> __device__ __forceinline__ void cpwait() {
    asm volatile("cp.async.wait_group %0;" :: "n"(W) : "memory");
}
__device__ __forceinline__ void ldsm4(unsigned a, unsigned& r0, unsigned& r1,
                                      unsigned& r2, unsigned& r3) {
    asm volatile("ldmatrix.sync.aligned.m8n8.x4.shared.b16 {%0,%1,%2,%3}, [%4];"
                 : "=r"(r0), "=r"(r1), "=r"(r2), "=r"(r3) : "r"(a));
}
__device__ __forceinline__ void mma16816(float* c, const unsigned* a, const unsigned* b) {
    asm volatile(
        "mma.sync.aligned.m16n8k16.row.col.f32.f16.f16.f32 "
        "{%0,%1,%2,%3}, {%4,%5,%6,%7}, {%8,%9}, {%0,%1,%2,%3};"
        : "+f"(c[0]), "+f"(c[1]), "+f"(c[2]), "+f"(c[3])
        : "r"(a[0]), "r"(a[1]), "r"(a[2]), "r"(a[3]), "r"(b[0]), "r"(b[1]));
}

// ---------------- K1: adaFM spectra -> per-batch 64x64 conv matrices --------
__global__ void __launch_bounds__(256) k_prep(
    const float* __restrict__ t,
    const float* __restrict__ wmsa, const float* __restrict__ bmsa,
    const float* __restrict__ wmlp, const float* __restrict__ bmlp)
{
    int b = blockIdx.x, tid = threadIdx.x;
    __shared__ float st[640];
    __shared__ float s[2][40];
    __shared__ float seff[2][64];
    __shared__ float ker[2][64];

    for (int i = tid; i < 640; i += 256) {
        float v = t[b * 640 + i];
        st[i] = v / (1.f + __expf(-v));
    }
    __syncthreads();
    if (tid < 80) {
        int br = tid / 40, f = tid % 40;
        const float* w  = br ? wmlp : wmsa;
        const float* bb = br ? bmlp : bmsa;
        float acc = bb[f];
        for (int e = 0; e < 640; e++) acc = fmaf(st[e], w[f * 640 + e], acc);
        s[br][f] = acc;
    }
    __syncthreads();
    if (tid < 128) {
        int br = tid >> 6, i = tid & 63, k1 = i >> 3, k2 = i & 7;
        float v;
        if (k2 == 0 || k2 == 4)
            v = 0.5f * (s[br][k1 * 5 + k2] + s[br][((8 - k1) & 7) * 5 + k2]);
        else if (k2 < 4) v = s[br][k1 * 5 + k2];
        else             v = s[br][((8 - k1) & 7) * 5 + (8 - k2)];
        seff[br][i] = v;
    }
    __syncthreads();
    if (tid < 128) {
        int br = tid >> 6, i = tid & 63, d1 = i >> 3, d2 = i & 7;
        float acc = 0.f;
        #pragma unroll
        for (int k = 0; k < 64; k++)
            acc = fmaf(seff[br][k], c_cos8[((k >> 3) * d1 + (k & 7) * d2) & 7], acc);
        ker[br][i] = acc * (1.f / 64.f);
    }
    __syncthreads();
    for (int idx = tid; idx < 8192; idx += 256) {
        int br = idx >> 12, j = idx & 4095;
        int in = j >> 6, out = j & 63;
        g_M[br][b][j] = ker[br][(((out >> 3) - (in >> 3)) & 7) * 8 +
                               (((out & 7) - (in & 7)) & 7)];
    }
}

// ---------------- K1b: weight fp32 -> fp16 -----------------------------------
__global__ void k_wconv(const float* __restrict__ w, __half* __restrict__ h, int n)
{
    int i = blockIdx.x * 256 + threadIdx.x;
    if (i < n) h[i] = __float2half_rn(w[i]);
}

// ---------------- K2: GroupNorm stats ---------------------------------------
__global__ void __launch_bounds__(256) k_gnstats(const float* __restrict__ x, int gi)
{
    int g = blockIdx.x, b = blockIdx.y;
    const float* p = x + ((size_t)b * 192 + g * 6) * 4096;
    float s = 0.f, s2 = 0.f;
    for (int i = threadIdx.x; i < 24576; i += 256) {
        float v = p[i]; s += v; s2 = fmaf(v, v, s2);
    }
    #pragma unroll
    for (int o = 16; o; o >>= 1) {
        s += __shfl_xor_sync(~0u, s, o); s2 += __shfl_xor_sync(~0u, s2, o);
    }
    __shared__ float sh[2][8];
    int wid = threadIdx.x >> 5;
    if (!(threadIdx.x & 31)) { sh[0][wid] = s; sh[1][wid] = s2; }
    __syncthreads();
    if (threadIdx.x < 32) {
        s  = (threadIdx.x < 8) ? sh[0][threadIdx.x] : 0.f;
        s2 = (threadIdx.x < 8) ? sh[1][threadIdx.x] : 0.f;
        #pragma unroll
        for (int o = 4; o; o >>= 1) {
            s += __shfl_xor_sync(~0u, s, o); s2 += __shfl_xor_sync(~0u, s2, o);
        }
        if (!threadIdx.x) {
            float m = s * (1.f / 24576.f);
            float var = s2 * (1.f / 24576.f) - m * m;
            g_gn[gi][b][g] = make_float2(m, rsqrtf(var + 1e-5f));
        }
    }
}

// ---------------- K3: GN apply + adafm patch GEMM + scatter (fp16 out) ------
template <int MODE>
__global__ void __launch_bounds__(256) k_adafm(
    const float* __restrict__ src,
    const float* __restrict__ gw, const float* __restrict__ gbv)
{
    extern __shared__ float sm[];
    float* Xs = sm;               // 64 x 196
    float* Ms = sm + 64 * 196;    // 4096
    float* ga = Ms + 4096;        // 192
    float* gb = ga + 192;         // 192
    int patch = blockIdx.x, b = blockIdx.y;
    int py = patch >> 3, px = patch & 7, tid = threadIdx.x;

    if (tid < 192) {
        float2 st = g_gn[MODE][b][tid / 6];
        float a = st.y * gw[tid];
        ga[tid] = a; gb[tid] = gbv[tid] - st.x * a;
    }
    for (int i = tid; i < 4096; i += 256) Ms[i] = g_M[MODE][b][i];
    __syncthreads();

    int u = tid >> 5, cl = tid & 31;
    const float* sb = src + ((size_t)b * 192) * 4096 + (py * 8 + u) * 64 + px * 8;
    #pragma unroll
    for (int cb = 0; cb < 6; cb++) {
        int c = cb * 32 + cl;
        const float* pr = sb + (size_t)c * 4096;
        float4 v0 = *(const float4*)pr;
        float4 v1 = *(const float4*)(pr + 4);
        float a = ga[c], o = gb[c];
        float vv[8] = {v0.x, v0.y, v0.z, v0.w, v1.x, v1.y, v1.z, v1.w};
        #pragma unroll
        for (int j = 0; j < 8; j++)
            Xs[(u * 8 + j) * 196 + c] = fmaf(vv[j], a, o);
    }
    __syncthreads();

    int p = tid & 63, cg = tid >> 6;
    float4 acc[12];
    #pragma unroll
    for (int j = 0; j < 12; j++) acc[j] = make_float4(0.f, 0.f, 0.f, 0.f);
    for (int uu = 0; uu < 64; uu++) {
        float m = Ms[uu * 64 + p];
        const float4* xr = (const float4*)(Xs + uu * 196) + cg * 12;
        #pragma unroll
        for (int j = 0; j < 12; j++) {
            float4 xv = xr[j];
            acc[j].x = fmaf(m, xv.x, acc[j].x);
            acc[j].y = fmaf(m, xv.y, acc[j].y);
            acc[j].z = fmaf(m, xv.z, acc[j].z);
            acc[j].w = fmaf(m, xv.w, acc[j].w);
        }
    }
    int hh = py * 8 + (p >> 3), ww = px * 8 + (p & 7);
    size_t off;
    if (MODE == 0) {
        int hh2 = (hh + 60) & 63, ww2 = (ww + 60) & 63;
        int win = ((hh2 >> 3) << 3) | (ww2 >> 3);
        int nn  = ((hh2 & 7) << 3) | (ww2 & 7);
        off = (((size_t)(b * 64 + win) * 64 + nn) * 192) + cg * 48;
    } else {
        off = (((size_t)b * 4096 + hh * 64 + ww) * 192) + cg * 48;
    }
    #pragma unroll
    for (int j = 0; j < 12; j++) {
        float4 v = acc[j];
        __half2 p0 = __floats2half2_rn(v.x, v.y);
        __half2 p1 = __floats2half2_rn(v.z, v.w);
        *(__half2*)(g_a + off + j * 4)     = p0;
        *(__half2*)(g_a + off + j * 4 + 2) = p1;
    }
}

// ---------------- K4: pipelined fp16 tensor GEMM, block 128x64, k-tile 32 ---
// C[m][n] = sum_k A[m][k]*W[n][k].
// EPI 0: +bias -> fp32 | 1: +bias GELU -> fp16 | 2: +bias win-rev+roll+res
// EPI 3: +bias chan-major + res
template <int EPI>
__global__ void __launch_bounds__(256, 2) k_hgemm(
    const __half* __restrict__ A, const __half* __restrict__ W,
    const float* __restrict__ bias, float* __restrict__ Cf,
    __half* __restrict__ Ch,
    int K, int N, const float* __restrict__ res)
{
    extern __shared__ __half smem[];
    const int ASZ = 128 * KSTR, BSZ = 64 * KSTR;
    const int STG = ASZ + BSZ;   // 7680 halves per stage

    int m0 = blockIdx.y * 128, n0 = blockIdx.x * 64;
    int tid = threadIdx.x, lane = tid & 31, wid = tid >> 5;
    int wm = (wid & 3) * 32, wn = (wid >> 2) * 32;

    const __half* Ab = A + (size_t)m0 * K;
    const __half* Bb = W + (size_t)n0 * K;
    int KT = K >> 5;

    float c[2][4][4];
    #pragma unroll
    for (int mt = 0; mt < 2; mt++)
        #pragma unroll
        for (int nt = 0; nt < 4; nt++)
            #pragma unroll
            for (int i = 0; i < 4; i++) c[mt][nt][i] = 0.f;

    auto fill = [&](int kt, int st) {
        __half* base = smem + st * STG;
        int k0 = kt * 32;
        #pragma unroll
        for (int r = 0; r < 2; r++) {    // A: 128 rows x 4 chunks of 8 halves
            int e = tid * 2 + r, row = e >> 2, ch = e & 3;
            unsigned d = su32(base + row * KSTR + ch * 8);
            cpasync16(d, Ab + (size_t)row * K + k0 + ch * 8);
        }
        {                                 // B: 64 rows x 4 chunks
            int row = tid >> 2, ch = tid & 3;
            unsigned d = su32(base + ASZ + row * KSTR + ch * 8);
            cpasync16(d, Bb + (size_t)row * K + k0 + ch * 8);
        }
        cpcommit();
    };

    fill(0, 0);
    for (int kt = 0; kt < KT; kt++) {
        if (kt + 1 < KT) { fill(kt + 1, (kt + 1) & 1); cpwait<1>(); }
        else             { cpwait<0>(); }
        __syncthreads();

        const __half* base = smem + (kt & 1) * STG;
        unsigned sA = su32(base);
        unsigned sB = su32(base + ASZ);

        unsigned a[2][2][4];
        #pragma unroll
        for (int mt = 0; mt < 2; mt++)
            #pragma unroll
            for (int kk = 0; kk < 2; kk++) {
                int row = wm + mt * 16 + (lane & 15);
                int col = kk * 16 + ((lane & 16) ? 8 : 0);
                unsigned off = (unsigned)((row * KSTR + col) * 2);
                ldsm4(sA + off, a[mt][kk][0], a[mt][kk][1], a[mt][kk][2], a[mt][kk][3]);
            }
        #pragma unroll
        for (int kk = 0; kk < 2; kk++) {
            unsigned bf[4][2];
            #pragma unroll
            for (int ntp = 0; ntp < 2; ntp++) {
                int row = wn + ntp * 16 + ((lane & 16) ? 8 : 0) + (lane & 7);
                int col = kk * 16 + ((lane & 8) ? 8 : 0);
                unsigned off = (unsigned)((row * KSTR + col) * 2);
                unsigned r0, r1, r2, r3;
                ldsm4(sB + off, r0, r1, r2, r3);
                bf[ntp * 2][0] = r0; bf[ntp * 2][1] = r1;
                bf[ntp * 2 + 1][0] = r2; bf[ntp * 2 + 1][1] = r3;
            }
            #pragma unroll
            for (int mt = 0; mt < 2; mt++)
                #pragma unroll
                for (int nt = 0; nt < 4; nt++)
                    mma16816(c[mt][nt], a[mt][kk], bf[nt]);
        }
        __syncthreads();
    }

    // epilogue: row = m0+wm+mt*16+(lane>>2)+h*8, col = n0+wn+nt*8+(lane&3)*2
    int g = lane >> 2, tg = lane & 3;
    #pragma unroll
    for (int nt = 0; nt < 4; nt++) {
        int cb = n0 + wn + nt * 8 + tg * 2;
        float2 bv = *(const float2*)(bias + cb);
        #pragma unroll
        for (int mt = 0; mt < 2; mt++)
            #pragma unroll
            for (int h = 0; h < 2; h++) {
                int m = m0 + wm + mt * 16 + g + h * 8;
                float v0 = c[mt][nt][h * 2 + 0] + bv.x;
                float v1 = c[mt][nt][h * 2 + 1] + bv.y;
                if (EPI == 0) {
                    *(float2*)(Cf + (size_t)m * N + cb) = make_float2(v0, v1);
                } else if (EPI == 1) {
                    float g0 = 0.5f * v0 * (1.f + erff(v0 * 0.70710678118654752f));
                    float g1 = 0.5f * v1 * (1.f + erff(v1 * 0.70710678118654752f));
                    *(__half2*)(Ch + (size_t)m * N + cb) = __floats2half2_rn(g0, g1);
                } else if (EPI == 2) {
                    int b = m >> 12, win = (m >> 6) & 63, nn = m & 63;
                    int hh = ((((win >> 3) << 3) + (nn >> 3)) + 4) & 63;
                    int ww = ((((win & 7) << 3) + (nn & 7)) + 4) & 63;
                    size_t base2 = ((size_t)b * 192) * 4096 + hh * 64 + ww;
                    size_t i0 = base2 + (size_t)cb * 4096;
                    size_t i1 = base2 + (size_t)(cb + 1) * 4096;
                    Cf[i0] = res[i0] + v0;
                    Cf[i1] = res[i1] + v1;
                } else {
                    int b = m >> 12, pix = m & 4095;
                    size_t i0 = ((size_t)(b * 192 + cb)) * 4096 + pix;
                    size_t i1 = i0 + 4096;
                    Cf[i0] = res[i0] + v0;
                    Cf[i1] = res[i1] + v1;
                }
            }
    }
}

// ---------------- K5: fused window attention (fp16 out) ----------------------
__global__ void __launch_bounds__(64) k_attn(
    const float* __restrict__ qkv, const float* __restrict__ rpb)
{
    int w = blockIdx.x, head = blockIdx.y, n = threadIdx.x;
    __shared__ float Ks[64 * 32], Vs[64 * 32], Pr[64 * 64], Br[225];
    __shared__ int Cat[64];

    const float* base = qkv + (size_t)w * 64 * 576 + head * 32;
    {
        const float4* kp = (const float4*)(base + (size_t)n * 576 + 192);
        const float4* vp = (const float4*)(base + (size_t)n * 576 + 384);
        float4* kd = (float4*)(Ks + n * 32);
        float4* vd = (float4*)(Vs + n * 32);
        #pragma unroll
        for (int i = 0; i < 8; i++) { kd[i] = kp[i]; vd[i] = vp[i]; }
    }
    for (int i = n; i < 225; i += 64) Br[i] = rpb[i * 6 + head];
    {
        int win = w & 63;
        int hh2 = ((win >> 3) << 3) + (n >> 3);
        int ww2 = ((win & 7) << 3) + (n & 7);
        int ch = hh2 < 56 ? 0 : (hh2 < 60 ? 1 : 2);
        int cw = ww2 < 56 ? 0 : (ww2 < 60 ? 1 : 2);
        Cat[n] = ch * 3 + cw;
    }
    float q[32];
    {
        const float4* qp = (const float4*)(base + (size_t)n * 576);
        #pragma unroll
        for (int i = 0; i < 8; i++) {
            float4 v = qp[i];
            q[i * 4 + 0] = v.x * SCALE_Q; q[i * 4 + 1] = v.y * SCALE_Q;
            q[i * 4 + 2] = v.z * SCALE_Q; q[i * 4 + 3] = v.w * SCALE_Q;
        }
    }
    __syncthreads();

    int rn = n >> 3, cn = n & 7, mycat = Cat[n];
    float mx = -1e30f;
    for (int m = 0; m < 64; m++) {
        float d = 0.f;
        const float* kr = Ks + m * 32;
        #pragma unroll
        for (int i = 0; i < 32; i++) d = fmaf(q[i], kr[i], d);
        d += Br[(rn - (m >> 3) + 7) * 15 + (cn - (m & 7) + 7)];
        if (Cat[m] != mycat) d -= 100.f;
        Pr[m * 64 + n] = d;
        mx = fmaxf(mx, d);
    }
    float sum = 0.f;
    for (int m = 0; m < 64; m++) {
        float e = __expf(Pr[m * 64 + n] - mx);
        Pr[m * 64 + n] = e;
        sum += e;
    }
    float inv = 1.f / sum;
    float acc[32];
    #pragma unroll
    for (int i = 0; i < 32; i++) acc[i] = 0.f;
    for (int m = 0; m < 64; m++) {
        float p = Pr[m * 64 + n];
        const float* vr = Vs + m * 32;
        #pragma unroll
        for (int i = 0; i < 32; i++) acc[i] = fmaf(p, vr[i], acc[i]);
    }
    size_t off = ((size_t)w * 64 + n) * 192 + head * 32;
    #pragma unroll
    for (int i = 0; i < 8; i++) {
        __half2 p0 = __floats2half2_rn(acc[i * 4 + 0] * inv, acc[i * 4 + 1] * inv);
        __half2 p1 = __floats2half2_rn(acc[i * 4 + 2] * inv, acc[i * 4 + 3] * inv);
        *(__half2*)(g_a + off + i * 4)     = p0;
        *(__half2*)(g_a + off + i * 4 + 2) = p1;
    }
}

// ---------------- launch ------------------------------------------------------
extern "C" void kernel_launch(void* const* d_in, const int* in_sizes, int n_in,
                              void* d_out, int out_size)
{
    const float* x    = (const float*)d_in[0];
    const float* t    = (const float*)d_in[1];
    const float* n1w  = (const float*)d_in[2];
    const float* n1b  = (const float*)d_in[3];
    const float* qkvw = (const float*)d_in[4];
    const float* qkvb = (const float*)d_in[5];
    const float* rpb  = (const float*)d_in[6];
    const float* pw   = (const float*)d_in[7];
    const float* pb   = (const float*)d_in[8];
    const float* n2w  = (const float*)d_in[9];
    const float* n2b  = (const float*)d_in[10];
    const float* f1w  = (const float*)d_in[11];
    const float* f1b  = (const float*)d_in[12];
    const float* f2w  = (const float*)d_in[13];
    const float* f2b  = (const float*)d_in[14];
    const float* amw  = (const float*)d_in[15];
    const float* amb  = (const float*)d_in[16];
    const float* alw  = (const float*)d_in[17];
    const float* alb  = (const float*)d_in[18];
    float* out = (float*)d_out;

    float *qkvf, *x2;
    __half *a16, *b16, *w16;
    cudaGetSymbolAddress((void**)&qkvf, g_qkv);
    cudaGetSymbolAddress((void**)&x2,   g_x2v);
    cudaGetSymbolAddress((void**)&a16,  g_a);
    cudaGetSymbolAddress((void**)&b16,  g_b);
    cudaGetSymbolAddress((void**)&w16,  g_w);

    const int ADAFM_SMEM = (64 * 196 + 4096 + 384) * 4;
    const int GEMM_SMEM  = 2 * (128 * KSTR + 64 * KSTR) * 2;  // 30720 B
    static int attr_done = 0;
    if (!attr_done) {
        cudaFuncSetAttribute(k_adafm<0>, cudaFuncAttributeMaxDynamicSharedMemorySize, ADAFM_SMEM);
        cudaFuncSetAttribute(k_adafm<1>, cudaFuncAttributeMaxDynamicSharedMemorySize, ADAFM_SMEM);
        cudaFuncSetAttribute(k_hgemm<0>, cudaFuncAttributeMaxDynamicSharedMemorySize, GEMM_SMEM);
        cudaFuncSetAttribute(k_hgemm<1>, cudaFuncAttributeMaxDynamicSharedMemorySize, GEMM_SMEM);
        cudaFuncSetAttribute(k_hgemm<2>, cudaFuncAttributeMaxDynamicSharedMemorySize, GEMM_SMEM);
        cudaFuncSetAttribute(k_hgemm<3>, cudaFuncAttributeMaxDynamicSharedMemorySize, GEMM_SMEM);
        attr_done = 1;
    }

    k_prep<<<32, 256>>>(t, amw, amb, alw, alb);
    k_wconv<<<432, 256>>>(qkvw, w16, 110592);
    k_wconv<<<144, 256>>>(pw,   w16 + 110592, 36864);
    k_wconv<<<576, 256>>>(f1w,  w16 + 147456, 147456);
    k_wconv<<<576, 256>>>(f2w,  w16 + 294912, 147456);

    k_gnstats<<<dim3(32, 32), 256>>>(x, 0);
    k_adafm<0><<<dim3(64, 32), 256, ADAFM_SMEM>>>(x, n1w, n1b);
    // qkv: (131072 x 192) @ (576 x 192)^T -> fp32
    k_hgemm<0><<<dim3(9, 1024), 256, GEMM_SMEM>>>(a16, w16, qkvb,
                                                  qkvf, nullptr, 192, 576, nullptr);
    k_attn<<<dim3(2048, 6), 64>>>(qkvf, rpb);
    // proj + window reverse + roll + residual -> x2
    k_hgemm<2><<<dim3(3, 1024), 256, GEMM_SMEM>>>(a16, w16 + 110592, pb,
                                                  x2, nullptr, 192, 192, x);
    k_gnstats<<<dim3(32, 32), 256>>>(x2, 1);
    k_adafm<1><<<dim3(64, 32), 256, ADAFM_SMEM>>>(x2, n2w, n2b);
    // fc1 + GELU -> fp16
    k_hgemm<1><<<dim3(12, 1024), 256, GEMM_SMEM>>>(a16, w16 + 147456, f1b,
                                                   nullptr, b16, 192, 768, nullptr);
    // fc2 + residual scatter -> out
    k_hgemm<3><<<dim3(3, 1024), 256, GEMM_SMEM>>>(b16, w16 + 294912, f2b,
                                                  out, nullptr, 768, 192, x2);
}

// round 9
// speedup vs baseline: 1.8698x; 1.2630x over previous
#include <cuda_runtime.h>
#include <cuda_fp16.h>
#include <math.h>

#define SCALE_Q 0.17677669529663687f
#define KSTR 40   // smem row stride in halves (80B, conflict-free for LDSM)

// ---------------- scratch (device globals) ----------------------------------
__device__ float g_x2v[25165824];            // x after attn residual (B,C,H,W)
__device__ __half g_a[25165824];             // activations fp16 (131072 x 192)
__device__ __half g_b[100663296];            // qkv (131072x576) then fc1 out (131072x768)
__device__ __half g_w[442368];               // weights fp16 (qkv|proj|fc1|fc2)
__device__ float g_M[2][32][4096];           // per-batch 64x64 patch conv matrices
__device__ float2 g_gn[2][32][32];           // (mean, rstd)

__constant__ float c_cos8[8] = {
    1.f, 0.70710678118654752f, 0.f, -0.70710678118654752f,
   -1.f, -0.70710678118654752f, 0.f, 0.70710678118654752f};

// ---------------- helpers ----------------------------------------------------
__device__ __forceinline__ unsigned su32(const void* p) {
    return (unsigned)__cvta_generic_to_shared(p);
}
__device__ __forceinline__ void cpasync16(unsigned dst, const void* src) {
    asm volatile("cp.async.ca.shared.global [%0], [%1], 16;" :: "r"(dst), "l"(src) : "memory");
}
__device__ __forceinline__ void cpcommit() {
    asm volatile("cp.async.commit_group;" ::: "memory");
}
template <int W> __device__ __forceinline__ void cpwait() {
    asm volatile("cp.async.wait_group %0;" :: "n"(W) : "memory");
}
__device__ __forceinline__ void ldsm4(unsigned a, unsigned& r0, unsigned& r1,
                                      unsigned& r2, unsigned& r3) {
    asm volatile("ldmatrix.sync.aligned.m8n8.x4.shared.b16 {%0,%1,%2,%3}, [%4];"
                 : "=r"(r0), "=r"(r1), "=r"(r2), "=r"(r3) : "r"(a));
}
__device__ __forceinline__ void ldsm4t(unsigned a, unsigned& r0, unsigned& r1,
                                       unsigned& r2, unsigned& r3) {
    asm volatile("ldmatrix.sync.aligned.m8n8.x4.trans.shared.b16 {%0,%1,%2,%3}, [%4];"
                 : "=r"(r0), "=r"(r1), "=r"(r2), "=r"(r3) : "r"(a));
}
__device__ __forceinline__ void mma16816(float* c, const unsigned* a, const unsigned* b) {
    asm volatile(
        "mma.sync.aligned.m16n8k16.row.col.f32.f16.f16.f32 "
        "{%0,%1,%2,%3}, {%4,%5,%6,%7}, {%8,%9}, {%0,%1,%2,%3};"
        : "+f"(c[0]), "+f"(c[1]), "+f"(c[2]), "+f"(c[3])
        : "r"(a[0]), "r"(a[1]), "r"(a[2]), "r"(a[3]), "r"(b[0]), "r"(b[1]));
}
__device__ __forceinline__ unsigned packh2(float x, float y) {
    __half2 h = __floats2half2_rn(x, y);
    return *(unsigned*)&h;
}

// ---------------- K1: adaFM spectra -> per-batch 64x64 conv matrices --------
__global__ void __launch_bounds__(256) k_prep(
    const float* __restrict__ t,
    const float* __restrict__ wmsa, const float* __restrict__ bmsa,
    const float* __restrict__ wmlp, const float* __restrict__ bmlp)
{
    int b = blockIdx.x, tid = threadIdx.x;
    __shared__ float st[640];
    __shared__ float s[2][40];
    __shared__ float seff[2][64];
    __shared__ float ker[2][64];

    for (int i = tid; i < 640; i += 256) {
        float v = t[b * 640 + i];
        st[i] = v / (1.f + __expf(-v));
    }
    __syncthreads();
    if (tid < 80) {
        int br = tid / 40, f = tid % 40;
        const float* w  = br ? wmlp : wmsa;
        const float* bb = br ? bmlp : bmsa;
        float acc = bb[f];
        for (int e = 0; e < 640; e++) acc = fmaf(st[e], w[f * 640 + e], acc);
        s[br][f] = acc;
    }
    __syncthreads();
    if (tid < 128) {
        int br = tid >> 6, i = tid & 63, k1 = i >> 3, k2 = i & 7;
        float v;
        if (k2 == 0 || k2 == 4)
            v = 0.5f * (s[br][k1 * 5 + k2] + s[br][((8 - k1) & 7) * 5 + k2]);
        else if (k2 < 4) v = s[br][k1 * 5 + k2];
        else             v = s[br][((8 - k1) & 7) * 5 + (8 - k2)];
        seff[br][i] = v;
    }
    __syncthreads();
    if (tid < 128) {
        int br = tid >> 6, i = tid & 63, d1 = i >> 3, d2 = i & 7;
        float acc = 0.f;
        #pragma unroll
        for (int k = 0; k < 64; k++)
            acc = fmaf(seff[br][k], c_cos8[((k >> 3) * d1 + (k & 7) * d2) & 7], acc);
        ker[br][i] = acc * (1.f / 64.f);
    }
    __syncthreads();
    for (int idx = tid; idx < 8192; idx += 256) {
        int br = idx >> 12, j = idx & 4095;
        int in = j >> 6, out = j & 63;
        g_M[br][b][j] = ker[br][(((out >> 3) - (in >> 3)) & 7) * 8 +
                               (((out & 7) - (in & 7)) & 7)];
    }
}

// ---------------- K1b: weight fp32 -> fp16 -----------------------------------
__global__ void k_wconv(const float* __restrict__ w, __half* __restrict__ h, int n)
{
    int i = blockIdx.x * 256 + threadIdx.x;
    if (i < n) h[i] = __float2half_rn(w[i]);
}

// ---------------- K2: GroupNorm stats ---------------------------------------
__global__ void __launch_bounds__(256) k_gnstats(const float* __restrict__ x, int gi)
{
    int g = blockIdx.x, b = blockIdx.y;
    const float* p = x + ((size_t)b * 192 + g * 6) * 4096;
    float s = 0.f, s2 = 0.f;
    for (int i = threadIdx.x; i < 24576; i += 256) {
        float v = p[i]; s += v; s2 = fmaf(v, v, s2);
    }
    #pragma unroll
    for (int o = 16; o; o >>= 1) {
        s += __shfl_xor_sync(~0u, s, o); s2 += __shfl_xor_sync(~0u, s2, o);
    }
    __shared__ float sh[2][8];
    int wid = threadIdx.x >> 5;
    if (!(threadIdx.x & 31)) { sh[0][wid] = s; sh[1][wid] = s2; }
    __syncthreads();
    if (threadIdx.x < 32) {
        s  = (threadIdx.x < 8) ? sh[0][threadIdx.x] : 0.f;
        s2 = (threadIdx.x < 8) ? sh[1][threadIdx.x] : 0.f;
        #pragma unroll
        for (int o = 4; o; o >>= 1) {
            s += __shfl_xor_sync(~0u, s, o); s2 += __shfl_xor_sync(~0u, s2, o);
        }
        if (!threadIdx.x) {
            float m = s * (1.f / 24576.f);
            float var = s2 * (1.f / 24576.f) - m * m;
            g_gn[gi][b][g] = make_float2(m, rsqrtf(var + 1e-5f));
        }
    }
}

// ---------------- K3: GN apply + adafm patch GEMM + scatter (fp16 out) ------
template <int MODE>
__global__ void __launch_bounds__(256) k_adafm(
    const float* __restrict__ src,
    const float* __restrict__ gw, const float* __restrict__ gbv)
{
    extern __shared__ float sm[];
    float* Xs = sm;               // 64 x 196
    float* Ms = sm + 64 * 196;    // 4096
    float* ga = Ms + 4096;        // 192
    float* gb = ga + 192;         // 192
    int patch = blockIdx.x, b = blockIdx.y;
    int py = patch >> 3, px = patch & 7, tid = threadIdx.x;

    if (tid < 192) {
        float2 st = g_gn[MODE][b][tid / 6];
        float a = st.y * gw[tid];
        ga[tid] = a; gb[tid] = gbv[tid] - st.x * a;
    }
    for (int i = tid; i < 4096; i += 256) Ms[i] = g_M[MODE][b][i];
    __syncthreads();

    int u = tid >> 5, cl = tid & 31;
    const float* sb = src + ((size_t)b * 192) * 4096 + (py * 8 + u) * 64 + px * 8;
    #pragma unroll
    for (int cb = 0; cb < 6; cb++) {
        int c = cb * 32 + cl;
        const float* pr = sb + (size_t)c * 4096;
        float4 v0 = *(const float4*)pr;
        float4 v1 = *(const float4*)(pr + 4);
        float a = ga[c], o = gb[c];
        float vv[8] = {v0.x, v0.y, v0.z, v0.w, v1.x, v1.y, v1.z, v1.w};
        #pragma unroll
        for (int j = 0; j < 8; j++)
            Xs[(u * 8 + j) * 196 + c] = fmaf(vv[j], a, o);
    }
    __syncthreads();

    int p = tid & 63, cg = tid >> 6;
    float4 acc[12];
    #pragma unroll
    for (int j = 0; j < 12; j++) acc[j] = make_float4(0.f, 0.f, 0.f, 0.f);
    for (int uu = 0; uu < 64; uu++) {
        float m = Ms[uu * 64 + p];
        const float4* xr = (const float4*)(Xs + uu * 196) + cg * 12;
        #pragma unroll
        for (int j = 0; j < 12; j++) {
            float4 xv = xr[j];
            acc[j].x = fmaf(m, xv.x, acc[j].x);
            acc[j].y = fmaf(m, xv.y, acc[j].y);
            acc[j].z = fmaf(m, xv.z, acc[j].z);
            acc[j].w = fmaf(m, xv.w, acc[j].w);
        }
    }
    int hh = py * 8 + (p >> 3), ww = px * 8 + (p & 7);
    size_t off;
    if (MODE == 0) {
        int hh2 = (hh + 60) & 63, ww2 = (ww + 60) & 63;
        int win = ((hh2 >> 3) << 3) | (ww2 >> 3);
        int nn  = ((hh2 & 7) << 3) | (ww2 & 7);
        off = (((size_t)(b * 64 + win) * 64 + nn) * 192) + cg * 48;
    } else {
        off = (((size_t)b * 4096 + hh * 64 + ww) * 192) + cg * 48;
    }
    #pragma unroll
    for (int j = 0; j < 12; j++) {
        float4 v = acc[j];
        *(__half2*)(g_a + off + j * 4)     = __floats2half2_rn(v.x, v.y);
        *(__half2*)(g_a + off + j * 4 + 2) = __floats2half2_rn(v.z, v.w);
    }
}

// ---------------- K4: pipelined fp16 tensor GEMM, block 128x64, k-tile 32 ---
// EPI 0: +bias -> fp16 (qkv) | 1: +bias GELU -> fp16 | 2: +bias win-rev+roll+res
// EPI 3: +bias chan-major + res
template <int EPI>
__global__ void __launch_bounds__(256, 2) k_hgemm(
    const __half* __restrict__ A, const __half* __restrict__ W,
    const float* __restrict__ bias, float* __restrict__ Cf,
    __half* __restrict__ Ch,
    int K, int N, const float* __restrict__ res)
{
    extern __shared__ __half smem[];
    const int ASZ = 128 * KSTR, BSZ = 64 * KSTR;
    const int STG = ASZ + BSZ;

    int m0 = blockIdx.y * 128, n0 = blockIdx.x * 64;
    int tid = threadIdx.x, lane = tid & 31, wid = tid >> 5;
    int wm = (wid & 3) * 32, wn = (wid >> 2) * 32;

    const __half* Ab = A + (size_t)m0 * K;
    const __half* Bb = W + (size_t)n0 * K;
    int KT = K >> 5;

    float c[2][4][4];
    #pragma unroll
    for (int mt = 0; mt < 2; mt++)
        #pragma unroll
        for (int nt = 0; nt < 4; nt++)
            #pragma unroll
            for (int i = 0; i < 4; i++) c[mt][nt][i] = 0.f;

    auto fill = [&](int kt, int st) {
        __half* base = smem + st * STG;
        int k0 = kt * 32;
        #pragma unroll
        for (int r = 0; r < 2; r++) {
            int e = tid * 2 + r, row = e >> 2, ch = e & 3;
            unsigned d = su32(base + row * KSTR + ch * 8);
            cpasync16(d, Ab + (size_t)row * K + k0 + ch * 8);
        }
        {
            int row = tid >> 2, ch = tid & 3;
            unsigned d = su32(base + ASZ + row * KSTR + ch * 8);
            cpasync16(d, Bb + (size_t)row * K + k0 + ch * 8);
        }
        cpcommit();
    };

    fill(0, 0);
    for (int kt = 0; kt < KT; kt++) {
        if (kt + 1 < KT) { fill(kt + 1, (kt + 1) & 1); cpwait<1>(); }
        else             { cpwait<0>(); }
        __syncthreads();

        const __half* base = smem + (kt & 1) * STG;
        unsigned sA = su32(base);
        unsigned sB = su32(base + ASZ);

        unsigned a[2][2][4];
        #pragma unroll
        for (int mt = 0; mt < 2; mt++)
            #pragma unroll
            for (int kk = 0; kk < 2; kk++) {
                int row = wm + mt * 16 + (lane & 15);
                int col = kk * 16 + ((lane & 16) ? 8 : 0);
                unsigned off = (unsigned)((row * KSTR + col) * 2);
                ldsm4(sA + off, a[mt][kk][0], a[mt][kk][1], a[mt][kk][2], a[mt][kk][3]);
            }
        #pragma unroll
        for (int kk = 0; kk < 2; kk++) {
            unsigned bf[4][2];
            #pragma unroll
            for (int ntp = 0; ntp < 2; ntp++) {
                int row = wn + ntp * 16 + ((lane & 16) ? 8 : 0) + (lane & 7);
                int col = kk * 16 + ((lane & 8) ? 8 : 0);
                unsigned off = (unsigned)((row * KSTR + col) * 2);
                unsigned r0, r1, r2, r3;
                ldsm4(sB + off, r0, r1, r2, r3);
                bf[ntp * 2][0] = r0; bf[ntp * 2][1] = r1;
                bf[ntp * 2 + 1][0] = r2; bf[ntp * 2 + 1][1] = r3;
            }
            #pragma unroll
            for (int mt = 0; mt < 2; mt++)
                #pragma unroll
                for (int nt = 0; nt < 4; nt++)
                    mma16816(c[mt][nt], a[mt][kk], bf[nt]);
        }
        __syncthreads();
    }

    int g = lane >> 2, tg = lane & 3;
    #pragma unroll
    for (int nt = 0; nt < 4; nt++) {
        int cb = n0 + wn + nt * 8 + tg * 2;
        float2 bv = *(const float2*)(bias + cb);
        #pragma unroll
        for (int mt = 0; mt < 2; mt++)
            #pragma unroll
            for (int h = 0; h < 2; h++) {
                int m = m0 + wm + mt * 16 + g + h * 8;
                float v0 = c[mt][nt][h * 2 + 0] + bv.x;
                float v1 = c[mt][nt][h * 2 + 1] + bv.y;
                if (EPI == 0) {
                    *(__half2*)(Ch + (size_t)m * N + cb) = __floats2half2_rn(v0, v1);
                } else if (EPI == 1) {
                    float g0 = 0.5f * v0 * (1.f + erff(v0 * 0.70710678118654752f));
                    float g1 = 0.5f * v1 * (1.f + erff(v1 * 0.70710678118654752f));
                    *(__half2*)(Ch + (size_t)m * N + cb) = __floats2half2_rn(g0, g1);
                } else if (EPI == 2) {
                    int b = m >> 12, win = (m >> 6) & 63, nn = m & 63;
                    int hh = ((((win >> 3) << 3) + (nn >> 3)) + 4) & 63;
                    int ww = ((((win & 7) << 3) + (nn & 7)) + 4) & 63;
                    size_t base2 = ((size_t)b * 192) * 4096 + hh * 64 + ww;
                    size_t i0 = base2 + (size_t)cb * 4096;
                    size_t i1 = base2 + (size_t)(cb + 1) * 4096;
                    Cf[i0] = res[i0] + v0;
                    Cf[i1] = res[i1] + v1;
                } else {
                    int b = m >> 12, pix = m & 4095;
                    size_t i0 = ((size_t)(b * 192 + cb)) * 4096 + pix;
                    size_t i1 = i0 + 4096;
                    Cf[i0] = res[i0] + v0;
                    Cf[i1] = res[i1] + v1;
                }
            }
    }
}

// ---------------- K5: tensor-core window attention ---------------------------
// block = (window, head), 128 threads (4 warps); warp wq owns query rows wq*16..+15.
__global__ void __launch_bounds__(128) k_attn_tc(
    const __half* __restrict__ qkv, const float* __restrict__ rpb)
{
    __shared__ __half Qs[64 * KSTR], Ks[64 * KSTR], Vs[64 * KSTR];
    __shared__ float Br[225];
    __shared__ int Cat[64];

    int w = blockIdx.x, head = blockIdx.y;
    int tid = threadIdx.x, lane = tid & 31, wq = tid >> 5;

    // load Q,K,V tiles (64 x 32 halves each) via cp.async
    const __half* base = qkv + (size_t)w * 64 * 576 + head * 32;
    #pragma unroll
    for (int r = 0; r < 2; r++) {
        int idx = tid + r * 128;           // 0..255
        int row = idx >> 2, ch = idx & 3;
        const __half* src = base + (size_t)row * 576 + ch * 8;
        unsigned doff = (unsigned)((row * KSTR + ch * 8) * 2);
        cpasync16(su32(Qs) + doff, src);
        cpasync16(su32(Ks) + doff, src + 192);
        cpasync16(su32(Vs) + doff, src + 384);
    }
    cpcommit();

    for (int i = tid; i < 225; i += 128) Br[i] = rpb[i * 6 + head];
    if (tid < 64) {
        int win = w & 63;
        int hh2 = ((win >> 3) << 3) + (tid >> 3);
        int ww2 = ((win & 7) << 3) + (tid & 7);
        int ch = hh2 < 56 ? 0 : (hh2 < 60 ? 1 : 2);
        int cw = ww2 < 56 ? 0 : (ww2 < 60 ? 1 : 2);
        Cat[tid] = ch * 3 + cw;
    }
    cpwait<0>();
    __syncthreads();

    int g = lane >> 2, tg = lane & 3;

    // ---- S = Q @ K^T : c[8 ntiles][4] ----
    float c[8][4];
    #pragma unroll
    for (int nt = 0; nt < 8; nt++)
        #pragma unroll
        for (int i = 0; i < 4; i++) c[nt][i] = 0.f;

    unsigned aq[2][4];
    #pragma unroll
    for (int kk = 0; kk < 2; kk++) {
        int row = wq * 16 + (lane & 15);
        int col = kk * 16 + ((lane & 16) ? 8 : 0);
        ldsm4(su32(Qs) + (unsigned)((row * KSTR + col) * 2),
              aq[kk][0], aq[kk][1], aq[kk][2], aq[kk][3]);
    }
    #pragma unroll
    for (int kk = 0; kk < 2; kk++) {
        #pragma unroll
        for (int ntp = 0; ntp < 4; ntp++) {
            int row = ntp * 16 + ((lane & 16) ? 8 : 0) + (lane & 7);
            int col = kk * 16 + ((lane & 8) ? 8 : 0);
            unsigned r0, r1, r2, r3;
            ldsm4(su32(Ks) + (unsigned)((row * KSTR + col) * 2), r0, r1, r2, r3);
            unsigned b0[2] = {r0, r1}, b1[2] = {r2, r3};
            mma16816(c[ntp * 2],     aq[kk], b0);
            mma16816(c[ntp * 2 + 1], aq[kk], b1);
        }
    }

    // ---- scale + bias + mask ----
    int row0 = wq * 16 + g, row1 = row0 + 8;
    int rn0 = row0 >> 3, cn0 = row0 & 7, rn1 = row1 >> 3, cn1 = row1 & 7;
    int cat0 = Cat[row0], cat1 = Cat[row1];
    #pragma unroll
    for (int nt = 0; nt < 8; nt++) {
        #pragma unroll
        for (int j = 0; j < 2; j++) {
            int col = nt * 8 + tg * 2 + j;
            int rm = col >> 3, cm = col & 7, cc = Cat[col];
            float b0v = Br[(rn0 - rm + 7) * 15 + (cn0 - cm + 7)] + (cc != cat0 ? -100.f : 0.f);
            float b1v = Br[(rn1 - rm + 7) * 15 + (cn1 - cm + 7)] + (cc != cat1 ? -100.f : 0.f);
            c[nt][j]     = c[nt][j]     * SCALE_Q + b0v;
            c[nt][j + 2] = c[nt][j + 2] * SCALE_Q + b1v;
        }
    }

    // ---- softmax over each row (cols spread over tg quad) ----
    float mx0 = -1e30f, mx1 = -1e30f;
    #pragma unroll
    for (int nt = 0; nt < 8; nt++) {
        mx0 = fmaxf(mx0, fmaxf(c[nt][0], c[nt][1]));
        mx1 = fmaxf(mx1, fmaxf(c[nt][2], c[nt][3]));
    }
    #pragma unroll
    for (int o = 1; o < 4; o <<= 1) {
        mx0 = fmaxf(mx0, __shfl_xor_sync(~0u, mx0, o));
        mx1 = fmaxf(mx1, __shfl_xor_sync(~0u, mx1, o));
    }
    float sm0 = 0.f, sm1 = 0.f;
    #pragma unroll
    for (int nt = 0; nt < 8; nt++) {
        c[nt][0] = __expf(c[nt][0] - mx0); sm0 += c[nt][0];
        c[nt][1] = __expf(c[nt][1] - mx0); sm0 += c[nt][1];
        c[nt][2] = __expf(c[nt][2] - mx1); sm1 += c[nt][2];
        c[nt][3] = __expf(c[nt][3] - mx1); sm1 += c[nt][3];
    }
    #pragma unroll
    for (int o = 1; o < 4; o <<= 1) {
        sm0 += __shfl_xor_sync(~0u, sm0, o);
        sm1 += __shfl_xor_sync(~0u, sm1, o);
    }
    float inv0 = 1.f / sm0, inv1 = 1.f / sm1;

    // ---- O = P @ V : P fragments come straight from S accum layout ----
    float c2[4][4];
    #pragma unroll
    for (int nt = 0; nt < 4; nt++)
        #pragma unroll
        for (int i = 0; i < 4; i++) c2[nt][i] = 0.f;

    #pragma unroll
    for (int kk = 0; kk < 4; kk++) {       // 16 keys per step
        unsigned ap[4];
        ap[0] = packh2(c[kk * 2][0],     c[kk * 2][1]);       // row g,   k 2tg
        ap[1] = packh2(c[kk * 2][2],     c[kk * 2][3]);       // row g+8
        ap[2] = packh2(c[kk * 2 + 1][0], c[kk * 2 + 1][1]);   // row g,   k 8+2tg
        ap[3] = packh2(c[kk * 2 + 1][2], c[kk * 2 + 1][3]);   // row g+8
        #pragma unroll
        for (int np = 0; np < 2; np++) {   // d cols 0-15, 16-31
            int row = kk * 16 + (lane & 15);
            int col = np * 16 + ((lane & 16) ? 8 : 0);
            unsigned r0, r1, r2, r3;
            ldsm4t(su32(Vs) + (unsigned)((row * KSTR + col) * 2), r0, r1, r2, r3);
            unsigned b0[2] = {r0, r1}, b1[2] = {r2, r3};
            mma16816(c2[np * 2],     ap, b0);
            mma16816(c2[np * 2 + 1], ap, b1);
        }
    }

    // ---- write O (token-major fp16) ----
    size_t obase = ((size_t)w * 64) * 192 + head * 32;
    #pragma unroll
    for (int nt = 0; nt < 4; nt++) {
        int col = nt * 8 + tg * 2;
        *(__half2*)(g_a + obase + (size_t)row0 * 192 + col) =
            __floats2half2_rn(c2[nt][0] * inv0, c2[nt][1] * inv0);
        *(__half2*)(g_a + obase + (size_t)row1 * 192 + col) =
            __floats2half2_rn(c2[nt][2] * inv1, c2[nt][3] * inv1);
    }
}

// ---------------- launch ------------------------------------------------------
extern "C" void kernel_launch(void* const* d_in, const int* in_sizes, int n_in,
                              void* d_out, int out_size)
{
    const float* x    = (const float*)d_in[0];
    const float* t    = (const float*)d_in[1];
    const float* n1w  = (const float*)d_in[2];
    const float* n1b  = (const float*)d_in[3];
    const float* qkvw = (const float*)d_in[4];
    const float* qkvb = (const float*)d_in[5];
    const float* rpb  = (const float*)d_in[6];
    const float* pw   = (const float*)d_in[7];
    const float* pb   = (const float*)d_in[8];
    const float* n2w  = (const float*)d_in[9];
    const float* n2b  = (const float*)d_in[10];
    const float* f1w  = (const float*)d_in[11];
    const float* f1b  = (const float*)d_in[12];
    const float* f2w  = (const float*)d_in[13];
    const float* f2b  = (const float*)d_in[14];
    const float* amw  = (const float*)d_in[15];
    const float* amb  = (const float*)d_in[16];
    const float* alw  = (const float*)d_in[17];
    const float* alb  = (const float*)d_in[18];
    float* out = (float*)d_out;

    float *x2;
    __half *a16, *b16, *w16;
    cudaGetSymbolAddress((void**)&x2,  g_x2v);
    cudaGetSymbolAddress((void**)&a16, g_a);
    cudaGetSymbolAddress((void**)&b16, g_b);
    cudaGetSymbolAddress((void**)&w16, g_w);

    const int ADAFM_SMEM = (64 * 196 + 4096 + 384) * 4;
    const int GEMM_SMEM  = 2 * (128 * KSTR + 64 * KSTR) * 2;  // 30720 B
    static int attr_done = 0;
    if (!attr_done) {
        cudaFuncSetAttribute(k_adafm<0>, cudaFuncAttributeMaxDynamicSharedMemorySize, ADAFM_SMEM);
        cudaFuncSetAttribute(k_adafm<1>, cudaFuncAttributeMaxDynamicSharedMemorySize, ADAFM_SMEM);
        cudaFuncSetAttribute(k_hgemm<0>, cudaFuncAttributeMaxDynamicSharedMemorySize, GEMM_SMEM);
        cudaFuncSetAttribute(k_hgemm<1>, cudaFuncAttributeMaxDynamicSharedMemorySize, GEMM_SMEM);
        cudaFuncSetAttribute(k_hgemm<2>, cudaFuncAttributeMaxDynamicSharedMemorySize, GEMM_SMEM);
        cudaFuncSetAttribute(k_hgemm<3>, cudaFuncAttributeMaxDynamicSharedMemorySize, GEMM_SMEM);
        attr_done = 1;
    }

    k_prep<<<32, 256>>>(t, amw, amb, alw, alb);
    k_wconv<<<432, 256>>>(qkvw, w16, 110592);
    k_wconv<<<144, 256>>>(pw,   w16 + 110592, 36864);
    k_wconv<<<576, 256>>>(f1w,  w16 + 147456, 147456);
    k_wconv<<<576, 256>>>(f2w,  w16 + 294912, 147456);

    k_gnstats<<<dim3(32, 32), 256>>>(x, 0);
    k_adafm<0><<<dim3(64, 32), 256, ADAFM_SMEM>>>(x, n1w, n1b);
    // qkv: (131072 x 192) @ (576 x 192)^T -> fp16 into g_b
    k_hgemm<0><<<dim3(9, 1024), 256, GEMM_SMEM>>>(a16, w16, qkvb,
                                                  nullptr, b16, 192, 576, nullptr);
    // tensor-core attention -> g_a (fp16)
    k_attn_tc<<<dim3(2048, 6), 128>>>(b16, rpb);
    // proj + window reverse + roll + residual -> x2
    k_hgemm<2><<<dim3(3, 1024), 256, GEMM_SMEM>>>(a16, w16 + 110592, pb,
                                                  x2, nullptr, 192, 192, x);
    k_gnstats<<<dim3(32, 32), 256>>>(x2, 1);
    k_adafm<1><<<dim3(64, 32), 256, ADAFM_SMEM>>>(x2, n2w, n2b);
    // fc1 + GELU -> fp16
    k_hgemm<1><<<dim3(12, 1024), 256, GEMM_SMEM>>>(a16, w16 + 147456, f1b,
                                                   nullptr, b16, 192, 768, nullptr);
    // fc2 + residual scatter -> out
    k_hgemm<3><<<dim3(3, 1024), 256, GEMM_SMEM>>>(b16, w16 + 294912, f2b,
                                                  out, nullptr, 768, 192, x2);
}

// round 10
// speedup vs baseline: 2.3356x; 1.2491x over previous
#include <cuda_runtime.h>
#include <cuda_fp16.h>
#include <math.h>

#define SCALE_Q 0.17677669529663687f
#define KSTR 40   // GEMM smem row stride in halves (80B, conflict-free for LDSM)

// ---------------- scratch (device globals) ----------------------------------
__device__ float g_x2v[25165824];            // x after attn residual (B,C,H,W)
__device__ __half g_a[25165824];             // activations fp16 (131072 x 192)
__device__ __half g_b[100663296];            // qkv (131072x576) then fc1 out (131072x768)
__device__ __half g_w[442368];               // weights fp16 (qkv|proj|fc1|fc2)
__device__ float g_M[2][32][4096];           // per-batch 64x64 patch conv matrices
__device__ float2 g_gn[2][32][32];           // (mean, rstd)

__constant__ float c_cos8[8] = {
    1.f, 0.70710678118654752f, 0.f, -0.70710678118654752f,
   -1.f, -0.70710678118654752f, 0.f, 0.70710678118654752f};

// ---------------- helpers ----------------------------------------------------
__device__ __forceinline__ unsigned su32(const void* p) {
    return (unsigned)__cvta_generic_to_shared(p);
}
__device__ __forceinline__ void cpasync16(unsigned dst, const void* src) {
    asm volatile("cp.async.ca.shared.global [%0], [%1], 16;" :: "r"(dst), "l"(src) : "memory");
}
__device__ __forceinline__ void cpcommit() {
    asm volatile("cp.async.commit_group;" ::: "memory");
}
template <int W> __device__ __forceinline__ void cpwait() {
    asm volatile("cp.async.wait_group %0;" :: "n"(W) : "memory");
}
__device__ __forceinline__ void ldsm4(unsigned a, unsigned& r0, unsigned& r1,
                                      unsigned& r2, unsigned& r3) {
    asm volatile("ldmatrix.sync.aligned.m8n8.x4.shared.b16 {%0,%1,%2,%3}, [%4];"
                 : "=r"(r0), "=r"(r1), "=r"(r2), "=r"(r3) : "r"(a));
}
__device__ __forceinline__ void ldsm4t(unsigned a, unsigned& r0, unsigned& r1,
                                       unsigned& r2, unsigned& r3) {
    asm volatile("ldmatrix.sync.aligned.m8n8.x4.trans.shared.b16 {%0,%1,%2,%3}, [%4];"
                 : "=r"(r0), "=r"(r1), "=r"(r2), "=r"(r3) : "r"(a));
}
__device__ __forceinline__ void mma16816(float* c, const unsigned* a, const unsigned* b) {
    asm volatile(
        "mma.sync.aligned.m16n8k16.row.col.f32.f16.f16.f32 "
        "{%0,%1,%2,%3}, {%4,%5,%6,%7}, {%8,%9}, {%0,%1,%2,%3};"
        : "+f"(c[0]), "+f"(c[1]), "+f"(c[2]), "+f"(c[3])
        : "r"(a[0]), "r"(a[1]), "r"(a[2]), "r"(a[3]), "r"(b[0]), "r"(b[1]));
}
__device__ __forceinline__ unsigned packh2(float x, float y) {
    __half2 h = __floats2half2_rn(x, y);
    return *(unsigned*)&h;
}

// ---------------- K1: adaFM spectra -> per-batch 64x64 conv matrices --------
__global__ void __launch_bounds__(256) k_prep(
    const float* __restrict__ t,
    const float* __restrict__ wmsa, const float* __restrict__ bmsa,
    const float* __restrict__ wmlp, const float* __restrict__ bmlp)
{
    int b = blockIdx.x, tid = threadIdx.x;
    __shared__ float st[640];
    __shared__ float s[2][40];
    __shared__ float seff[2][64];
    __shared__ float ker[2][64];

    for (int i = tid; i < 640; i += 256) {
        float v = t[b * 640 + i];
        st[i] = v / (1.f + __expf(-v));
    }
    __syncthreads();
    if (tid < 80) {
        int br = tid / 40, f = tid % 40;
        const float* w  = br ? wmlp : wmsa;
        const float* bb = br ? bmlp : bmsa;
        float acc = bb[f];
        for (int e = 0; e < 640; e++) acc = fmaf(st[e], w[f * 640 + e], acc);
        s[br][f] = acc;
    }
    __syncthreads();
    if (tid < 128) {
        int br = tid >> 6, i = tid & 63, k1 = i >> 3, k2 = i & 7;
        float v;
        if (k2 == 0 || k2 == 4)
            v = 0.5f * (s[br][k1 * 5 + k2] + s[br][((8 - k1) & 7) * 5 + k2]);
        else if (k2 < 4) v = s[br][k1 * 5 + k2];
        else             v = s[br][((8 - k1) & 7) * 5 + (8 - k2)];
        seff[br][i] = v;
    }
    __syncthreads();
    if (tid < 128) {
        int br = tid >> 6, i = tid & 63, d1 = i >> 3, d2 = i & 7;
        float acc = 0.f;
        #pragma unroll
        for (int k = 0; k < 64; k++)
            acc = fmaf(seff[br][k], c_cos8[((k >> 3) * d1 + (k & 7) * d2) & 7], acc);
        ker[br][i] = acc * (1.f / 64.f);
    }
    __syncthreads();
    for (int idx = tid; idx < 8192; idx += 256) {
        int br = idx >> 12, j = idx & 4095;
        int in = j >> 6, out = j & 63;
        g_M[br][b][j] = ker[br][(((out >> 3) - (in >> 3)) & 7) * 8 +
                               (((out & 7) - (in & 7)) & 7)];
    }
}

// ---------------- K1b: weight fp32 -> fp16 -----------------------------------
__global__ void k_wconv(const float* __restrict__ w, __half* __restrict__ h, int n)
{
    int i = blockIdx.x * 256 + threadIdx.x;
    if (i < n) h[i] = __float2half_rn(w[i]);
}

// ---------------- K2: GroupNorm stats ---------------------------------------
__global__ void __launch_bounds__(256) k_gnstats(const float* __restrict__ x, int gi)
{
    int g = blockIdx.x, b = blockIdx.y;
    const float* p = x + ((size_t)b * 192 + g * 6) * 4096;
    float s = 0.f, s2 = 0.f;
    for (int i = threadIdx.x; i < 24576; i += 256) {
        float v = p[i]; s += v; s2 = fmaf(v, v, s2);
    }
    #pragma unroll
    for (int o = 16; o; o >>= 1) {
        s += __shfl_xor_sync(~0u, s, o); s2 += __shfl_xor_sync(~0u, s2, o);
    }
    __shared__ float sh[2][8];
    int wid = threadIdx.x >> 5;
    if (!(threadIdx.x & 31)) { sh[0][wid] = s; sh[1][wid] = s2; }
    __syncthreads();
    if (threadIdx.x < 32) {
        s  = (threadIdx.x < 8) ? sh[0][threadIdx.x] : 0.f;
        s2 = (threadIdx.x < 8) ? sh[1][threadIdx.x] : 0.f;
        #pragma unroll
        for (int o = 4; o; o >>= 1) {
            s += __shfl_xor_sync(~0u, s, o); s2 += __shfl_xor_sync(~0u, s2, o);
        }
        if (!threadIdx.x) {
            float m = s * (1.f / 24576.f);
            float var = s2 * (1.f / 24576.f) - m * m;
            g_gn[gi][b][g] = make_float2(m, rsqrtf(var + 1e-5f));
        }
    }
}

// ---------------- K3: tensor-core GN+adafm: Y = M(64x64) @ X(64x192) --------
// block = (patch, batch), 256 threads (8 warps: 4 row-tiles x 2 col-halves)
// MODE 0: roll(-4,-4)+window-partition scatter ; MODE 1: token-major
#define XSTR 200   // X smem stride (halves); 400B -> trans-LDSM conflict-free
#define MSTR 72    // M smem stride (halves); 144B -> LDSM conflict-free
template <int MODE>
__global__ void __launch_bounds__(256) k_adafm_tc(
    const float* __restrict__ src,
    const float* __restrict__ gw, const float* __restrict__ gbv)
{
    __shared__ __half Xs[64 * XSTR];
    __shared__ __half Ms[64 * MSTR];
    __shared__ float ga[192], gb[192];

    int patch = blockIdx.x, b = blockIdx.y;
    int py = patch >> 3, px = patch & 7;
    int tid = threadIdx.x, lane = tid & 31, wid = tid >> 5;

    if (tid < 192) {
        float2 st = g_gn[MODE][b][tid / 6];
        float a = st.y * gw[tid];
        ga[tid] = a; gb[tid] = gbv[tid] - st.x * a;
    }
    // M transpose load: g_M[j], j = in*64 + out  ->  Ms[out][in]
    for (int i = tid; i < 4096; i += 256)
        Ms[(i & 63) * MSTR + (i >> 6)] = __float2half_rn(g_M[MODE][b][i]);
    __syncthreads();

    // X load + GN affine -> fp16 smem  (row = pixel u, col = channel)
    {
        int u = tid >> 5, cl = tid & 31;
        const float* sb = src + ((size_t)b * 192) * 4096 + (py * 8 + u) * 64 + px * 8;
        #pragma unroll
        for (int cb = 0; cb < 6; cb++) {
            int c = cb * 32 + cl;
            const float* pr = sb + (size_t)c * 4096;
            float4 v0 = *(const float4*)pr;
            float4 v1 = *(const float4*)(pr + 4);
            float a = ga[c], o = gb[c];
            float vv[8] = {v0.x, v0.y, v0.z, v0.w, v1.x, v1.y, v1.z, v1.w};
            #pragma unroll
            for (int j = 0; j < 8; j++)
                Xs[(u * 8 + j) * XSTR + c] = __float2half_rn(fmaf(vv[j], a, o));
        }
    }
    __syncthreads();

    // warp tile: rows wr..wr+15, cols wc..wc+95
    int wr = (wid & 3) * 16, wc = (wid >> 2) * 96;
    float c[12][4];
    #pragma unroll
    for (int nt = 0; nt < 12; nt++)
        #pragma unroll
        for (int i = 0; i < 4; i++) c[nt][i] = 0.f;

    unsigned am[4][4];
    #pragma unroll
    for (int kk = 0; kk < 4; kk++) {
        int row = wr + (lane & 15);
        int col = kk * 16 + ((lane & 16) ? 8 : 0);
        ldsm4(su32(Ms) + (unsigned)((row * MSTR + col) * 2),
              am[kk][0], am[kk][1], am[kk][2], am[kk][3]);
    }
    #pragma unroll
    for (int kk = 0; kk < 4; kk++) {
        #pragma unroll
        for (int np = 0; np < 6; np++) {
            int row = kk * 16 + (lane & 15);
            int col = wc + np * 16 + ((lane & 16) ? 8 : 0);
            unsigned r0, r1, r2, r3;
            ldsm4t(su32(Xs) + (unsigned)((row * XSTR + col) * 2), r0, r1, r2, r3);
            unsigned b0[2] = {r0, r1}, b1[2] = {r2, r3};
            mma16816(c[np * 2],     am[kk], b0);
            mma16816(c[np * 2 + 1], am[kk], b1);
        }
    }

    // epilogue scatter (rows p0 = wr+g, p1 = p0+8; cols wc + nt*8 + tg*2)
    int g = lane >> 2, tg = lane & 3;
    #pragma unroll
    for (int h = 0; h < 2; h++) {
        int p = wr + g + h * 8;
        int hh = py * 8 + (p >> 3), ww = px * 8 + (p & 7);
        size_t off;
        if (MODE == 0) {
            int hh2 = (hh + 60) & 63, ww2 = (ww + 60) & 63;
            int win = ((hh2 >> 3) << 3) | (ww2 >> 3);
            int nn  = ((hh2 & 7) << 3) | (ww2 & 7);
            off = ((size_t)(b * 64 + win) * 64 + nn) * 192;
        } else {
            off = ((size_t)b * 4096 + hh * 64 + ww) * 192;
        }
        #pragma unroll
        for (int nt = 0; nt < 12; nt++) {
            int col = wc + nt * 8 + tg * 2;
            *(__half2*)(g_a + off + col) =
                __floats2half2_rn(c[nt][h * 2 + 0], c[nt][h * 2 + 1]);
        }
    }
}

// ---------------- K4: pipelined fp16 tensor GEMM, block 128x64, k-tile 32 ---
// EPI 0: +bias -> fp16 (qkv) | 1: +bias GELU -> fp16 | 2: +bias win-rev+roll+res
// EPI 3: +bias chan-major + res
template <int EPI>
__global__ void __launch_bounds__(256, 2) k_hgemm(
    const __half* __restrict__ A, const __half* __restrict__ W,
    const float* __restrict__ bias, float* __restrict__ Cf,
    __half* __restrict__ Ch,
    int K, int N, const float* __restrict__ res)
{
    extern __shared__ __half smem[];
    const int ASZ = 128 * KSTR, BSZ = 64 * KSTR;
    const int STG = ASZ + BSZ;

    int m0 = blockIdx.y * 128, n0 = blockIdx.x * 64;
    int tid = threadIdx.x, lane = tid & 31, wid = tid >> 5;
    int wm = (wid & 3) * 32, wn = (wid >> 2) * 32;

    const __half* Ab = A + (size_t)m0 * K;
    const __half* Bb = W + (size_t)n0 * K;
    int KT = K >> 5;

    float c[2][4][4];
    #pragma unroll
    for (int mt = 0; mt < 2; mt++)
        #pragma unroll
        for (int nt = 0; nt < 4; nt++)
            #pragma unroll
            for (int i = 0; i < 4; i++) c[mt][nt][i] = 0.f;

    auto fill = [&](int kt, int st) {
        __half* base = smem + st * STG;
        int k0 = kt * 32;
        #pragma unroll
        for (int r = 0; r < 2; r++) {
            int e = tid * 2 + r, row = e >> 2, ch = e & 3;
            unsigned d = su32(base + row * KSTR + ch * 8);
            cpasync16(d, Ab + (size_t)row * K + k0 + ch * 8);
        }
        {
            int row = tid >> 2, ch = tid & 3;
            unsigned d = su32(base + ASZ + row * KSTR + ch * 8);
            cpasync16(d, Bb + (size_t)row * K + k0 + ch * 8);
        }
        cpcommit();
    };

    fill(0, 0);
    for (int kt = 0; kt < KT; kt++) {
        if (kt + 1 < KT) { fill(kt + 1, (kt + 1) & 1); cpwait<1>(); }
        else             { cpwait<0>(); }
        __syncthreads();

        const __half* base = smem + (kt & 1) * STG;
        unsigned sA = su32(base);
        unsigned sB = su32(base + ASZ);

        unsigned a[2][2][4];
        #pragma unroll
        for (int mt = 0; mt < 2; mt++)
            #pragma unroll
            for (int kk = 0; kk < 2; kk++) {
                int row = wm + mt * 16 + (lane & 15);
                int col = kk * 16 + ((lane & 16) ? 8 : 0);
                unsigned off = (unsigned)((row * KSTR + col) * 2);
                ldsm4(sA + off, a[mt][kk][0], a[mt][kk][1], a[mt][kk][2], a[mt][kk][3]);
            }
        #pragma unroll
        for (int kk = 0; kk < 2; kk++) {
            unsigned bf[4][2];
            #pragma unroll
            for (int ntp = 0; ntp < 2; ntp++) {
                int row = wn + ntp * 16 + ((lane & 16) ? 8 : 0) + (lane & 7);
                int col = kk * 16 + ((lane & 8) ? 8 : 0);
                unsigned off = (unsigned)((row * KSTR + col) * 2);
                unsigned r0, r1, r2, r3;
                ldsm4(sB + off, r0, r1, r2, r3);
                bf[ntp * 2][0] = r0; bf[ntp * 2][1] = r1;
                bf[ntp * 2 + 1][0] = r2; bf[ntp * 2 + 1][1] = r3;
            }
            #pragma unroll
            for (int mt = 0; mt < 2; mt++)
                #pragma unroll
                for (int nt = 0; nt < 4; nt++)
                    mma16816(c[mt][nt], a[mt][kk], bf[nt]);
        }
        __syncthreads();
    }

    int g = lane >> 2, tg = lane & 3;
    #pragma unroll
    for (int nt = 0; nt < 4; nt++) {
        int cb = n0 + wn + nt * 8 + tg * 2;
        float2 bv = *(const float2*)(bias + cb);
        #pragma unroll
        for (int mt = 0; mt < 2; mt++)
            #pragma unroll
            for (int h = 0; h < 2; h++) {
                int m = m0 + wm + mt * 16 + g + h * 8;
                float v0 = c[mt][nt][h * 2 + 0] + bv.x;
                float v1 = c[mt][nt][h * 2 + 1] + bv.y;
                if (EPI == 0) {
                    *(__half2*)(Ch + (size_t)m * N + cb) = __floats2half2_rn(v0, v1);
                } else if (EPI == 1) {
                    float g0 = 0.5f * v0 * (1.f + erff(v0 * 0.70710678118654752f));
                    float g1 = 0.5f * v1 * (1.f + erff(v1 * 0.70710678118654752f));
                    *(__half2*)(Ch + (size_t)m * N + cb) = __floats2half2_rn(g0, g1);
                } else if (EPI == 2) {
                    int b = m >> 12, win = (m >> 6) & 63, nn = m & 63;
                    int hh = ((((win >> 3) << 3) + (nn >> 3)) + 4) & 63;
                    int ww = ((((win & 7) << 3) + (nn & 7)) + 4) & 63;
                    size_t base2 = ((size_t)b * 192) * 4096 + hh * 64 + ww;
                    size_t i0 = base2 + (size_t)cb * 4096;
                    size_t i1 = base2 + (size_t)(cb + 1) * 4096;
                    Cf[i0] = res[i0] + v0;
                    Cf[i1] = res[i1] + v1;
                } else {
                    int b = m >> 12, pix = m & 4095;
                    size_t i0 = ((size_t)(b * 192 + cb)) * 4096 + pix;
                    size_t i1 = i0 + 4096;
                    Cf[i0] = res[i0] + v0;
                    Cf[i1] = res[i1] + v1;
                }
            }
    }
}

// ---------------- K5: tensor-core window attention ---------------------------
__global__ void __launch_bounds__(128) k_attn_tc(
    const __half* __restrict__ qkv, const float* __restrict__ rpb)
{
    __shared__ __half Qs[64 * KSTR], Ks[64 * KSTR], Vs[64 * KSTR];
    __shared__ float Br[225];
    __shared__ int Cat[64];

    int w = blockIdx.x, head = blockIdx.y;
    int tid = threadIdx.x, lane = tid & 31, wq = tid >> 5;

    const __half* base = qkv + (size_t)w * 64 * 576 + head * 32;
    #pragma unroll
    for (int r = 0; r < 2; r++) {
        int idx = tid + r * 128;
        int row = idx >> 2, ch = idx & 3;
        const __half* src = base + (size_t)row * 576 + ch * 8;
        unsigned doff = (unsigned)((row * KSTR + ch * 8) * 2);
        cpasync16(su32(Qs) + doff, src);
        cpasync16(su32(Ks) + doff, src + 192);
        cpasync16(su32(Vs) + doff, src + 384);
    }
    cpcommit();

    for (int i = tid; i < 225; i += 128) Br[i] = rpb[i * 6 + head];
    if (tid < 64) {
        int win = w & 63;
        int hh2 = ((win >> 3) << 3) + (tid >> 3);
        int ww2 = ((win & 7) << 3) + (tid & 7);
        int ch = hh2 < 56 ? 0 : (hh2 < 60 ? 1 : 2);
        int cw = ww2 < 56 ? 0 : (ww2 < 60 ? 1 : 2);
        Cat[tid] = ch * 3 + cw;
    }
    cpwait<0>();
    __syncthreads();

    int g = lane >> 2, tg = lane & 3;

    float c[8][4];
    #pragma unroll
    for (int nt = 0; nt < 8; nt++)
        #pragma unroll
        for (int i = 0; i < 4; i++) c[nt][i] = 0.f;

    unsigned aq[2][4];
    #pragma unroll
    for (int kk = 0; kk < 2; kk++) {
        int row = wq * 16 + (lane & 15);
        int col = kk * 16 + ((lane & 16) ? 8 : 0);
        ldsm4(su32(Qs) + (unsigned)((row * KSTR + col) * 2),
              aq[kk][0], aq[kk][1], aq[kk][2], aq[kk][3]);
    }
    #pragma unroll
    for (int kk = 0; kk < 2; kk++) {
        #pragma unroll
        for (int ntp = 0; ntp < 4; ntp++) {
            int row = ntp * 16 + ((lane & 16) ? 8 : 0) + (lane & 7);
            int col = kk * 16 + ((lane & 8) ? 8 : 0);
            unsigned r0, r1, r2, r3;
            ldsm4(su32(Ks) + (unsigned)((row * KSTR + col) * 2), r0, r1, r2, r3);
            unsigned b0[2] = {r0, r1}, b1[2] = {r2, r3};
            mma16816(c[ntp * 2],     aq[kk], b0);
            mma16816(c[ntp * 2 + 1], aq[kk], b1);
        }
    }

    int row0 = wq * 16 + g, row1 = row0 + 8;
    int rn0 = row0 >> 3, cn0 = row0 & 7, rn1 = row1 >> 3, cn1 = row1 & 7;
    int cat0 = Cat[row0], cat1 = Cat[row1];
    #pragma unroll
    for (int nt = 0; nt < 8; nt++) {
        #pragma unroll
        for (int j = 0; j < 2; j++) {
            int col = nt * 8 + tg * 2 + j;
            int rm = col >> 3, cm = col & 7, cc = Cat[col];
            float b0v = Br[(rn0 - rm + 7) * 15 + (cn0 - cm + 7)] + (cc != cat0 ? -100.f : 0.f);
            float b1v = Br[(rn1 - rm + 7) * 15 + (cn1 - cm + 7)] + (cc != cat1 ? -100.f : 0.f);
            c[nt][j]     = c[nt][j]     * SCALE_Q + b0v;
            c[nt][j + 2] = c[nt][j + 2] * SCALE_Q + b1v;
        }
    }

    float mx0 = -1e30f, mx1 = -1e30f;
    #pragma unroll
    for (int nt = 0; nt < 8; nt++) {
        mx0 = fmaxf(mx0, fmaxf(c[nt][0], c[nt][1]));
        mx1 = fmaxf(mx1, fmaxf(c[nt][2], c[nt][3]));
    }
    #pragma unroll
    for (int o = 1; o < 4; o <<= 1) {
        mx0 = fmaxf(mx0, __shfl_xor_sync(~0u, mx0, o));
        mx1 = fmaxf(mx1, __shfl_xor_sync(~0u, mx1, o));
    }
    float sm0 = 0.f, sm1 = 0.f;
    #pragma unroll
    for (int nt = 0; nt < 8; nt++) {
        c[nt][0] = __expf(c[nt][0] - mx0); sm0 += c[nt][0];
        c[nt][1] = __expf(c[nt][1] - mx0); sm0 += c[nt][1];
        c[nt][2] = __expf(c[nt][2] - mx1); sm1 += c[nt][2];
        c[nt][3] = __expf(c[nt][3] - mx1); sm1 += c[nt][3];
    }
    #pragma unroll
    for (int o = 1; o < 4; o <<= 1) {
        sm0 += __shfl_xor_sync(~0u, sm0, o);
        sm1 += __shfl_xor_sync(~0u, sm1, o);
    }
    float inv0 = 1.f / sm0, inv1 = 1.f / sm1;

    float c2[4][4];
    #pragma unroll
    for (int nt = 0; nt < 4; nt++)
        #pragma unroll
        for (int i = 0; i < 4; i++) c2[nt][i] = 0.f;

    #pragma unroll
    for (int kk = 0; kk < 4; kk++) {
        unsigned ap[4];
        ap[0] = packh2(c[kk * 2][0],     c[kk * 2][1]);
        ap[1] = packh2(c[kk * 2][2],     c[kk * 2][3]);
        ap[2] = packh2(c[kk * 2 + 1][0], c[kk * 2 + 1][1]);
        ap[3] = packh2(c[kk * 2 + 1][2], c[kk * 2 + 1][3]);
        #pragma unroll
        for (int np = 0; np < 2; np++) {
            int row = kk * 16 + (lane & 15);
            int col = np * 16 + ((lane & 16) ? 8 : 0);
            unsigned r0, r1, r2, r3;
            ldsm4t(su32(Vs) + (unsigned)((row * KSTR + col) * 2), r0, r1, r2, r3);
            unsigned b0[2] = {r0, r1}, b1[2] = {r2, r3};
            mma16816(c2[np * 2],     ap, b0);
            mma16816(c2[np * 2 + 1], ap, b1);
        }
    }

    size_t obase = ((size_t)w * 64) * 192 + head * 32;
    #pragma unroll
    for (int nt = 0; nt < 4; nt++) {
        int col = nt * 8 + tg * 2;
        *(__half2*)(g_a + obase + (size_t)row0 * 192 + col) =
            __floats2half2_rn(c2[nt][0] * inv0, c2[nt][1] * inv0);
        *(__half2*)(g_a + obase + (size_t)row1 * 192 + col) =
            __floats2half2_rn(c2[nt][2] * inv1, c2[nt][3] * inv1);
    }
}

// ---------------- launch ------------------------------------------------------
extern "C" void kernel_launch(void* const* d_in, const int* in_sizes, int n_in,
                              void* d_out, int out_size)
{
    const float* x    = (const float*)d_in[0];
    const float* t    = (const float*)d_in[1];
    const float* n1w  = (const float*)d_in[2];
    const float* n1b  = (const float*)d_in[3];
    const float* qkvw = (const float*)d_in[4];
    const float* qkvb = (const float*)d_in[5];
    const float* rpb  = (const float*)d_in[6];
    const float* pw   = (const float*)d_in[7];
    const float* pb   = (const float*)d_in[8];
    const float* n2w  = (const float*)d_in[9];
    const float* n2b  = (const float*)d_in[10];
    const float* f1w  = (const float*)d_in[11];
    const float* f1b  = (const float*)d_in[12];
    const float* f2w  = (const float*)d_in[13];
    const float* f2b  = (const float*)d_in[14];
    const float* amw  = (const float*)d_in[15];
    const float* amb  = (const float*)d_in[16];
    const float* alw  = (const float*)d_in[17];
    const float* alb  = (const float*)d_in[18];
    float* out = (float*)d_out;

    float *x2;
    __half *a16, *b16, *w16;
    cudaGetSymbolAddress((void**)&x2,  g_x2v);
    cudaGetSymbolAddress((void**)&a16, g_a);
    cudaGetSymbolAddress((void**)&b16, g_b);
    cudaGetSymbolAddress((void**)&w16, g_w);

    const int GEMM_SMEM = 2 * (128 * KSTR + 64 * KSTR) * 2;  // 30720 B
    static int attr_done = 0;
    if (!attr_done) {
        cudaFuncSetAttribute(k_hgemm<0>, cudaFuncAttributeMaxDynamicSharedMemorySize, GEMM_SMEM);
        cudaFuncSetAttribute(k_hgemm<1>, cudaFuncAttributeMaxDynamicSharedMemorySize, GEMM_SMEM);
        cudaFuncSetAttribute(k_hgemm<2>, cudaFuncAttributeMaxDynamicSharedMemorySize, GEMM_SMEM);
        cudaFuncSetAttribute(k_hgemm<3>, cudaFuncAttributeMaxDynamicSharedMemorySize, GEMM_SMEM);
        attr_done = 1;
    }

    k_prep<<<32, 256>>>(t, amw, amb, alw, alb);
    k_wconv<<<432, 256>>>(qkvw, w16, 110592);
    k_wconv<<<144, 256>>>(pw,   w16 + 110592, 36864);
    k_wconv<<<576, 256>>>(f1w,  w16 + 147456, 147456);
    k_wconv<<<576, 256>>>(f2w,  w16 + 294912, 147456);

    k_gnstats<<<dim3(32, 32), 256>>>(x, 0);
    k_adafm_tc<0><<<dim3(64, 32), 256>>>(x, n1w, n1b);
    // qkv: (131072 x 192) @ (576 x 192)^T -> fp16 into g_b
    k_hgemm<0><<<dim3(9, 1024), 256, GEMM_SMEM>>>(a16, w16, qkvb,
                                                  nullptr, b16, 192, 576, nullptr);
    // tensor-core attention -> g_a (fp16)
    k_attn_tc<<<dim3(2048, 6), 128>>>(b16, rpb);
    // proj + window reverse + roll + residual -> x2
    k_hgemm<2><<<dim3(3, 1024), 256, GEMM_SMEM>>>(a16, w16 + 110592, pb,
                                                  x2, nullptr, 192, 192, x);
    k_gnstats<<<dim3(32, 32), 256>>>(x2, 1);
    k_adafm_tc<1><<<dim3(64, 32), 256>>>(x2, n2w, n2b);
    // fc1 + GELU -> fp16
    k_hgemm<1><<<dim3(12, 1024), 256, GEMM_SMEM>>>(a16, w16 + 147456, f1b,
                                                   nullptr, b16, 192, 768, nullptr);
    // fc2 + residual scatter -> out
    k_hgemm<3><<<dim3(3, 1024), 256, GEMM_SMEM>>>(b16, w16 + 294912, f2b,
                                                  out, nullptr, 768, 192, x2);
}

// round 11
// speedup vs baseline: 2.5876x; 1.1079x over previous
#include <cuda_runtime.h>
#include <cuda_fp16.h>
#include <math.h>

#define SCALE_Q 0.17677669529663687f
#define KSTR 40   // GEMM smem row stride in halves (80B, conflict-free for LDSM)

// ---------------- scratch (device globals) ----------------------------------
__device__ float g_x2v[25165824];            // x after attn residual (B,C,H,W)
__device__ __half g_a[25165824];             // activations fp16 (131072 x 192)
__device__ __half g_b[100663296];            // qkv (131072x576) then fc1 out (131072x768)
__device__ __half g_w[442368];               // weights fp16 (qkv|proj|fc1|fc2)
__device__ float g_M[2][32][4096];           // per-batch 64x64 patch conv matrices
__device__ float2 g_gn[2][32][32];           // (mean, rstd)

__constant__ float c_cos8[8] = {
    1.f, 0.70710678118654752f, 0.f, -0.70710678118654752f,
   -1.f, -0.70710678118654752f, 0.f, 0.70710678118654752f};

// ---------------- helpers ----------------------------------------------------
__device__ __forceinline__ unsigned su32(const void* p) {
    return (unsigned)__cvta_generic_to_shared(p);
}
__device__ __forceinline__ void cpasync16(unsigned dst, const void* src) {
    asm volatile("cp.async.ca.shared.global [%0], [%1], 16;" :: "r"(dst), "l"(src) : "memory");
}
__device__ __forceinline__ void cpcommit() {
    asm volatile("cp.async.commit_group;" ::: "memory");
}
template <int W> __device__ __forceinline__ void cpwait() {
    asm volatile("cp.async.wait_group %0;" :: "n"(W) : "memory");
}
__device__ __forceinline__ void ldsm4(unsigned a, unsigned& r0, unsigned& r1,
                                      unsigned& r2, unsigned& r3) {
    asm volatile("ldmatrix.sync.aligned.m8n8.x4.shared.b16 {%0,%1,%2,%3}, [%4];"
                 : "=r"(r0), "=r"(r1), "=r"(r2), "=r"(r3) : "r"(a));
}
__device__ __forceinline__ void ldsm4t(unsigned a, unsigned& r0, unsigned& r1,
                                       unsigned& r2, unsigned& r3) {
    asm volatile("ldmatrix.sync.aligned.m8n8.x4.trans.shared.b16 {%0,%1,%2,%3}, [%4];"
                 : "=r"(r0), "=r"(r1), "=r"(r2), "=r"(r3) : "r"(a));
}
__device__ __forceinline__ void mma16816(float* c, const unsigned* a, const unsigned* b) {
    asm volatile(
        "mma.sync.aligned.m16n8k16.row.col.f32.f16.f16.f32 "
        "{%0,%1,%2,%3}, {%4,%5,%6,%7}, {%8,%9}, {%0,%1,%2,%3};"
        : "+f"(c[0]), "+f"(c[1]), "+f"(c[2]), "+f"(c[3])
        : "r"(a[0]), "r"(a[1]), "r"(a[2]), "r"(a[3]), "r"(b[0]), "r"(b[1]));
}
__device__ __forceinline__ unsigned packh2(float x, float y) {
    __half2 h = __floats2half2_rn(x, y);
    return *(unsigned*)&h;
}

// ---------------- K1: adaFM spectra -> per-batch 64x64 conv matrices --------
__global__ void __launch_bounds__(256) k_prep(
    const float* __restrict__ t,
    const float* __restrict__ wmsa, const float* __restrict__ bmsa,
    const float* __restrict__ wmlp, const float* __restrict__ bmlp)
{
    int b = blockIdx.x, tid = threadIdx.x;
    __shared__ float st[640];
    __shared__ float s[2][40];
    __shared__ float seff[2][64];
    __shared__ float ker[2][64];

    for (int i = tid; i < 640; i += 256) {
        float v = t[b * 640 + i];
        st[i] = v / (1.f + __expf(-v));
    }
    __syncthreads();
    if (tid < 80) {
        int br = tid / 40, f = tid % 40;
        const float* w  = br ? wmlp : wmsa;
        const float* bb = br ? bmlp : bmsa;
        float acc = bb[f];
        for (int e = 0; e < 640; e++) acc = fmaf(st[e], w[f * 640 + e], acc);
        s[br][f] = acc;
    }
    __syncthreads();
    if (tid < 128) {
        int br = tid >> 6, i = tid & 63, k1 = i >> 3, k2 = i & 7;
        float v;
        if (k2 == 0 || k2 == 4)
            v = 0.5f * (s[br][k1 * 5 + k2] + s[br][((8 - k1) & 7) * 5 + k2]);
        else if (k2 < 4) v = s[br][k1 * 5 + k2];
        else             v = s[br][((8 - k1) & 7) * 5 + (8 - k2)];
        seff[br][i] = v;
    }
    __syncthreads();
    if (tid < 128) {
        int br = tid >> 6, i = tid & 63, d1 = i >> 3, d2 = i & 7;
        float acc = 0.f;
        #pragma unroll
        for (int k = 0; k < 64; k++)
            acc = fmaf(seff[br][k], c_cos8[((k >> 3) * d1 + (k & 7) * d2) & 7], acc);
        ker[br][i] = acc * (1.f / 64.f);
    }
    __syncthreads();
    for (int idx = tid; idx < 8192; idx += 256) {
        int br = idx >> 12, j = idx & 4095;
        int in = j >> 6, out = j & 63;
        g_M[br][b][j] = ker[br][(((out >> 3) - (in >> 3)) & 7) * 8 +
                               (((out & 7) - (in & 7)) & 7)];
    }
}

// ---------------- K1b: all weights fp32 -> fp16 (one launch) -----------------
__global__ void k_wconv4(const float* __restrict__ w0, const float* __restrict__ w1,
                         const float* __restrict__ w2, const float* __restrict__ w3,
                         __half* __restrict__ h)
{
    int i = blockIdx.x * 256 + threadIdx.x;
    const float* s; int off;
    if (i < 110592)      { s = w0; off = 0; }
    else if (i < 147456) { s = w1; off = 110592; }
    else if (i < 294912) { s = w2; off = 147456; }
    else if (i < 442368) { s = w3; off = 294912; }
    else return;
    h[i] = __float2half_rn(s[i - off]);
}

// ---------------- K2: GroupNorm stats ---------------------------------------
__global__ void __launch_bounds__(256) k_gnstats(const float* __restrict__ x, int gi)
{
    int g = blockIdx.x, b = blockIdx.y;
    const float* p = x + ((size_t)b * 192 + g * 6) * 4096;
    float s = 0.f, s2 = 0.f;
    for (int i = threadIdx.x; i < 24576; i += 256) {
        float v = p[i]; s += v; s2 = fmaf(v, v, s2);
    }
    #pragma unroll
    for (int o = 16; o; o >>= 1) {
        s += __shfl_xor_sync(~0u, s, o); s2 += __shfl_xor_sync(~0u, s2, o);
    }
    __shared__ float sh[2][8];
    int wid = threadIdx.x >> 5;
    if (!(threadIdx.x & 31)) { sh[0][wid] = s; sh[1][wid] = s2; }
    __syncthreads();
    if (threadIdx.x < 32) {
        s  = (threadIdx.x < 8) ? sh[0][threadIdx.x] : 0.f;
        s2 = (threadIdx.x < 8) ? sh[1][threadIdx.x] : 0.f;
        #pragma unroll
        for (int o = 4; o; o >>= 1) {
            s += __shfl_xor_sync(~0u, s, o); s2 += __shfl_xor_sync(~0u, s2, o);
        }
        if (!threadIdx.x) {
            float m = s * (1.f / 24576.f);
            float var = s2 * (1.f / 24576.f) - m * m;
            g_gn[gi][b][g] = make_float2(m, rsqrtf(var + 1e-5f));
        }
    }
}

// ---------------- K3: tensor-core GN+adafm: Y = M(64x64) @ X(64x192) --------
#define XSTR 200   // X smem stride (halves); 400B -> trans-LDSM conflict-free
#define MSTR 72    // M smem stride (halves); 144B -> LDSM conflict-free
template <int MODE>
__global__ void __launch_bounds__(256) k_adafm_tc(
    const float* __restrict__ src,
    const float* __restrict__ gw, const float* __restrict__ gbv)
{
    __shared__ __half Xs[64 * XSTR];
    __shared__ __half Ms[64 * MSTR];
    __shared__ float ga[192], gb[192];

    int patch = blockIdx.x, b = blockIdx.y;
    int py = patch >> 3, px = patch & 7;
    int tid = threadIdx.x, lane = tid & 31, wid = tid >> 5;

    if (tid < 192) {
        float2 st = g_gn[MODE][b][tid / 6];
        float a = st.y * gw[tid];
        ga[tid] = a; gb[tid] = gbv[tid] - st.x * a;
    }
    for (int i = tid; i < 4096; i += 256)
        Ms[(i & 63) * MSTR + (i >> 6)] = __float2half_rn(g_M[MODE][b][i]);
    __syncthreads();

    // X load (sector-coalesced: thread -> (channel, row, half-row)) + GN affine
    {
        const float* sb = src + ((size_t)b * 192) * 4096 + (py * 8) * 64 + px * 8;
        #pragma unroll
        for (int it = 0; it < 12; it++) {
            int idx = it * 256 + tid;
            int c = idx >> 4, u = (idx >> 1) & 7, hf = idx & 1;
            float4 v = *(const float4*)(sb + (size_t)c * 4096 + u * 64 + hf * 4);
            float a = ga[c], o = gb[c];
            int prow = u * 8 + hf * 4;
            Xs[(prow + 0) * XSTR + c] = __float2half_rn(fmaf(v.x, a, o));
            Xs[(prow + 1) * XSTR + c] = __float2half_rn(fmaf(v.y, a, o));
            Xs[(prow + 2) * XSTR + c] = __float2half_rn(fmaf(v.z, a, o));
            Xs[(prow + 3) * XSTR + c] = __float2half_rn(fmaf(v.w, a, o));
        }
    }
    __syncthreads();

    int wr = (wid & 3) * 16, wc = (wid >> 2) * 96;
    float c[12][4];
    #pragma unroll
    for (int nt = 0; nt < 12; nt++)
        #pragma unroll
        for (int i = 0; i < 4; i++) c[nt][i] = 0.f;

    unsigned am[4][4];
    #pragma unroll
    for (int kk = 0; kk < 4; kk++) {
        int row = wr + (lane & 15);
        int col = kk * 16 + ((lane & 16) ? 8 : 0);
        ldsm4(su32(Ms) + (unsigned)((row * MSTR + col) * 2),
              am[kk][0], am[kk][1], am[kk][2], am[kk][3]);
    }
    #pragma unroll
    for (int kk = 0; kk < 4; kk++) {
        #pragma unroll
        for (int np = 0; np < 6; np++) {
            int row = kk * 16 + (lane & 15);
            int col = wc + np * 16 + ((lane & 16) ? 8 : 0);
            unsigned r0, r1, r2, r3;
            ldsm4t(su32(Xs) + (unsigned)((row * XSTR + col) * 2), r0, r1, r2, r3);
            unsigned b0[2] = {r0, r1}, b1[2] = {r2, r3};
            mma16816(c[np * 2],     am[kk], b0);
            mma16816(c[np * 2 + 1], am[kk], b1);
        }
    }

    int g = lane >> 2, tg = lane & 3;
    #pragma unroll
    for (int h = 0; h < 2; h++) {
        int p = wr + g + h * 8;
        int hh = py * 8 + (p >> 3), ww = px * 8 + (p & 7);
        size_t off;
        if (MODE == 0) {
            int hh2 = (hh + 60) & 63, ww2 = (ww + 60) & 63;
            int win = ((hh2 >> 3) << 3) | (ww2 >> 3);
            int nn  = ((hh2 & 7) << 3) | (ww2 & 7);
            off = ((size_t)(b * 64 + win) * 64 + nn) * 192;
        } else {
            off = ((size_t)b * 4096 + hh * 64 + ww) * 192;
        }
        #pragma unroll
        for (int nt = 0; nt < 12; nt++) {
            int col = wc + nt * 8 + tg * 2;
            *(__half2*)(g_a + off + col) =
                __floats2half2_rn(c[nt][h * 2 + 0], c[nt][h * 2 + 1]);
        }
    }
}

// ---------------- K4: pipelined fp16 tensor GEMM, block 128x96, k-tile 32 ---
// EPI 0: +bias -> fp16 (qkv) | 1: +bias GELU -> fp16 | 2: +bias win-rev+roll+res
// EPI 3: +bias chan-major + res
template <int EPI>
__global__ void __launch_bounds__(256, 2) k_hgemm(
    const __half* __restrict__ A, const __half* __restrict__ W,
    const float* __restrict__ bias, float* __restrict__ Cf,
    __half* __restrict__ Ch,
    int K, int N, const float* __restrict__ res)
{
    extern __shared__ __half smem[];
    const int ASZ = 128 * KSTR, BSZ = 96 * KSTR;
    const int STG = ASZ + BSZ;

    int m0 = blockIdx.y * 128, n0 = blockIdx.x * 96;
    int tid = threadIdx.x, lane = tid & 31, wid = tid >> 5;
    int wm = (wid & 3) * 32, wn = (wid >> 2) * 48;

    const __half* Ab = A + (size_t)m0 * K;
    const __half* Bb = W + (size_t)n0 * K;
    int KT = K >> 5;

    float c[2][6][4];
    #pragma unroll
    for (int mt = 0; mt < 2; mt++)
        #pragma unroll
        for (int nt = 0; nt < 6; nt++)
            #pragma unroll
            for (int i = 0; i < 4; i++) c[mt][nt][i] = 0.f;

    auto fill = [&](int kt, int st) {
        __half* base = smem + st * STG;
        int k0 = kt * 32;
        #pragma unroll
        for (int r = 0; r < 2; r++) {            // A: 512 chunks
            int e = tid * 2 + r, row = e >> 2, ch = e & 3;
            cpasync16(su32(base + row * KSTR + ch * 8),
                      Ab + (size_t)row * K + k0 + ch * 8);
        }
        {                                         // B: 384 chunks
            int row = tid >> 2, ch = tid & 3;
            cpasync16(su32(base + ASZ + row * KSTR + ch * 8),
                      Bb + (size_t)row * K + k0 + ch * 8);
        }
        if (tid < 128) {
            int e = 256 + tid, row = e >> 2, ch = e & 3;
            cpasync16(su32(base + ASZ + row * KSTR + ch * 8),
                      Bb + (size_t)row * K + k0 + ch * 8);
        }
        cpcommit();
    };

    fill(0, 0);
    for (int kt = 0; kt < KT; kt++) {
        if (kt + 1 < KT) { fill(kt + 1, (kt + 1) & 1); cpwait<1>(); }
        else             { cpwait<0>(); }
        __syncthreads();

        const __half* base = smem + (kt & 1) * STG;
        unsigned sA = su32(base);
        unsigned sB = su32(base + ASZ);

        #pragma unroll
        for (int kk = 0; kk < 2; kk++) {
            unsigned a[2][4];
            #pragma unroll
            for (int mt = 0; mt < 2; mt++) {
                int row = wm + mt * 16 + (lane & 15);
                int col = kk * 16 + ((lane & 16) ? 8 : 0);
                ldsm4(sA + (unsigned)((row * KSTR + col) * 2),
                      a[mt][0], a[mt][1], a[mt][2], a[mt][3]);
            }
            #pragma unroll
            for (int ntp = 0; ntp < 3; ntp++) {
                int row = wn + ntp * 16 + ((lane & 16) ? 8 : 0) + (lane & 7);
                int col = kk * 16 + ((lane & 8) ? 8 : 0);
                unsigned r0, r1, r2, r3;
                ldsm4(sB + (unsigned)((row * KSTR + col) * 2), r0, r1, r2, r3);
                unsigned b0[2] = {r0, r1}, b1[2] = {r2, r3};
                #pragma unroll
                for (int mt = 0; mt < 2; mt++) {
                    mma16816(c[mt][ntp * 2],     a[mt], b0);
                    mma16816(c[mt][ntp * 2 + 1], a[mt], b1);
                }
            }
        }
        __syncthreads();
    }

    int g = lane >> 2, tg = lane & 3;
    #pragma unroll
    for (int nt = 0; nt < 6; nt++) {
        int cb = n0 + wn + nt * 8 + tg * 2;
        float2 bv = *(const float2*)(bias + cb);
        #pragma unroll
        for (int mt = 0; mt < 2; mt++)
            #pragma unroll
            for (int h = 0; h < 2; h++) {
                int m = m0 + wm + mt * 16 + g + h * 8;
                float v0 = c[mt][nt][h * 2 + 0] + bv.x;
                float v1 = c[mt][nt][h * 2 + 1] + bv.y;
                if (EPI == 0) {
                    *(__half2*)(Ch + (size_t)m * N + cb) = __floats2half2_rn(v0, v1);
                } else if (EPI == 1) {
                    float g0 = 0.5f * v0 * (1.f + erff(v0 * 0.70710678118654752f));
                    float g1 = 0.5f * v1 * (1.f + erff(v1 * 0.70710678118654752f));
                    *(__half2*)(Ch + (size_t)m * N + cb) = __floats2half2_rn(g0, g1);
                } else if (EPI == 2) {
                    int b = m >> 12, win = (m >> 6) & 63, nn = m & 63;
                    int hh = ((((win >> 3) << 3) + (nn >> 3)) + 4) & 63;
                    int ww = ((((win & 7) << 3) + (nn & 7)) + 4) & 63;
                    size_t base2 = ((size_t)b * 192) * 4096 + hh * 64 + ww;
                    size_t i0 = base2 + (size_t)cb * 4096;
                    size_t i1 = base2 + (size_t)(cb + 1) * 4096;
                    Cf[i0] = res[i0] + v0;
                    Cf[i1] = res[i1] + v1;
                } else {
                    int b = m >> 12, pix = m & 4095;
                    size_t i0 = ((size_t)(b * 192 + cb)) * 4096 + pix;
                    size_t i1 = i0 + 4096;
                    Cf[i0] = res[i0] + v0;
                    Cf[i1] = res[i1] + v1;
                }
            }
    }
}

// ---------------- K5: tensor-core window attention ---------------------------
__global__ void __launch_bounds__(128) k_attn_tc(
    const __half* __restrict__ qkv, const float* __restrict__ rpb)
{
    __shared__ __half Qs[64 * KSTR], Ks[64 * KSTR], Vs[64 * KSTR];
    __shared__ float Br[225];
    __shared__ int Cat[64];

    int w = blockIdx.x, head = blockIdx.y;
    int tid = threadIdx.x, lane = tid & 31, wq = tid >> 5;

    const __half* base = qkv + (size_t)w * 64 * 576 + head * 32;
    #pragma unroll
    for (int r = 0; r < 2; r++) {
        int idx = tid + r * 128;
        int row = idx >> 2, ch = idx & 3;
        const __half* src = base + (size_t)row * 576 + ch * 8;
        unsigned doff = (unsigned)((row * KSTR + ch * 8) * 2);
        cpasync16(su32(Qs) + doff, src);
        cpasync16(su32(Ks) + doff, src + 192);
        cpasync16(su32(Vs) + doff, src + 384);
    }
    cpcommit();

    for (int i = tid; i < 225; i += 128) Br[i] = rpb[i * 6 + head];
    if (tid < 64) {
        int win = w & 63;
        int hh2 = ((win >> 3) << 3) + (tid >> 3);
        int ww2 = ((win & 7) << 3) + (tid & 7);
        int ch = hh2 < 56 ? 0 : (hh2 < 60 ? 1 : 2);
        int cw = ww2 < 56 ? 0 : (ww2 < 60 ? 1 : 2);
        Cat[tid] = ch * 3 + cw;
    }
    cpwait<0>();
    __syncthreads();

    int g = lane >> 2, tg = lane & 3;

    float c[8][4];
    #pragma unroll
    for (int nt = 0; nt < 8; nt++)
        #pragma unroll
        for (int i = 0; i < 4; i++) c[nt][i] = 0.f;

    unsigned aq[2][4];
    #pragma unroll
    for (int kk = 0; kk < 2; kk++) {
        int row = wq * 16 + (lane & 15);
        int col = kk * 16 + ((lane & 16) ? 8 : 0);
        ldsm4(su32(Qs) + (unsigned)((row * KSTR + col) * 2),
              aq[kk][0], aq[kk][1], aq[kk][2], aq[kk][3]);
    }
    #pragma unroll
    for (int kk = 0; kk < 2; kk++) {
        #pragma unroll
        for (int ntp = 0; ntp < 4; ntp++) {
            int row = ntp * 16 + ((lane & 16) ? 8 : 0) + (lane & 7);
            int col = kk * 16 + ((lane & 8) ? 8 : 0);
            unsigned r0, r1, r2, r3;
            ldsm4(su32(Ks) + (unsigned)((row * KSTR + col) * 2), r0, r1, r2, r3);
            unsigned b0[2] = {r0, r1}, b1[2] = {r2, r3};
            mma16816(c[ntp * 2],     aq[kk], b0);
            mma16816(c[ntp * 2 + 1], aq[kk], b1);
        }
    }

    int row0 = wq * 16 + g, row1 = row0 + 8;
    int rn0 = row0 >> 3, cn0 = row0 & 7, rn1 = row1 >> 3, cn1 = row1 & 7;
    int cat0 = Cat[row0], cat1 = Cat[row1];
    #pragma unroll
    for (int nt = 0; nt < 8; nt++) {
        #pragma unroll
        for (int j = 0; j < 2; j++) {
            int col = nt * 8 + tg * 2 + j;
            int rm = col >> 3, cm = col & 7, cc = Cat[col];
            float b0v = Br[(rn0 - rm + 7) * 15 + (cn0 - cm + 7)] + (cc != cat0 ? -100.f : 0.f);
            float b1v = Br[(rn1 - rm + 7) * 15 + (cn1 - cm + 7)] + (cc != cat1 ? -100.f : 0.f);
            c[nt][j]     = c[nt][j]     * SCALE_Q + b0v;
            c[nt][j + 2] = c[nt][j + 2] * SCALE_Q + b1v;
        }
    }

    float mx0 = -1e30f, mx1 = -1e30f;
    #pragma unroll
    for (int nt = 0; nt < 8; nt++) {
        mx0 = fmaxf(mx0, fmaxf(c[nt][0], c[nt][1]));
        mx1 = fmaxf(mx1, fmaxf(c[nt][2], c[nt][3]));
    }
    #pragma unroll
    for (int o = 1; o < 4; o <<= 1) {
        mx0 = fmaxf(mx0, __shfl_xor_sync(~0u, mx0, o));
        mx1 = fmaxf(mx1, __shfl_xor_sync(~0u, mx1, o));
    }
    float sm0 = 0.f, sm1 = 0.f;
    #pragma unroll
    for (int nt = 0; nt < 8; nt++) {
        c[nt][0] = __expf(c[nt][0] - mx0); sm0 += c[nt][0];
        c[nt][1] = __expf(c[nt][1] - mx0); sm0 += c[nt][1];
        c[nt][2] = __expf(c[nt][2] - mx1); sm1 += c[nt][2];
        c[nt][3] = __expf(c[nt][3] - mx1); sm1 += c[nt][3];
    }
    #pragma unroll
    for (int o = 1; o < 4; o <<= 1) {
        sm0 += __shfl_xor_sync(~0u, sm0, o);
        sm1 += __shfl_xor_sync(~0u, sm1, o);
    }
    float inv0 = 1.f / sm0, inv1 = 1.f / sm1;

    float c2[4][4];
    #pragma unroll
    for (int nt = 0; nt < 4; nt++)
        #pragma unroll
        for (int i = 0; i < 4; i++) c2[nt][i] = 0.f;

    #pragma unroll
    for (int kk = 0; kk < 4; kk++) {
        unsigned ap[4];
        ap[0] = packh2(c[kk * 2][0],     c[kk * 2][1]);
        ap[1] = packh2(c[kk * 2][2],     c[kk * 2][3]);
        ap[2] = packh2(c[kk * 2 + 1][0], c[kk * 2 + 1][1]);
        ap[3] = packh2(c[kk * 2 + 1][2], c[kk * 2 + 1][3]);
        #pragma unroll
        for (int np = 0; np < 2; np++) {
            int row = kk * 16 + (lane & 15);
            int col = np * 16 + ((lane & 16) ? 8 : 0);
            unsigned r0, r1, r2, r3;
            ldsm4t(su32(Vs) + (unsigned)((row * KSTR + col) * 2), r0, r1, r2, r3);
            unsigned b0[2] = {r0, r1}, b1[2] = {r2, r3};
            mma16816(c2[np * 2],     ap, b0);
            mma16816(c2[np * 2 + 1], ap, b1);
        }
    }

    size_t obase = ((size_t)w * 64) * 192 + head * 32;
    #pragma unroll
    for (int nt = 0; nt < 4; nt++) {
        int col = nt * 8 + tg * 2;
        *(__half2*)(g_a + obase + (size_t)row0 * 192 + col) =
            __floats2half2_rn(c2[nt][0] * inv0, c2[nt][1] * inv0);
        *(__half2*)(g_a + obase + (size_t)row1 * 192 + col) =
            __floats2half2_rn(c2[nt][2] * inv1, c2[nt][3] * inv1);
    }
}

// ---------------- launch ------------------------------------------------------
extern "C" void kernel_launch(void* const* d_in, const int* in_sizes, int n_in,
                              void* d_out, int out_size)
{
    const float* x    = (const float*)d_in[0];
    const float* t    = (const float*)d_in[1];
    const float* n1w  = (const float*)d_in[2];
    const float* n1b  = (const float*)d_in[3];
    const float* qkvw = (const float*)d_in[4];
    const float* qkvb = (const float*)d_in[5];
    const float* rpb  = (const float*)d_in[6];
    const float* pw   = (const float*)d_in[7];
    const float* pb   = (const float*)d_in[8];
    const float* n2w  = (const float*)d_in[9];
    const float* n2b  = (const float*)d_in[10];
    const float* f1w  = (const float*)d_in[11];
    const float* f1b  = (const float*)d_in[12];
    const float* f2w  = (const float*)d_in[13];
    const float* f2b  = (const float*)d_in[14];
    const float* amw  = (const float*)d_in[15];
    const float* amb  = (const float*)d_in[16];
    const float* alw  = (const float*)d_in[17];
    const float* alb  = (const float*)d_in[18];
    float* out = (float*)d_out;

    float *x2;
    __half *a16, *b16, *w16;
    cudaGetSymbolAddress((void**)&x2,  g_x2v);
    cudaGetSymbolAddress((void**)&a16, g_a);
    cudaGetSymbolAddress((void**)&b16, g_b);
    cudaGetSymbolAddress((void**)&w16, g_w);

    const int GEMM_SMEM = 2 * (128 * KSTR + 96 * KSTR) * 2;  // 35840 B
    static int attr_done = 0;
    if (!attr_done) {
        cudaFuncSetAttribute(k_hgemm<0>, cudaFuncAttributeMaxDynamicSharedMemorySize, GEMM_SMEM);
        cudaFuncSetAttribute(k_hgemm<1>, cudaFuncAttributeMaxDynamicSharedMemorySize, GEMM_SMEM);
        cudaFuncSetAttribute(k_hgemm<2>, cudaFuncAttributeMaxDynamicSharedMemorySize, GEMM_SMEM);
        cudaFuncSetAttribute(k_hgemm<3>, cudaFuncAttributeMaxDynamicSharedMemorySize, GEMM_SMEM);
        attr_done = 1;
    }

    k_prep<<<32, 256>>>(t, amw, amb, alw, alb);
    k_wconv4<<<1728, 256>>>(qkvw, pw, f1w, f2w, w16);

    k_gnstats<<<dim3(32, 32), 256>>>(x, 0);
    k_adafm_tc<0><<<dim3(64, 32), 256>>>(x, n1w, n1b);
    // qkv: (131072 x 192) @ (576 x 192)^T -> fp16 into g_b
    k_hgemm<0><<<dim3(6, 1024), 256, GEMM_SMEM>>>(a16, w16, qkvb,
                                                  nullptr, b16, 192, 576, nullptr);
    // tensor-core attention -> g_a (fp16)
    k_attn_tc<<<dim3(2048, 6), 128>>>(b16, rpb);
    // proj + window reverse + roll + residual -> x2
    k_hgemm<2><<<dim3(2, 1024), 256, GEMM_SMEM>>>(a16, w16 + 110592, pb,
                                                  x2, nullptr, 192, 192, x);
    k_gnstats<<<dim3(32, 32), 256>>>(x2, 1);
    k_adafm_tc<1><<<dim3(64, 32), 256>>>(x2, n2w, n2b);
    // fc1 + GELU -> fp16
    k_hgemm<1><<<dim3(8, 1024), 256, GEMM_SMEM>>>(a16, w16 + 147456, f1b,
                                                  nullptr, b16, 192, 768, nullptr);
    // fc2 + residual scatter -> out
    k_hgemm<3><<<dim3(2, 1024), 256, GEMM_SMEM>>>(b16, w16 + 294912, f2b,
                                                  out, nullptr, 768, 192, x2);
}

// round 13
// speedup vs baseline: 2.8068x; 1.0847x over previous
#include <cuda_runtime.h>
#include <cuda_fp16.h>
#include <math.h>

#define SCALE_Q 0.17677669529663687f
#define KSTR 40   // GEMM smem row stride in halves (80B, conflict-free for LDSM)
#define XS2 72    // adafm smem stride (halves); 144B -> LDSM conflict-free

// ---------------- scratch (device globals) ----------------------------------
__device__ float g_x2v[25165824];            // x after attn residual (B,C,H,W)
__device__ __half g_a[25165824];             // activations fp16 (131072 x 192)
__device__ __half g_b[100663296];            // qkv (131072x576) then fc1 out (131072x768)
__device__ __half g_w[442368];               // weights fp16 (qkv|proj|fc1|fc2)
__device__ __half g_Mh[2][32][4096];         // per-batch conv matrices, [out][in], fp16
__device__ float2 g_gn[2][32][32];           // (mean, rstd)

__constant__ float c_cos8[8] = {
    1.f, 0.70710678118654752f, 0.f, -0.70710678118654752f,
   -1.f, -0.70710678118654752f, 0.f, 0.70710678118654752f};

// ---------------- helpers ----------------------------------------------------
__device__ __forceinline__ unsigned su32(const void* p) {
    return (unsigned)__cvta_generic_to_shared(p);
}
__device__ __forceinline__ void cpasync16(unsigned dst, const void* src) {
    asm volatile("cp.async.ca.shared.global [%0], [%1], 16;" :: "r"(dst), "l"(src) : "memory");
}
__device__ __forceinline__ void cpcommit() {
    asm volatile("cp.async.commit_group;" ::: "memory");
}
template <int W> __device__ __forceinline__ void cpwait() {
    asm volatile("cp.async.wait_group %0;" :: "n"(W) : "memory");
}
__device__ __forceinline__ void ldsm4(unsigned a, unsigned& r0, unsigned& r1,
                                      unsigned& r2, unsigned& r3) {
    asm volatile("ldmatrix.sync.aligned.m8n8.x4.shared.b16 {%0,%1,%2,%3}, [%4];"
                 : "=r"(r0), "=r"(r1), "=r"(r2), "=r"(r3) : "r"(a));
}
__device__ __forceinline__ void ldsm4t(unsigned a, unsigned& r0, unsigned& r1,
                                       unsigned& r2, unsigned& r3) {
    asm volatile("ldmatrix.sync.aligned.m8n8.x4.trans.shared.b16 {%0,%1,%2,%3}, [%4];"
                 : "=r"(r0), "=r"(r1), "=r"(r2), "=r"(r3) : "r"(a));
}
__device__ __forceinline__ void mma16816(float* c, const unsigned* a, const unsigned* b) {
    asm volatile(
        "mma.sync.aligned.m16n8k16.row.col.f32.f16.f16.f32 "
        "{%0,%1,%2,%3}, {%4,%5,%6,%7}, {%8,%9}, {%0,%1,%2,%3};"
        : "+f"(c[0]), "+f"(c[1]), "+f"(c[2]), "+f"(c[3])
        : "r"(a[0]), "r"(a[1]), "r"(a[2]), "r"(a[3]), "r"(b[0]), "r"(b[1]));
}
__device__ __forceinline__ unsigned packh2(float x, float y) {
    __half2 h = __floats2half2_rn(x, y);
    return *(unsigned*)&h;
}

// ---------------- K1: adaFM spectra -> per-batch conv matrices (fp16, [out][in])
__global__ void __launch_bounds__(256) k_prep(
    const float* __restrict__ t,
    const float* __restrict__ wmsa, const float* __restrict__ bmsa,
    const float* __restrict__ wmlp, const float* __restrict__ bmlp)
{
    int b = blockIdx.x, tid = threadIdx.x;
    __shared__ float st[640];
    __shared__ float s[2][40];
    __shared__ float seff[2][64];
    __shared__ float ker[2][64];

    for (int i = tid; i < 640; i += 256) {
        float v = t[b * 640 + i];
        st[i] = v / (1.f + __expf(-v));
    }
    __syncthreads();
    if (tid < 80) {
        int br = tid / 40, f = tid % 40;
        const float* w  = br ? wmlp : wmsa;
        const float* bb = br ? bmlp : bmsa;
        float acc = bb[f];
        for (int e = 0; e < 640; e++) acc = fmaf(st[e], w[f * 640 + e], acc);
        s[br][f] = acc;
    }
    __syncthreads();
    if (tid < 128) {
        int br = tid >> 6, i = tid & 63, k1 = i >> 3, k2 = i & 7;
        float v;
        if (k2 == 0 || k2 == 4)
            v = 0.5f * (s[br][k1 * 5 + k2] + s[br][((8 - k1) & 7) * 5 + k2]);
        else if (k2 < 4) v = s[br][k1 * 5 + k2];
        else             v = s[br][((8 - k1) & 7) * 5 + (8 - k2)];
        seff[br][i] = v;
    }
    __syncthreads();
    if (tid < 128) {
        int br = tid >> 6, i = tid & 63, d1 = i >> 3, d2 = i & 7;
        float acc = 0.f;
        #pragma unroll
        for (int k = 0; k < 64; k++)
            acc = fmaf(seff[br][k], c_cos8[((k >> 3) * d1 + (k & 7) * d2) & 7], acc);
        ker[br][i] = acc * (1.f / 64.f);
    }
    __syncthreads();
    for (int idx = tid; idx < 8192; idx += 256) {
        int br = idx >> 12, j = idx & 4095;
        int out = j >> 6, in = j & 63;
        g_Mh[br][b][j] = __float2half_rn(
            ker[br][(((out >> 3) - (in >> 3)) & 7) * 8 + (((out & 7) - (in & 7)) & 7)]);
    }
}

// ---------------- K1b: all weights fp32 -> fp16 (one launch) -----------------
__global__ void k_wconv4(const float* __restrict__ w0, const float* __restrict__ w1,
                         const float* __restrict__ w2, const float* __restrict__ w3,
                         __half* __restrict__ h)
{
    int i = blockIdx.x * 256 + threadIdx.x;
    const float* s; int off;
    if (i < 110592)      { s = w0; off = 0; }
    else if (i < 147456) { s = w1; off = 110592; }
    else if (i < 294912) { s = w2; off = 147456; }
    else if (i < 442368) { s = w3; off = 294912; }
    else return;
    h[i] = __float2half_rn(s[i - off]);
}

// ---------------- K2: GroupNorm stats ---------------------------------------
__global__ void __launch_bounds__(256) k_gnstats(const float* __restrict__ x, int gi)
{
    int g = blockIdx.x, b = blockIdx.y;
    const float* p = x + ((size_t)b * 192 + g * 6) * 4096;
    float s = 0.f, s2 = 0.f;
    for (int i = threadIdx.x; i < 24576; i += 256) {
        float v = p[i]; s += v; s2 = fmaf(v, v, s2);
    }
    #pragma unroll
    for (int o = 16; o; o >>= 1) {
        s += __shfl_xor_sync(~0u, s, o); s2 += __shfl_xor_sync(~0u, s2, o);
    }
    __shared__ float sh[2][8];
    int wid = threadIdx.x >> 5;
    if (!(threadIdx.x & 31)) { sh[0][wid] = s; sh[1][wid] = s2; }
    __syncthreads();
    if (threadIdx.x < 32) {
        s  = (threadIdx.x < 8) ? sh[0][threadIdx.x] : 0.f;
        s2 = (threadIdx.x < 8) ? sh[1][threadIdx.x] : 0.f;
        #pragma unroll
        for (int o = 4; o; o >>= 1) {
            s += __shfl_xor_sync(~0u, s, o); s2 += __shfl_xor_sync(~0u, s2, o);
        }
        if (!threadIdx.x) {
            float m = s * (1.f / 24576.f);
            float var = s2 * (1.f / 24576.f) - m * m;
            g_gn[gi][b][g] = make_float2(m, rsqrtf(var + 1e-5f));
        }
    }
}

// ---------------- K3: tensor-core GN+adafm: Y = M(64x64) @ X(64x192) --------
// Xs channel-major [192 ch][64 px] -> vectorized fill, B frags via non-trans ldsm4.
template <int MODE>
__global__ void __launch_bounds__(256) k_adafm_tc(
    const float* __restrict__ src,
    const float* __restrict__ gw, const float* __restrict__ gbv)
{
    __shared__ __half Xs[192 * XS2];
    __shared__ __half Ms[64 * XS2];
    __shared__ float ga[192], gb[192];

    int patch = blockIdx.x, b = blockIdx.y;
    int py = patch >> 3, px = patch & 7;
    int tid = threadIdx.x, lane = tid & 31, wid = tid >> 5;

    // M tile via cp.async (fp16, [out][in]) — 512 chunks, 2 per thread
    #pragma unroll
    for (int r = 0; r < 2; r++) {
        int e = tid * 2 + r;                 // 0..511
        int row = e >> 3, ch = e & 7;
        cpasync16(su32(Ms + row * XS2 + ch * 8), &g_Mh[MODE][b][row * 64 + ch * 8]);
    }
    cpcommit();

    if (tid < 192) {
        float2 st = g_gn[MODE][b][tid / 6];
        float a = st.y * gw[tid];
        ga[tid] = a; gb[tid] = gbv[tid] - st.x * a;
    }
    __syncthreads();   // ga/gb visible

    // X fill: channel-major, vectorized half2 stores
    {
        const float* sb = src + ((size_t)b * 192) * 4096 + (py * 8) * 64 + px * 8;
        #pragma unroll
        for (int it = 0; it < 12; it++) {
            int idx = it * 256 + tid;
            int c = idx >> 4, q = idx & 15;          // q: group of 4 pixels
            float4 v = *(const float4*)(sb + (size_t)c * 4096 + (q >> 1) * 64 + (q & 1) * 4);
            float a = ga[c], o = gb[c];
            __half2* dst = (__half2*)(Xs + c * XS2 + q * 4);
            dst[0] = __floats2half2_rn(fmaf(v.x, a, o), fmaf(v.y, a, o));
            dst[1] = __floats2half2_rn(fmaf(v.z, a, o), fmaf(v.w, a, o));
        }
    }
    cpwait<0>();
    __syncthreads();

    int wr = (wid & 3) * 16, wc = (wid >> 2) * 96;
    float c[12][4];
    #pragma unroll
    for (int nt = 0; nt < 12; nt++)
        #pragma unroll
        for (int i = 0; i < 4; i++) c[nt][i] = 0.f;

    unsigned am[4][4];
    #pragma unroll
    for (int kk = 0; kk < 4; kk++) {
        int row = wr + (lane & 15);
        int col = kk * 16 + ((lane & 16) ? 8 : 0);
        ldsm4(su32(Ms) + (unsigned)((row * XS2 + col) * 2),
              am[kk][0], am[kk][1], am[kk][2], am[kk][3]);
    }
    #pragma unroll
    for (int kk = 0; kk < 4; kk++) {
        #pragma unroll
        for (int np = 0; np < 6; np++) {
            int row = wc + np * 16 + ((lane & 16) ? 8 : 0) + (lane & 7);
            int col = kk * 16 + ((lane & 8) ? 8 : 0);
            unsigned r0, r1, r2, r3;
            ldsm4(su32(Xs) + (unsigned)((row * XS2 + col) * 2), r0, r1, r2, r3);
            unsigned b0[2] = {r0, r1}, b1[2] = {r2, r3};
            mma16816(c[np * 2],     am[kk], b0);
            mma16816(c[np * 2 + 1], am[kk], b1);
        }
    }

    int g = lane >> 2, tg = lane & 3;
    #pragma unroll
    for (int h = 0; h < 2; h++) {
        int p = wr + g + h * 8;
        int hh = py * 8 + (p >> 3), ww = px * 8 + (p & 7);
        size_t off;
        if (MODE == 0) {
            int hh2 = (hh + 60) & 63, ww2 = (ww + 60) & 63;
            int win = ((hh2 >> 3) << 3) | (ww2 >> 3);
            int nn  = ((hh2 & 7) << 3) | (ww2 & 7);
            off = ((size_t)(b * 64 + win) * 64 + nn) * 192;
        } else {
            off = ((size_t)b * 4096 + hh * 64 + ww) * 192;
        }
        #pragma unroll
        for (int nt = 0; nt < 12; nt++) {
            int col = wc + nt * 8 + tg * 2;
            *(__half2*)(g_a + off + col) =
                __floats2half2_rn(c[nt][h * 2 + 0], c[nt][h * 2 + 1]);
        }
    }
}

// ---------------- K4: pipelined fp16 tensor GEMM, block 128x96, k-tile 32 ---
template <int EPI>
__global__ void __launch_bounds__(256, 2) k_hgemm(
    const __half* __restrict__ A, const __half* __restrict__ W,
    const float* __restrict__ bias, float* __restrict__ Cf,
    __half* __restrict__ Ch,
    int K, int N, const float* __restrict__ res)
{
    extern __shared__ __half smem[];
    const int ASZ = 128 * KSTR, BSZ = 96 * KSTR;
    const int STG = ASZ + BSZ;

    int m0 = blockIdx.y * 128, n0 = blockIdx.x * 96;
    int tid = threadIdx.x, lane = tid & 31, wid = tid >> 5;
    int wm = (wid & 3) * 32, wn = (wid >> 2) * 48;

    const __half* Ab = A + (size_t)m0 * K;
    const __half* Bb = W + (size_t)n0 * K;
    int KT = K >> 5;

    float c[2][6][4];
    #pragma unroll
    for (int mt = 0; mt < 2; mt++)
        #pragma unroll
        for (int nt = 0; nt < 6; nt++)
            #pragma unroll
            for (int i = 0; i < 4; i++) c[mt][nt][i] = 0.f;

    auto fill = [&](int kt, int st) {
        __half* base = smem + st * STG;
        int k0 = kt * 32;
        #pragma unroll
        for (int r = 0; r < 2; r++) {
            int e = tid * 2 + r, row = e >> 2, ch = e & 3;
            cpasync16(su32(base + row * KSTR + ch * 8),
                      Ab + (size_t)row * K + k0 + ch * 8);
        }
        {
            int row = tid >> 2, ch = tid & 3;
            cpasync16(su32(base + ASZ + row * KSTR + ch * 8),
                      Bb + (size_t)row * K + k0 + ch * 8);
        }
        if (tid < 128) {
            int e = 256 + tid, row = e >> 2, ch = e & 3;
            cpasync16(su32(base + ASZ + row * KSTR + ch * 8),
                      Bb + (size_t)row * K + k0 + ch * 8);
        }
        cpcommit();
    };

    fill(0, 0);
    for (int kt = 0; kt < KT; kt++) {
        if (kt + 1 < KT) { fill(kt + 1, (kt + 1) & 1); cpwait<1>(); }
        else             { cpwait<0>(); }
        __syncthreads();

        const __half* base = smem + (kt & 1) * STG;
        unsigned sA = su32(base);
        unsigned sB = su32(base + ASZ);

        #pragma unroll
        for (int kk = 0; kk < 2; kk++) {
            unsigned a[2][4];
            #pragma unroll
            for (int mt = 0; mt < 2; mt++) {
                int row = wm + mt * 16 + (lane & 15);
                int col = kk * 16 + ((lane & 16) ? 8 : 0);
                ldsm4(sA + (unsigned)((row * KSTR + col) * 2),
                      a[mt][0], a[mt][1], a[mt][2], a[mt][3]);
            }
            #pragma unroll
            for (int ntp = 0; ntp < 3; ntp++) {
                int row = wn + ntp * 16 + ((lane & 16) ? 8 : 0) + (lane & 7);
                int col = kk * 16 + ((lane & 8) ? 8 : 0);
                unsigned r0, r1, r2, r3;
                ldsm4(sB + (unsigned)((row * KSTR + col) * 2), r0, r1, r2, r3);
                unsigned b0[2] = {r0, r1}, b1[2] = {r2, r3};
                #pragma unroll
                for (int mt = 0; mt < 2; mt++) {
                    mma16816(c[mt][ntp * 2],     a[mt], b0);
                    mma16816(c[mt][ntp * 2 + 1], a[mt], b1);
                }
            }
        }
        __syncthreads();
    }

    int g = lane >> 2, tg = lane & 3;
    #pragma unroll
    for (int nt = 0; nt < 6; nt++) {
        int cb = n0 + wn + nt * 8 + tg * 2;
        float2 bv = *(const float2*)(bias + cb);
        #pragma unroll
        for (int mt = 0; mt < 2; mt++)
            #pragma unroll
            for (int h = 0; h < 2; h++) {
                int m = m0 + wm + mt * 16 + g + h * 8;
                float v0 = c[mt][nt][h * 2 + 0] + bv.x;
                float v1 = c[mt][nt][h * 2 + 1] + bv.y;
                if (EPI == 0) {
                    *(__half2*)(Ch + (size_t)m * N + cb) = __floats2half2_rn(v0, v1);
                } else if (EPI == 1) {
                    float g0 = 0.5f * v0 * (1.f + erff(v0 * 0.70710678118654752f));
                    float g1 = 0.5f * v1 * (1.f + erff(v1 * 0.70710678118654752f));
                    *(__half2*)(Ch + (size_t)m * N + cb) = __floats2half2_rn(g0, g1);
                } else if (EPI == 2) {
                    int b = m >> 12, win = (m >> 6) & 63, nn = m & 63;
                    int hh = ((((win >> 3) << 3) + (nn >> 3)) + 4) & 63;
                    int ww = ((((win & 7) << 3) + (nn & 7)) + 4) & 63;
                    size_t base2 = ((size_t)b * 192) * 4096 + hh * 64 + ww;
                    size_t i0 = base2 + (size_t)cb * 4096;
                    size_t i1 = base2 + (size_t)(cb + 1) * 4096;
                    Cf[i0] = res[i0] + v0;
                    Cf[i1] = res[i1] + v1;
                } else {
                    int b = m >> 12, pix = m & 4095;
                    size_t i0 = ((size_t)(b * 192 + cb)) * 4096 + pix;
                    size_t i1 = i0 + 4096;
                    Cf[i0] = res[i0] + v0;
                    Cf[i1] = res[i1] + v1;
                }
            }
    }
}

// ---------------- K5: tensor-core window attention ---------------------------
__global__ void __launch_bounds__(128) k_attn_tc(
    const __half* __restrict__ qkv, const float* __restrict__ rpb)
{
    __shared__ __half Qs[64 * KSTR], Ks[64 * KSTR], Vs[64 * KSTR];
    __shared__ float Br[225];
    __shared__ int Cat[64];

    int w = blockIdx.x, head = blockIdx.y;
    int tid = threadIdx.x, lane = tid & 31, wq = tid >> 5;

    const __half* base = qkv + (size_t)w * 64 * 576 + head * 32;
    #pragma unroll
    for (int r = 0; r < 2; r++) {
        int idx = tid + r * 128;
        int row = idx >> 2, ch = idx & 3;
        const __half* src = base + (size_t)row * 576 + ch * 8;
        unsigned doff = (unsigned)((row * KSTR + ch * 8) * 2);
        cpasync16(su32(Qs) + doff, src);
        cpasync16(su32(Ks) + doff, src + 192);
        cpasync16(su32(Vs) + doff, src + 384);
    }
    cpcommit();

    for (int i = tid; i < 225; i += 128) Br[i] = rpb[i * 6 + head];
    if (tid < 64) {
        int win = w & 63;
        int hh2 = ((win >> 3) << 3) + (tid >> 3);
        int ww2 = ((win & 7) << 3) + (tid & 7);
        int ch = hh2 < 56 ? 0 : (hh2 < 60 ? 1 : 2);
        int cw = ww2 < 56 ? 0 : (ww2 < 60 ? 1 : 2);
        Cat[tid] = ch * 3 + cw;
    }
    cpwait<0>();
    __syncthreads();

    int g = lane >> 2, tg = lane & 3;

    float c[8][4];
    #pragma unroll
    for (int nt = 0; nt < 8; nt++)
        #pragma unroll
        for (int i = 0; i < 4; i++) c[nt][i] = 0.f;

    unsigned aq[2][4];
    #pragma unroll
    for (int kk = 0; kk < 2; kk++) {
        int row = wq * 16 + (lane & 15);
        int col = kk * 16 + ((lane & 16) ? 8 : 0);
        ldsm4(su32(Qs) + (unsigned)((row * KSTR + col) * 2),
              aq[kk][0], aq[kk][1], aq[kk][2], aq[kk][3]);
    }
    #pragma unroll
    for (int kk = 0; kk < 2; kk++) {
        #pragma unroll
        for (int ntp = 0; ntp < 4; ntp++) {
            int row = ntp * 16 + ((lane & 16) ? 8 : 0) + (lane & 7);
            int col = kk * 16 + ((lane & 8) ? 8 : 0);
            unsigned r0, r1, r2, r3;
            ldsm4(su32(Ks) + (unsigned)((row * KSTR + col) * 2), r0, r1, r2, r3);
            unsigned b0[2] = {r0, r1}, b1[2] = {r2, r3};
            mma16816(c[ntp * 2],     aq[kk], b0);
            mma16816(c[ntp * 2 + 1], aq[kk], b1);
        }
    }

    int row0 = wq * 16 + g, row1 = row0 + 8;
    int rn0 = row0 >> 3, cn0 = row0 & 7, rn1 = row1 >> 3, cn1 = row1 & 7;
    int cat0 = Cat[row0], cat1 = Cat[row1];
    #pragma unroll
    for (int nt = 0; nt < 8; nt++) {
        #pragma unroll
        for (int j = 0; j < 2; j++) {
            int col = nt * 8 + tg * 2 + j;
            int rm = col >> 3, cm = col & 7, cc = Cat[col];
            float b0v = Br[(rn0 - rm + 7) * 15 + (cn0 - cm + 7)] + (cc != cat0 ? -100.f : 0.f);
            float b1v = Br[(rn1 - rm + 7) * 15 + (cn1 - cm + 7)] + (cc != cat1 ? -100.f : 0.f);
            c[nt][j]     = c[nt][j]     * SCALE_Q + b0v;
            c[nt][j + 2] = c[nt][j + 2] * SCALE_Q + b1v;
        }
    }

    float mx0 = -1e30f, mx1 = -1e30f;
    #pragma unroll
    for (int nt = 0; nt < 8; nt++) {
        mx0 = fmaxf(mx0, fmaxf(c[nt][0], c[nt][1]));
        mx1 = fmaxf(mx1, fmaxf(c[nt][2], c[nt][3]));
    }
    #pragma unroll
    for (int o = 1; o < 4; o <<= 1) {
        mx0 = fmaxf(mx0, __shfl_xor_sync(~0u, mx0, o));
        mx1 = fmaxf(mx1, __shfl_xor_sync(~0u, mx1, o));
    }
    float sm0 = 0.f, sm1 = 0.f;
    #pragma unroll
    for (int nt = 0; nt < 8; nt++) {
        c[nt][0] = __expf(c[nt][0] - mx0); sm0 += c[nt][0];
        c[nt][1] = __expf(c[nt][1] - mx0); sm0 += c[nt][1];
        c[nt][2] = __expf(c[nt][2] - mx1); sm1 += c[nt][2];
        c[nt][3] = __expf(c[nt][3] - mx1); sm1 += c[nt][3];
    }
    #pragma unroll
    for (int o = 1; o < 4; o <<= 1) {
        sm0 += __shfl_xor_sync(~0u, sm0, o);
        sm1 += __shfl_xor_sync(~0u, sm1, o);
    }
    float inv0 = 1.f / sm0, inv1 = 1.f / sm1;

    float c2[4][4];
    #pragma unroll
    for (int nt = 0; nt < 4; nt++)
        #pragma unroll
        for (int i = 0; i < 4; i++) c2[nt][i] = 0.f;

    #pragma unroll
    for (int kk = 0; kk < 4; kk++) {
        unsigned ap[4];
        ap[0] = packh2(c[kk * 2][0],     c[kk * 2][1]);
        ap[1] = packh2(c[kk * 2][2],     c[kk * 2][3]);
        ap[2] = packh2(c[kk * 2 + 1][0], c[kk * 2 + 1][1]);
        ap[3] = packh2(c[kk * 2 + 1][2], c[kk * 2 + 1][3]);
        #pragma unroll
        for (int np = 0; np < 2; np++) {
            int row = kk * 16 + (lane & 15);
            int col = np * 16 + ((lane & 16) ? 8 : 0);
            unsigned r0, r1, r2, r3;
            ldsm4t(su32(Vs) + (unsigned)((row * KSTR + col) * 2), r0, r1, r2, r3);
            unsigned b0[2] = {r0, r1}, b1[2] = {r2, r3};
            mma16816(c2[np * 2],     ap, b0);
            mma16816(c2[np * 2 + 1], ap, b1);
        }
    }

    size_t obase = ((size_t)w * 64) * 192 + head * 32;
    #pragma unroll
    for (int nt = 0; nt < 4; nt++) {
        int col = nt * 8 + tg * 2;
        *(__half2*)(g_a + obase + (size_t)row0 * 192 + col) =
            __floats2half2_rn(c2[nt][0] * inv0, c2[nt][1] * inv0);
        *(__half2*)(g_a + obase + (size_t)row1 * 192 + col) =
            __floats2half2_rn(c2[nt][2] * inv1, c2[nt][3] * inv1);
    }
}

// ---------------- launch ------------------------------------------------------
extern "C" void kernel_launch(void* const* d_in, const int* in_sizes, int n_in,
                              void* d_out, int out_size)
{
    const float* x    = (const float*)d_in[0];
    const float* t    = (const float*)d_in[1];
    const float* n1w  = (const float*)d_in[2];
    const float* n1b  = (const float*)d_in[3];
    const float* qkvw = (const float*)d_in[4];
    const float* qkvb = (const float*)d_in[5];
    const float* rpb  = (const float*)d_in[6];
    const float* pw   = (const float*)d_in[7];
    const float* pb   = (const float*)d_in[8];
    const float* n2w  = (const float*)d_in[9];
    const float* n2b  = (const float*)d_in[10];
    const float* f1w  = (const float*)d_in[11];
    const float* f1b  = (const float*)d_in[12];
    const float* f2w  = (const float*)d_in[13];
    const float* f2b  = (const float*)d_in[14];
    const float* amw  = (const float*)d_in[15];
    const float* amb  = (const float*)d_in[16];
    const float* alw  = (const float*)d_in[17];
    const float* alb  = (const float*)d_in[18];
    float* out = (float*)d_out;

    float *x2;
    __half *a16, *b16, *w16;
    cudaGetSymbolAddress((void**)&x2,  g_x2v);
    cudaGetSymbolAddress((void**)&a16, g_a);
    cudaGetSymbolAddress((void**)&b16, g_b);
    cudaGetSymbolAddress((void**)&w16, g_w);

    const int GEMM_SMEM = 2 * (128 * KSTR + 96 * KSTR) * 2;  // 35840 B
    static int attr_done = 0;
    if (!attr_done) {
        cudaFuncSetAttribute(k_hgemm<0>, cudaFuncAttributeMaxDynamicSharedMemorySize, GEMM_SMEM);
        cudaFuncSetAttribute(k_hgemm<1>, cudaFuncAttributeMaxDynamicSharedMemorySize, GEMM_SMEM);
        cudaFuncSetAttribute(k_hgemm<2>, cudaFuncAttributeMaxDynamicSharedMemorySize, GEMM_SMEM);
        cudaFuncSetAttribute(k_hgemm<3>, cudaFuncAttributeMaxDynamicSharedMemorySize, GEMM_SMEM);
        attr_done = 1;
    }

    k_prep<<<32, 256>>>(t, amw, amb, alw, alb);
    k_wconv4<<<1728, 256>>>(qkvw, pw, f1w, f2w, w16);

    k_gnstats<<<dim3(32, 32), 256>>>(x, 0);
    k_adafm_tc<0><<<dim3(64, 32), 256>>>(x, n1w, n1b);
    // qkv: (131072 x 192) @ (576 x 192)^T -> fp16 into g_b
    k_hgemm<0><<<dim3(6, 1024), 256, GEMM_SMEM>>>(a16, w16, qkvb,
                                                  nullptr, b16, 192, 576, nullptr);
    // tensor-core attention -> g_a (fp16)
    k_attn_tc<<<dim3(2048, 6), 128>>>(b16, rpb);
    // proj + window reverse + roll + residual -> x2
    k_hgemm<2><<<dim3(2, 1024), 256, GEMM_SMEM>>>(a16, w16 + 110592, pb,
                                                  x2, nullptr, 192, 192, x);
    k_gnstats<<<dim3(32, 32), 256>>>(x2, 1);
    k_adafm_tc<1><<<dim3(64, 32), 256>>>(x2, n2w, n2b);
    // fc1 + GELU -> fp16
    k_hgemm<1><<<dim3(8, 1024), 256, GEMM_SMEM>>>(a16, w16 + 147456, f1b,
                                                  nullptr, b16, 192, 768, nullptr);
    // fc2 + residual scatter -> out
    k_hgemm<3><<<dim3(2, 1024), 256, GEMM_SMEM>>>(b16, w16 + 294912, f2b,
                                                  out, nullptr, 768, 192, x2);
}

// round 14
// speedup vs baseline: 3.3213x; 1.1833x over previous
#include <cuda_runtime.h>
#include <cuda_fp16.h>
#include <math.h>

#define SCALE_Q 0.17677669529663687f
#define KSTR 40   // attention smem row stride in halves
#define GS 72     // GEMM/adafm smem stride (halves); 144B rows, LDSM conflict-free

// ---------------- scratch (device globals) ----------------------------------
__device__ float g_x2v[25165824];            // x after attn residual (B,C,H,W)
__device__ __half g_a[25165824];             // activations fp16 (131072 x 192)
__device__ __half g_b[100663296];            // qkv (131072x576) then fc1 out (131072x768)
__device__ __half g_w[442368];               // weights fp16 (qkv|proj|fc1|fc2)
__device__ __half g_Mh[2][32][4096];         // per-batch conv matrices, [out][in], fp16
__device__ float2 g_gn[2][32][32];           // (mean, rstd)

__constant__ float c_cos8[8] = {
    1.f, 0.70710678118654752f, 0.f, -0.70710678118654752f,
   -1.f, -0.70710678118654752f, 0.f, 0.70710678118654752f};

// ---------------- helpers ----------------------------------------------------
__device__ __forceinline__ unsigned su32(const void* p) {
    return (unsigned)__cvta_generic_to_shared(p);
}
__device__ __forceinline__ void cpasync16(unsigned dst, const void* src) {
    asm volatile("cp.async.ca.shared.global [%0], [%1], 16;" :: "r"(dst), "l"(src) : "memory");
}
__device__ __forceinline__ void cpcommit() {
    asm volatile("cp.async.commit_group;" ::: "memory");
}
template <int W> __device__ __forceinline__ void cpwait() {
    asm volatile("cp.async.wait_group %0;" :: "n"(W) : "memory");
}
__device__ __forceinline__ void ldsm4(unsigned a, unsigned& r0, unsigned& r1,
                                      unsigned& r2, unsigned& r3) {
    asm volatile("ldmatrix.sync.aligned.m8n8.x4.shared.b16 {%0,%1,%2,%3}, [%4];"
                 : "=r"(r0), "=r"(r1), "=r"(r2), "=r"(r3) : "r"(a));
}
__device__ __forceinline__ void ldsm4t(unsigned a, unsigned& r0, unsigned& r1,
                                       unsigned& r2, unsigned& r3) {
    asm volatile("ldmatrix.sync.aligned.m8n8.x4.trans.shared.b16 {%0,%1,%2,%3}, [%4];"
                 : "=r"(r0), "=r"(r1), "=r"(r2), "=r"(r3) : "r"(a));
}
__device__ __forceinline__ void mma16816(float* c, const unsigned* a, const unsigned* b) {
    asm volatile(
        "mma.sync.aligned.m16n8k16.row.col.f32.f16.f16.f32 "
        "{%0,%1,%2,%3}, {%4,%5,%6,%7}, {%8,%9}, {%0,%1,%2,%3};"
        : "+f"(c[0]), "+f"(c[1]), "+f"(c[2]), "+f"(c[3])
        : "r"(a[0]), "r"(a[1]), "r"(a[2]), "r"(a[3]), "r"(b[0]), "r"(b[1]));
}
__device__ __forceinline__ unsigned packh2(float x, float y) {
    __half2 h = __floats2half2_rn(x, y);
    return *(unsigned*)&h;
}

// ---------------- K1: adaFM spectra -> per-batch conv matrices (fp16, [out][in])
__global__ void __launch_bounds__(256) k_prep(
    const float* __restrict__ t,
    const float* __restrict__ wmsa, const float* __restrict__ bmsa,
    const float* __restrict__ wmlp, const float* __restrict__ bmlp)
{
    int b = blockIdx.x, tid = threadIdx.x;
    __shared__ float st[640];
    __shared__ float s[2][40];
    __shared__ float seff[2][64];
    __shared__ float ker[2][64];

    for (int i = tid; i < 640; i += 256) {
        float v = t[b * 640 + i];
        st[i] = v / (1.f + __expf(-v));
    }
    __syncthreads();
    if (tid < 80) {
        int br = tid / 40, f = tid % 40;
        const float* w  = br ? wmlp : wmsa;
        const float* bb = br ? bmlp : bmsa;
        float acc = bb[f];
        for (int e = 0; e < 640; e++) acc = fmaf(st[e], w[f * 640 + e], acc);
        s[br][f] = acc;
    }
    __syncthreads();
    if (tid < 128) {
        int br = tid >> 6, i = tid & 63, k1 = i >> 3, k2 = i & 7;
        float v;
        if (k2 == 0 || k2 == 4)
            v = 0.5f * (s[br][k1 * 5 + k2] + s[br][((8 - k1) & 7) * 5 + k2]);
        else if (k2 < 4) v = s[br][k1 * 5 + k2];
        else             v = s[br][((8 - k1) & 7) * 5 + (8 - k2)];
        seff[br][i] = v;
    }
    __syncthreads();
    if (tid < 128) {
        int br = tid >> 6, i = tid & 63, d1 = i >> 3, d2 = i & 7;
        float acc = 0.f;
        #pragma unroll
        for (int k = 0; k < 64; k++)
            acc = fmaf(seff[br][k], c_cos8[((k >> 3) * d1 + (k & 7) * d2) & 7], acc);
        ker[br][i] = acc * (1.f / 64.f);
    }
    __syncthreads();
    for (int idx = tid; idx < 8192; idx += 256) {
        int br = idx >> 12, j = idx & 4095;
        int out = j >> 6, in = j & 63;
        g_Mh[br][b][j] = __float2half_rn(
            ker[br][(((out >> 3) - (in >> 3)) & 7) * 8 + (((out & 7) - (in & 7)) & 7)]);
    }
}

// ---------------- K1b: all weights fp32 -> fp16 (one launch) -----------------
__global__ void k_wconv4(const float* __restrict__ w0, const float* __restrict__ w1,
                         const float* __restrict__ w2, const float* __restrict__ w3,
                         __half* __restrict__ h)
{
    int i = blockIdx.x * 256 + threadIdx.x;
    const float* s; int off;
    if (i < 110592)      { s = w0; off = 0; }
    else if (i < 147456) { s = w1; off = 110592; }
    else if (i < 294912) { s = w2; off = 147456; }
    else if (i < 442368) { s = w3; off = 294912; }
    else return;
    h[i] = __float2half_rn(s[i - off]);
}

// ---------------- K2: GroupNorm stats ---------------------------------------
__global__ void __launch_bounds__(256) k_gnstats(const float* __restrict__ x, int gi)
{
    int g = blockIdx.x, b = blockIdx.y;
    const float* p = x + ((size_t)b * 192 + g * 6) * 4096;
    float s = 0.f, s2 = 0.f;
    for (int i = threadIdx.x; i < 24576; i += 256) {
        float v = p[i]; s += v; s2 = fmaf(v, v, s2);
    }
    #pragma unroll
    for (int o = 16; o; o >>= 1) {
        s += __shfl_xor_sync(~0u, s, o); s2 += __shfl_xor_sync(~0u, s2, o);
    }
    __shared__ float sh[2][8];
    int wid = threadIdx.x >> 5;
    if (!(threadIdx.x & 31)) { sh[0][wid] = s; sh[1][wid] = s2; }
    __syncthreads();
    if (threadIdx.x < 32) {
        s  = (threadIdx.x < 8) ? sh[0][threadIdx.x] : 0.f;
        s2 = (threadIdx.x < 8) ? sh[1][threadIdx.x] : 0.f;
        #pragma unroll
        for (int o = 4; o; o >>= 1) {
            s += __shfl_xor_sync(~0u, s, o); s2 += __shfl_xor_sync(~0u, s2, o);
        }
        if (!threadIdx.x) {
            float m = s * (1.f / 24576.f);
            float var = s2 * (1.f / 24576.f) - m * m;
            g_gn[gi][b][g] = make_float2(m, rsqrtf(var + 1e-5f));
        }
    }
}

// ---------------- K3: tensor-core GN+adafm: Y = M(64x64) @ X(64x192) --------
template <int MODE>
__global__ void __launch_bounds__(256) k_adafm_tc(
    const float* __restrict__ src,
    const float* __restrict__ gw, const float* __restrict__ gbv)
{
    __shared__ __half Xs[192 * GS];
    __shared__ __half Ms[64 * GS];
    __shared__ float ga[192], gb[192];

    int patch = blockIdx.x, b = blockIdx.y;
    int py = patch >> 3, px = patch & 7;
    int tid = threadIdx.x, lane = tid & 31, wid = tid >> 5;

    #pragma unroll
    for (int r = 0; r < 2; r++) {
        int e = tid * 2 + r;                 // 0..511
        int row = e >> 3, ch = e & 7;
        cpasync16(su32(Ms + row * GS + ch * 8), &g_Mh[MODE][b][row * 64 + ch * 8]);
    }
    cpcommit();

    if (tid < 192) {
        float2 st = g_gn[MODE][b][tid / 6];
        float a = st.y * gw[tid];
        ga[tid] = a; gb[tid] = gbv[tid] - st.x * a;
    }
    __syncthreads();

    {
        const float* sb = src + ((size_t)b * 192) * 4096 + (py * 8) * 64 + px * 8;
        #pragma unroll
        for (int it = 0; it < 12; it++) {
            int idx = it * 256 + tid;
            int c = idx >> 4, q = idx & 15;
            float4 v = *(const float4*)(sb + (size_t)c * 4096 + (q >> 1) * 64 + (q & 1) * 4);
            float a = ga[c], o = gb[c];
            __half2* dst = (__half2*)(Xs + c * GS + q * 4);
            dst[0] = __floats2half2_rn(fmaf(v.x, a, o), fmaf(v.y, a, o));
            dst[1] = __floats2half2_rn(fmaf(v.z, a, o), fmaf(v.w, a, o));
        }
    }
    cpwait<0>();
    __syncthreads();

    int wr = (wid & 3) * 16, wc = (wid >> 2) * 96;
    float c[12][4];
    #pragma unroll
    for (int nt = 0; nt < 12; nt++)
        #pragma unroll
        for (int i = 0; i < 4; i++) c[nt][i] = 0.f;

    unsigned am[4][4];
    #pragma unroll
    for (int kk = 0; kk < 4; kk++) {
        int row = wr + (lane & 15);
        int col = kk * 16 + ((lane & 16) ? 8 : 0);
        ldsm4(su32(Ms) + (unsigned)((row * GS + col) * 2),
              am[kk][0], am[kk][1], am[kk][2], am[kk][3]);
    }
    #pragma unroll
    for (int kk = 0; kk < 4; kk++) {
        #pragma unroll
        for (int np = 0; np < 6; np++) {
            int row = wc + np * 16 + ((lane & 16) ? 8 : 0) + (lane & 7);
            int col = kk * 16 + ((lane & 8) ? 8 : 0);
            unsigned r0, r1, r2, r3;
            ldsm4(su32(Xs) + (unsigned)((row * GS + col) * 2), r0, r1, r2, r3);
            unsigned b0[2] = {r0, r1}, b1[2] = {r2, r3};
            mma16816(c[np * 2],     am[kk], b0);
            mma16816(c[np * 2 + 1], am[kk], b1);
        }
    }

    int g = lane >> 2, tg = lane & 3;
    #pragma unroll
    for (int h = 0; h < 2; h++) {
        int p = wr + g + h * 8;
        int hh = py * 8 + (p >> 3), ww = px * 8 + (p & 7);
        size_t off;
        if (MODE == 0) {
            int hh2 = (hh + 60) & 63, ww2 = (ww + 60) & 63;
            int win = ((hh2 >> 3) << 3) | (ww2 >> 3);
            int nn  = ((hh2 & 7) << 3) | (ww2 & 7);
            off = ((size_t)(b * 64 + win) * 64 + nn) * 192;
        } else {
            off = ((size_t)b * 4096 + hh * 64 + ww) * 192;
        }
        #pragma unroll
        for (int nt = 0; nt < 12; nt++) {
            int col = wc + nt * 8 + tg * 2;
            *(__half2*)(g_a + off + col) =
                __floats2half2_rn(c[nt][h * 2 + 0], c[nt][h * 2 + 1]);
        }
    }
}

// ---------------- K4: pipelined fp16 tensor GEMM, block 128x96, k-tile 64 ---
template <int EPI>
__global__ void __launch_bounds__(256, 2) k_hgemm(
    const __half* __restrict__ A, const __half* __restrict__ W,
    const float* __restrict__ bias, float* __restrict__ Cf,
    __half* __restrict__ Ch,
    int K, int N, const float* __restrict__ res)
{
    extern __shared__ __half smem[];
    const int ASZ = 128 * GS, BSZ = 96 * GS;
    const int STG = ASZ + BSZ;

    int m0 = blockIdx.y * 128, n0 = blockIdx.x * 96;
    int tid = threadIdx.x, lane = tid & 31, wid = tid >> 5;
    int wm = (wid & 3) * 32, wn = (wid >> 2) * 48;

    const __half* Ab = A + (size_t)m0 * K;
    const __half* Bb = W + (size_t)n0 * K;
    int KT = K >> 6;

    float c[2][6][4];
    #pragma unroll
    for (int mt = 0; mt < 2; mt++)
        #pragma unroll
        for (int nt = 0; nt < 6; nt++)
            #pragma unroll
            for (int i = 0; i < 4; i++) c[mt][nt][i] = 0.f;

    auto fill = [&](int kt, int st) {
        __half* base = smem + st * STG;
        int k0 = kt * 64;
        #pragma unroll
        for (int r = 0; r < 4; r++) {            // A: 1024 chunks
            int e = tid + r * 256, row = e >> 3, ch = e & 7;
            cpasync16(su32(base + row * GS + ch * 8),
                      Ab + (size_t)row * K + k0 + ch * 8);
        }
        #pragma unroll
        for (int r = 0; r < 3; r++) {            // B: 768 chunks
            int e = tid + r * 256, row = e >> 3, ch = e & 7;
            cpasync16(su32(base + ASZ + row * GS + ch * 8),
                      Bb + (size_t)row * K + k0 + ch * 8);
        }
        cpcommit();
    };

    fill(0, 0);
    for (int kt = 0; kt < KT; kt++) {
        if (kt + 1 < KT) { fill(kt + 1, (kt + 1) & 1); cpwait<1>(); }
        else             { cpwait<0>(); }
        __syncthreads();

        const __half* base = smem + (kt & 1) * STG;
        unsigned sA = su32(base);
        unsigned sB = su32(base + ASZ);

        #pragma unroll
        for (int kk = 0; kk < 4; kk++) {
            unsigned a[2][4];
            #pragma unroll
            for (int mt = 0; mt < 2; mt++) {
                int row = wm + mt * 16 + (lane & 15);
                int col = kk * 16 + ((lane & 16) ? 8 : 0);
                ldsm4(sA + (unsigned)((row * GS + col) * 2),
                      a[mt][0], a[mt][1], a[mt][2], a[mt][3]);
            }
            #pragma unroll
            for (int ntp = 0; ntp < 3; ntp++) {
                int row = wn + ntp * 16 + ((lane & 16) ? 8 : 0) + (lane & 7);
                int col = kk * 16 + ((lane & 8) ? 8 : 0);
                unsigned r0, r1, r2, r3;
                ldsm4(sB + (unsigned)((row * GS + col) * 2), r0, r1, r2, r3);
                unsigned b0[2] = {r0, r1}, b1[2] = {r2, r3};
                #pragma unroll
                for (int mt = 0; mt < 2; mt++) {
                    mma16816(c[mt][ntp * 2],     a[mt], b0);
                    mma16816(c[mt][ntp * 2 + 1], a[mt], b1);
                }
            }
        }
        __syncthreads();
    }

    int g = lane >> 2, tg = lane & 3;
    #pragma unroll
    for (int nt = 0; nt < 6; nt++) {
        int cb = n0 + wn + nt * 8 + tg * 2;
        float2 bv = *(const float2*)(bias + cb);
        #pragma unroll
        for (int mt = 0; mt < 2; mt++)
            #pragma unroll
            for (int h = 0; h < 2; h++) {
                int m = m0 + wm + mt * 16 + g + h * 8;
                float v0 = c[mt][nt][h * 2 + 0] + bv.x;
                float v1 = c[mt][nt][h * 2 + 1] + bv.y;
                if (EPI == 0) {
                    *(__half2*)(Ch + (size_t)m * N + cb) = __floats2half2_rn(v0, v1);
                } else if (EPI == 1) {
                    float g0 = 0.5f * v0 * (1.f + erff(v0 * 0.70710678118654752f));
                    float g1 = 0.5f * v1 * (1.f + erff(v1 * 0.70710678118654752f));
                    *(__half2*)(Ch + (size_t)m * N + cb) = __floats2half2_rn(g0, g1);
                } else if (EPI == 2) {
                    int b = m >> 12, win = (m >> 6) & 63, nn = m & 63;
                    int hh = ((((win >> 3) << 3) + (nn >> 3)) + 4) & 63;
                    int ww = ((((win & 7) << 3) + (nn & 7)) + 4) & 63;
                    size_t base2 = ((size_t)b * 192) * 4096 + hh * 64 + ww;
                    size_t i0 = base2 + (size_t)cb * 4096;
                    size_t i1 = base2 + (size_t)(cb + 1) * 4096;
                    Cf[i0] = res[i0] + v0;
                    Cf[i1] = res[i1] + v1;
                } else {
                    int b = m >> 12, pix = m & 4095;
                    size_t i0 = ((size_t)(b * 192 + cb)) * 4096 + pix;
                    size_t i1 = i0 + 4096;
                    Cf[i0] = res[i0] + v0;
                    Cf[i1] = res[i1] + v1;
                }
            }
    }
}

// ---------------- K5: tensor-core window attention ---------------------------
__global__ void __launch_bounds__(128) k_attn_tc(
    const __half* __restrict__ qkv, const float* __restrict__ rpb)
{
    __shared__ __half Qs[64 * KSTR], Ks[64 * KSTR], Vs[64 * KSTR];
    __shared__ float Br[225];
    __shared__ int Cat[64];

    int w = blockIdx.x, head = blockIdx.y;
    int tid = threadIdx.x, lane = tid & 31, wq = tid >> 5;

    const __half* base = qkv + (size_t)w * 64 * 576 + head * 32;
    #pragma unroll
    for (int r = 0; r < 2; r++) {
        int idx = tid + r * 128;
        int row = idx >> 2, ch = idx & 3;
        const __half* src = base + (size_t)row * 576 + ch * 8;
        unsigned doff = (unsigned)((row * KSTR + ch * 8) * 2);
        cpasync16(su32(Qs) + doff, src);
        cpasync16(su32(Ks) + doff, src + 192);
        cpasync16(su32(Vs) + doff, src + 384);
    }
    cpcommit();

    for (int i = tid; i < 225; i += 128) Br[i] = rpb[i * 6 + head];
    if (tid < 64) {
        int win = w & 63;
        int hh2 = ((win >> 3) << 3) + (tid >> 3);
        int ww2 = ((win & 7) << 3) + (tid & 7);
        int ch = hh2 < 56 ? 0 : (hh2 < 60 ? 1 : 2);
        int cw = ww2 < 56 ? 0 : (ww2 < 60 ? 1 : 2);
        Cat[tid] = ch * 3 + cw;
    }
    cpwait<0>();
    __syncthreads();

    int g = lane >> 2, tg = lane & 3;

    float c[8][4];
    #pragma unroll
    for (int nt = 0; nt < 8; nt++)
        #pragma unroll
        for (int i = 0; i < 4; i++) c[nt][i] = 0.f;

    unsigned aq[2][4];
    #pragma unroll
    for (int kk = 0; kk < 2; kk++) {
        int row = wq * 16 + (lane & 15);
        int col = kk * 16 + ((lane & 16) ? 8 : 0);
        ldsm4(su32(Qs) + (unsigned)((row * KSTR + col) * 2),
              aq[kk][0], aq[kk][1], aq[kk][2], aq[kk][3]);
    }
    #pragma unroll
    for (int kk = 0; kk < 2; kk++) {
        #pragma unroll
        for (int ntp = 0; ntp < 4; ntp++) {
            int row = ntp * 16 + ((lane & 16) ? 8 : 0) + (lane & 7);
            int col = kk * 16 + ((lane & 8) ? 8 : 0);
            unsigned r0, r1, r2, r3;
            ldsm4(su32(Ks) + (unsigned)((row * KSTR + col) * 2), r0, r1, r2, r3);
            unsigned b0[2] = {r0, r1}, b1[2] = {r2, r3};
            mma16816(c[ntp * 2],     aq[kk], b0);
            mma16816(c[ntp * 2 + 1], aq[kk], b1);
        }
    }

    int row0 = wq * 16 + g, row1 = row0 + 8;
    int rn0 = row0 >> 3, cn0 = row0 & 7, rn1 = row1 >> 3, cn1 = row1 & 7;
    int cat0 = Cat[row0], cat1 = Cat[row1];
    #pragma unroll
    for (int nt = 0; nt < 8; nt++) {
        #pragma unroll
        for (int j = 0; j < 2; j++) {
            int col = nt * 8 + tg * 2 + j;
            int rm = col >> 3, cm = col & 7, cc = Cat[col];
            float b0v = Br[(rn0 - rm + 7) * 15 + (cn0 - cm + 7)] + (cc != cat0 ? -100.f : 0.f);
            float b1v = Br[(rn1 - rm + 7) * 15 + (cn1 - cm + 7)] + (cc != cat1 ? -100.f : 0.f);
            c[nt][j]     = c[nt][j]     * SCALE_Q + b0v;
            c[nt][j + 2] = c[nt][j + 2] * SCALE_Q + b1v;
        }
    }

    float mx0 = -1e30f, mx1 = -1e30f;
    #pragma unroll
    for (int nt = 0; nt < 8; nt++) {
        mx0 = fmaxf(mx0, fmaxf(c[nt][0], c[nt][1]));
        mx1 = fmaxf(mx1, fmaxf(c[nt][2], c[nt][3]));
    }
    #pragma unroll
    for (int o = 1; o < 4; o <<= 1) {
        mx0 = fmaxf(mx0, __shfl_xor_sync(~0u, mx0, o));
        mx1 = fmaxf(mx1, __shfl_xor_sync(~0u, mx1, o));
    }
    float sm0 = 0.f, sm1 = 0.f;
    #pragma unroll
    for (int nt = 0; nt < 8; nt++) {
        c[nt][0] = __expf(c[nt][0] - mx0); sm0 += c[nt][0];
        c[nt][1] = __expf(c[nt][1] - mx0); sm0 += c[nt][1];
        c[nt][2] = __expf(c[nt][2] - mx1); sm1 += c[nt][2];
        c[nt][3] = __expf(c[nt][3] - mx1); sm1 += c[nt][3];
    }
    #pragma unroll
    for (int o = 1; o < 4; o <<= 1) {
        sm0 += __shfl_xor_sync(~0u, sm0, o);
        sm1 += __shfl_xor_sync(~0u, sm1, o);
    }
    float inv0 = 1.f / sm0, inv1 = 1.f / sm1;

    float c2[4][4];
    #pragma unroll
    for (int nt = 0; nt < 4; nt++)
        #pragma unroll
        for (int i = 0; i < 4; i++) c2[nt][i] = 0.f;

    #pragma unroll
    for (int kk = 0; kk < 4; kk++) {
        unsigned ap[4];
        ap[0] = packh2(c[kk * 2][0],     c[kk * 2][1]);
        ap[1] = packh2(c[kk * 2][2],     c[kk * 2][3]);
        ap[2] = packh2(c[kk * 2 + 1][0], c[kk * 2 + 1][1]);
        ap[3] = packh2(c[kk * 2 + 1][2], c[kk * 2 + 1][3]);
        #pragma unroll
        for (int np = 0; np < 2; np++) {
            int row = kk * 16 + (lane & 15);
            int col = np * 16 + ((lane & 16) ? 8 : 0);
            unsigned r0, r1, r2, r3;
            ldsm4t(su32(Vs) + (unsigned)((row * KSTR + col) * 2), r0, r1, r2, r3);
            unsigned b0[2] = {r0, r1}, b1[2] = {r2, r3};
            mma16816(c2[np * 2],     ap, b0);
            mma16816(c2[np * 2 + 1], ap, b1);
        }
    }

    size_t obase = ((size_t)w * 64) * 192 + head * 32;
    #pragma unroll
    for (int nt = 0; nt < 4; nt++) {
        int col = nt * 8 + tg * 2;
        *(__half2*)(g_a + obase + (size_t)row0 * 192 + col) =
            __floats2half2_rn(c2[nt][0] * inv0, c2[nt][1] * inv0);
        *(__half2*)(g_a + obase + (size_t)row1 * 192 + col) =
            __floats2half2_rn(c2[nt][2] * inv1, c2[nt][3] * inv1);
    }
}

// ---------------- launch ------------------------------------------------------
extern "C" void kernel_launch(void* const* d_in, const int* in_sizes, int n_in,
                              void* d_out, int out_size)
{
    const float* x    = (const float*)d_in[0];
    const float* t    = (const float*)d_in[1];
    const float* n1w  = (const float*)d_in[2];
    const float* n1b  = (const float*)d_in[3];
    const float* qkvw = (const float*)d_in[4];
    const float* qkvb = (const float*)d_in[5];
    const float* rpb  = (const float*)d_in[6];
    const float* pw   = (const float*)d_in[7];
    const float* pb   = (const float*)d_in[8];
    const float* n2w  = (const float*)d_in[9];
    const float* n2b  = (const float*)d_in[10];
    const float* f1w  = (const float*)d_in[11];
    const float* f1b  = (const float*)d_in[12];
    const float* f2w  = (const float*)d_in[13];
    const float* f2b  = (const float*)d_in[14];
    const float* amw  = (const float*)d_in[15];
    const float* amb  = (const float*)d_in[16];
    const float* alw  = (const float*)d_in[17];
    const float* alb  = (const float*)d_in[18];
    float* out = (float*)d_out;

    float *x2;
    __half *a16, *b16, *w16;
    cudaGetSymbolAddress((void**)&x2,  g_x2v);
    cudaGetSymbolAddress((void**)&a16, g_a);
    cudaGetSymbolAddress((void**)&b16, g_b);
    cudaGetSymbolAddress((void**)&w16, g_w);

    const int GEMM_SMEM = 2 * (128 * GS + 96 * GS) * 2;  // 64512 B
    static int attr_done = 0;
    if (!attr_done) {
        cudaFuncSetAttribute(k_hgemm<0>, cudaFuncAttributeMaxDynamicSharedMemorySize, GEMM_SMEM);
        cudaFuncSetAttribute(k_hgemm<1>, cudaFuncAttributeMaxDynamicSharedMemorySize, GEMM_SMEM);
        cudaFuncSetAttribute(k_hgemm<2>, cudaFuncAttributeMaxDynamicSharedMemorySize, GEMM_SMEM);
        cudaFuncSetAttribute(k_hgemm<3>, cudaFuncAttributeMaxDynamicSharedMemorySize, GEMM_SMEM);
        attr_done = 1;
    }

    k_prep<<<32, 256>>>(t, amw, amb, alw, alb);
    k_wconv4<<<1728, 256>>>(qkvw, pw, f1w, f2w, w16);

    k_gnstats<<<dim3(32, 32), 256>>>(x, 0);
    k_adafm_tc<0><<<dim3(64, 32), 256>>>(x, n1w, n1b);
    // qkv: (131072 x 192) @ (576 x 192)^T -> fp16 into g_b
    k_hgemm<0><<<dim3(6, 1024), 256, GEMM_SMEM>>>(a16, w16, qkvb,
                                                  nullptr, b16, 192, 576, nullptr);
    // tensor-core attention -> g_a (fp16)
    k_attn_tc<<<dim3(2048, 6), 128>>>(b16, rpb);
    // proj + window reverse + roll + residual -> x2
    k_hgemm<2><<<dim3(2, 1024), 256, GEMM_SMEM>>>(a16, w16 + 110592, pb,
                                                  x2, nullptr, 192, 192, x);
    k_gnstats<<<dim3(32, 32), 256>>>(x2, 1);
    k_adafm_tc<1><<<dim3(64, 32), 256>>>(x2, n2w, n2b);
    // fc1 + GELU -> fp16
    k_hgemm<1><<<dim3(8, 1024), 256, GEMM_SMEM>>>(a16, w16 + 147456, f1b,
                                                  nullptr, b16, 192, 768, nullptr);
    // fc2 + residual scatter -> out
    k_hgemm<3><<<dim3(2, 1024), 256, GEMM_SMEM>>>(b16, w16 + 294912, f2b,
                                                  out, nullptr, 768, 192, x2);
}